// round 9
// baseline (speedup 1.0000x reference)
#include <cuda_runtime.h>
#include <cuda_bf16.h>
#include <math.h>
#include <stdint.h>

#define NN 100000
#define NE 400000
#define IND 771
#define HID 256
#define NG 64
#define KP0 800            // padded K for layer 0
#define NBLK 391           // ceil(NN/256)

// ---------------- scratch (static device globals; no allocation) ----------------
__device__ float  g_yl[(size_t)NN * 256];    // lin_l pre-agg (also score-GEMM scratch)
__device__ float  g_yr[(size_t)NN * 256];    // lin_r part
__device__ float  g_m[(size_t)NN * 256];     // pre-BN
__device__ float  g_h[(size_t)NN * 256];     // final layer output
__device__ float  g_inv[NN];
__device__ double g_sum[256];
__device__ double g_sumsq[256];
__device__ float  g_scale[256];
__device__ float  g_shift[256];
__device__ float  g_s[NN];
__device__ float  g_w[NN];
__device__ float  g_smax[NG];
__device__ float  g_denom[NG];
__device__ float  g_pooled[NG * HID];
__device__ int    g_is64;
__device__ int    g_src[NE];
__device__ int    g_dst[NE];
__device__ int    g_batch[NN];
// CSR by dst
__device__ int    g_cnt[NN];
__device__ int    g_off[NN];
__device__ int    g_cur[NN];
__device__ int    g_csr[NE];
__device__ int    g_bsum[NBLK];
__device__ int    g_boff[NBLK];
// bf16 split operands
__device__ __nv_bfloat16 g_ah[(size_t)NN * KP0];
__device__ __nv_bfloat16 g_al[(size_t)NN * KP0];
__device__ __nv_bfloat16 g_bh[512 * KP0];
__device__ __nv_bfloat16 g_bl[512 * KP0];

// ---------------- helpers ----------------
__device__ __forceinline__ uint32_t smem_u32(const void* p) {
    uint32_t a;
    asm("{ .reg .u64 t; cvta.to.shared.u64 t, %1; cvt.u32.u64 %0, t; }" : "=r"(a) : "l"(p));
    return a;
}
// 16-row x 32B tiles: toggle 16B half by (row>>2)&1 -> conflict-free ldmatrix + stores
#define SWZ16(b) ((b) ^ ((((b) >> 7) & 1) << 4))

__device__ __forceinline__ void cpasync16(uint32_t dst, const void* src, bool pred) {
    int sz = pred ? 16 : 0;
    asm volatile("cp.async.cg.shared.global [%0], [%1], 16, %2;"
                 :: "r"(dst), "l"(src), "r"(sz) : "memory");
}
__device__ __forceinline__ void cp_commit() {
    asm volatile("cp.async.commit_group;" ::: "memory");
}
__device__ __forceinline__ void cp_wait1() {
    asm volatile("cp.async.wait_group 1;" ::: "memory");
}
__device__ __forceinline__ void ldsm4(uint32_t* r, uint32_t addr) {
    asm volatile("ldmatrix.sync.aligned.m8n8.x4.shared.b16 {%0,%1,%2,%3}, [%4];"
                 : "=r"(r[0]), "=r"(r[1]), "=r"(r[2]), "=r"(r[3]) : "r"(addr));
}
__device__ __forceinline__ void mma_bf16(float* c, const uint32_t* a, uint32_t b0, uint32_t b1) {
    asm volatile(
        "mma.sync.aligned.m16n8k16.row.col.f32.bf16.bf16.f32 "
        "{%0,%1,%2,%3}, {%4,%5,%6,%7}, {%8,%9}, {%0,%1,%2,%3};"
        : "+f"(c[0]), "+f"(c[1]), "+f"(c[2]), "+f"(c[3])
        : "r"(a[0]), "r"(a[1]), "r"(a[2]), "r"(a[3]), "r"(b0), "r"(b1));
}
__device__ __forceinline__ void atomicMaxFloat(float* addr, float val) {
    int* ai = (int*)addr;
    int old = __float_as_int(*addr);
    while (__int_as_float(old) < val) {
        int assumed = old;
        old = atomicCAS(ai, assumed, __float_as_int(val));
        if (old == assumed) break;
    }
}
__device__ __forceinline__ void split1(float v, __nv_bfloat16& h, __nv_bfloat16& l) {
    h = __float2bfloat16(v);
    l = __float2bfloat16(v - __bfloat162float(h));
}

// ---------------- dtype detection + index normalization ----------------
__global__ void detect_dtype(const unsigned long long* __restrict__ ei) {
    if (threadIdx.x == 0 && blockIdx.x == 0) {
        int is64 = 1;
        for (int i = 0; i < 64; i++)
            if (ei[i] >= (unsigned long long)NN) { is64 = 0; break; }
        g_is64 = is64;
    }
}
__global__ void cvt_edges(const void* __restrict__ ei) {
    int e = blockIdx.x * blockDim.x + threadIdx.x;
    if (e >= NE) return;
    if (g_is64) {
        const long long* p = (const long long*)ei;
        g_src[e] = (int)p[e];
        g_dst[e] = (int)p[NE + e];
    } else {
        const int* p = (const int*)ei;
        g_src[e] = p[e];
        g_dst[e] = p[NE + e];
    }
}
__global__ void cvt_batch_zero(const void* __restrict__ b) {
    int n = blockIdx.x * blockDim.x + threadIdx.x;
    if (n >= NN) return;
    if (g_is64) g_batch[n] = (int)((const long long*)b)[n];
    else        g_batch[n] = ((const int*)b)[n];
    g_cnt[n] = 0;
}

// ---------------- CSR build ----------------
__global__ void cnt_kernel() {
    int e = blockIdx.x * blockDim.x + threadIdx.x;
    if (e < NE) atomicAdd(&g_cnt[g_dst[e]], 1);
}
__global__ void scan1() {
    __shared__ int sm[256];
    int b = blockIdx.x, t = threadIdx.x;
    int i = b * 256 + t;
    int v = (i < NN) ? g_cnt[i] : 0;
    sm[t] = v; __syncthreads();
    for (int o = 1; o < 256; o <<= 1) {
        int u = (t >= o) ? sm[t - o] : 0;
        __syncthreads();
        sm[t] += u;
        __syncthreads();
    }
    if (i < NN) g_off[i] = sm[t] - v;
    if (t == 255) g_bsum[b] = sm[255];
}
__global__ void scan2() {
    __shared__ int sm[512];
    int t = threadIdx.x;
    int v = (t < NBLK) ? g_bsum[t] : 0;
    sm[t] = v; __syncthreads();
    for (int o = 1; o < 512; o <<= 1) {
        int u = (t >= o) ? sm[t - o] : 0;
        __syncthreads();
        sm[t] += u;
        __syncthreads();
    }
    if (t < NBLK) g_boff[t] = sm[t] - v;
}
__global__ void scan3() {
    int i = blockIdx.x * blockDim.x + threadIdx.x;
    if (i < NN) {
        int o = g_off[i] + g_boff[i >> 8];
        g_off[i] = o;
        g_cur[i] = o;
        g_inv[i] = 1.f / fmaxf((float)g_cnt[i], 1.f);
    }
}
__global__ void place_kernel() {
    int e = blockIdx.x * blockDim.x + threadIdx.x;
    if (e < NE) {
        int pos = atomicAdd(&g_cur[g_dst[e]], 1);
        g_csr[pos] = g_src[e];
    }
}

// ---------------- zero / init ----------------
__global__ void zero_stats() {
    int c = threadIdx.x;
    g_sum[c] = 0.0; g_sumsq[c] = 0.0;
}
__global__ void init_pool() {
    int i = blockIdx.x * blockDim.x + threadIdx.x;
    if (i < NG * HID) g_pooled[i] = 0.f;
    if (i < NG) { g_smax[i] = -3.4e38f; g_denom[i] = 0.f; }
}

// ---------------- split x (layer 0 only) ----------------
__global__ void split_a(const float* __restrict__ A) {
    int kp2 = KP0 >> 1;
    int i = blockIdx.x * blockDim.x + threadIdx.x;
    if (i >= NN * kp2) return;
    int n = i / kp2, k2 = (i - n * kp2) * 2;
    float v0 = (k2 < IND)     ? A[(size_t)n * IND + k2]     : 0.f;
    float v1 = (k2 + 1 < IND) ? A[(size_t)n * IND + k2 + 1] : 0.f;
    __nv_bfloat162 hp, lp;
    split1(v0, hp.x, lp.x);
    split1(v1, hp.y, lp.y);
    *(__nv_bfloat162*)(g_ah + (size_t)n * KP0 + k2) = hp;
    *(__nv_bfloat162*)(g_al + (size_t)n * KP0 + k2) = lp;
}

// ---------------- pack [Wl|Wr]^T ----------------
__global__ void pack_wbT(const float* __restrict__ Wl, const float* __restrict__ Wr,
                         int K, int KP) {
    int kp2 = KP >> 1;
    int i = blockIdx.x * blockDim.x + threadIdx.x;
    if (i >= 512 * kp2) return;
    int n = i / kp2, k2 = (i - n * kp2) * 2;
    const float* W = (n < 256) ? Wl : Wr;
    int c = (n < 256) ? n : n - 256;
    float v0 = (k2 < K)     ? W[(size_t)k2 * 256 + c]       : 0.f;
    float v1 = (k2 + 1 < K) ? W[(size_t)(k2 + 1) * 256 + c] : 0.f;
    __nv_bfloat162 hp, lp;
    split1(v0, hp.x, lp.x);
    split1(v1, hp.y, lp.y);
    *(__nv_bfloat162*)(g_bh + (size_t)n * KP + k2) = hp;
    *(__nv_bfloat162*)(g_bl + (size_t)n * KP + k2) = lp;
}

// ---------------- pack Wa1^T (score GEMM B) ----------------
__global__ void pack_wa(const float* __restrict__ Wa1) {
    int i = blockIdx.x * blockDim.x + threadIdx.x;
    if (i >= 128 * 128) return;
    int n = i >> 7, k2 = (i & 127) * 2;
    float v0 = Wa1[(size_t)k2 * 128 + n];
    float v1 = Wa1[(size_t)(k2 + 1) * 128 + n];
    __nv_bfloat162 hp, lp;
    split1(v0, hp.x, lp.x);
    split1(v1, hp.y, lp.y);
    *(__nv_bfloat162*)(g_bh + (size_t)n * 256 + k2) = hp;
    *(__nv_bfloat162*)(g_bl + (size_t)n * 256 + k2) = lp;
}

// ---------------- split-bf16 GEMM: M128 x N128, 8 warps, k16 chunks ----------------
// 3-stage cp.async pipeline, ONE __syncthreads per chunk, precomputed src pointers.
// stage (16KB): A_hi 0 | A_lo 4096 | B_hi 8192 | B_lo 12288
__global__ __launch_bounds__(256) void gemm_tc(int KP) {
    __shared__ __align__(128) char sm_[49152];   // 3 x 16KB
    const uint32_t sb = smem_u32(sm_);
    int tid = threadIdx.x, lane = tid & 31, wid = tid >> 5;
    int wm = wid >> 2, wn = wid & 3;         // 2 x 4 warps, warp tile 64x32
    int row0 = blockIdx.y * 128;
    int col0 = blockIdx.x * 128;
    int nch = KP >> 4;

    // per-thread staging sources: thread handles row r, 16B half s16 of A(hi,lo), B(hi,lo)
    int r = tid >> 1, s16 = (tid & 1) * 16;
    bool predA = (row0 + r) < NN;
    const char* pAh = (const char*)g_ah + ((size_t)(row0 + r) * KP) * 2 + s16;
    const char* pAl = (const char*)g_al + ((size_t)(row0 + r) * KP) * 2 + s16;
    const char* pBh = (const char*)g_bh + ((size_t)(col0 + r) * KP) * 2 + s16;
    const char* pBl = (const char*)g_bl + ((size_t)(col0 + r) * KP) * 2 + s16;
    if (!predA) { pAh = (const char*)g_ah + s16; pAl = (const char*)g_al + s16; }
    const uint32_t soff = SWZ16((uint32_t)(r * 32 + s16));

#define STAGE(BUF)                                                   \
    do {                                                             \
        uint32_t stg = sb + (uint32_t)(BUF) * 16384 + soff;          \
        cpasync16(stg,         pAh, predA);                          \
        cpasync16(stg + 4096,  pAl, predA);                          \
        cpasync16(stg + 8192,  pBh, true);                           \
        cpasync16(stg + 12288, pBl, true);                           \
        cp_commit();                                                 \
        pAh += 32; pAl += 32; pBh += 32; pBl += 32;                  \
    } while (0)

    float acc[4][4][4];
#pragma unroll
    for (int a = 0; a < 4; a++)
#pragma unroll
        for (int b = 0; b < 4; b++)
#pragma unroll
            for (int c = 0; c < 4; c++) acc[a][b][c] = 0.f;

    STAGE(0);
    STAGE(1);

    int q = lane >> 3, lr = lane & 7;
    // precomputed ldmatrix base offsets (within a stage)
    const uint32_t aoff0 = (uint32_t)((wm * 64 + (q & 1) * 8 + lr) * 32 + (q >> 1) * 16);
    const uint32_t boff0 = (uint32_t)((wn * 32 + (q >> 1) * 8 + lr) * 32 + (q & 1) * 16);

    int bufS = 2, bufC = 0;
    for (int ch = 0; ch < nch; ch++) {
        cp_wait1();
        __syncthreads();
        if (ch + 2 < nch) {
            STAGE(bufS);
        } else {
            cp_commit();   // keep group count in lockstep
        }
        bufS = (bufS == 2) ? 0 : bufS + 1;

        uint32_t stg = sb + (uint32_t)bufC * 16384;
        bufC = (bufC == 2) ? 0 : bufC + 1;

        uint32_t Ah[4][4], Al[4][4], Bh[2][4], Bl[2][4];
#pragma unroll
        for (int mi = 0; mi < 4; mi++) {
            uint32_t a = stg + SWZ16(aoff0 + (uint32_t)(mi * 16 * 32));
            ldsm4(Ah[mi], a);
            ldsm4(Al[mi], a + 4096);
        }
#pragma unroll
        for (int p = 0; p < 2; p++) {
            uint32_t a = stg + 8192 + SWZ16(boff0 + (uint32_t)(p * 16 * 32));
            ldsm4(Bh[p], a);
            ldsm4(Bl[p], a + 4096);
        }
#pragma unroll
        for (int mi = 0; mi < 4; mi++)
#pragma unroll
            for (int ni = 0; ni < 4; ni++) {
                uint32_t bh0 = Bh[ni >> 1][(ni & 1) * 2], bh1 = Bh[ni >> 1][(ni & 1) * 2 + 1];
                uint32_t bl0 = Bl[ni >> 1][(ni & 1) * 2], bl1 = Bl[ni >> 1][(ni & 1) * 2 + 1];
                mma_bf16(acc[mi][ni], Ah[mi], bh0, bh1);
                mma_bf16(acc[mi][ni], Al[mi], bh0, bh1);
                mma_bf16(acc[mi][ni], Ah[mi], bl0, bl1);
            }
    }
#undef STAGE

    float* dstbase = (col0 < 256) ? g_yl : g_yr;
    int cb = col0 & 255;
    int tr = lane >> 2, tc = lane & 3;
#pragma unroll
    for (int mi = 0; mi < 4; mi++)
#pragma unroll
        for (int half = 0; half < 2; half++) {
            int row = row0 + wm * 64 + mi * 16 + tr + half * 8;
            if (row < NN) {
                float* p = dstbase + (size_t)row * 256 + cb + wn * 32 + tc * 2;
#pragma unroll
                for (int ni = 0; ni < 4; ni++) {
                    float2 v = make_float2(acc[mi][ni][half * 2], acc[mi][ni][half * 2 + 1]);
                    *(float2*)(p + ni * 8) = v;
                }
            }
        }
}

// ---------------- CSR aggregation + combine + BN stats (unroll-4 MLP) ----------------
__global__ __launch_bounds__(256) void agg_combine(const float* __restrict__ bl) {
    int c  = threadIdx.x;
    int r0 = blockIdx.x * 32;
    if (r0 >= NN) return;
    int r1 = min(r0 + 32, NN);
    float bias = bl[c];
    float s = 0.f, s2 = 0.f;
    for (int r = r0; r < r1; r++) {
        int beg = g_off[r];
        int end = (r == NN - 1) ? NE : g_off[r + 1];
        float a0 = 0.f, a1 = 0.f, a2 = 0.f, a3 = 0.f;
        int i = beg;
        for (; i + 4 <= end; i += 4) {
            int s0 = g_csr[i], s1 = g_csr[i + 1], s2i = g_csr[i + 2], s3 = g_csr[i + 3];
            float v0 = g_yl[(size_t)s0 * 256 + c];
            float v1 = g_yl[(size_t)s1 * 256 + c];
            float v2 = g_yl[(size_t)s2i * 256 + c];
            float v3 = g_yl[(size_t)s3 * 256 + c];
            a0 += v0; a1 += v1; a2 += v2; a3 += v3;
        }
        for (; i < end; i++) a0 += g_yl[(size_t)g_csr[i] * 256 + c];
        float acc = (a0 + a1) + (a2 + a3);
        float pre = acc * g_inv[r] + bias + g_yr[(size_t)r * 256 + c];
        g_m[(size_t)r * 256 + c] = pre;
        s += pre; s2 += pre * pre;
    }
    atomicAdd(&g_sum[c], (double)s);
    atomicAdd(&g_sumsq[c], (double)s2);
}

__global__ void finalize_bn(const float* __restrict__ gm, const float* __restrict__ bt) {
    int c = threadIdx.x;
    double mean = g_sum[c] / (double)NN;
    double var  = g_sumsq[c] / (double)NN - mean * mean;
    float rstd  = rsqrtf((float)var + 1e-5f);
    float sc    = rstd * gm[c];
    g_scale[c]  = sc;
    g_shift[c]  = bt[c] - (float)mean * sc;
}

// mode 1: bf16 hi/lo only; mode 2: bf16 + fp32 g_h
__global__ void bnrelu(int mode) {
    size_t i = (size_t)blockIdx.x * blockDim.x + threadIdx.x;
    if (i >= (size_t)NN * 64) return;
    size_t idx = i * 4;
    int c = (int)(idx & 255);
    float4 v = *(const float4*)(g_m + idx);
    v.x = fmaxf(v.x * g_scale[c + 0] + g_shift[c + 0], 0.f);
    v.y = fmaxf(v.y * g_scale[c + 1] + g_shift[c + 1], 0.f);
    v.z = fmaxf(v.z * g_scale[c + 2] + g_shift[c + 2], 0.f);
    v.w = fmaxf(v.w * g_scale[c + 3] + g_shift[c + 3], 0.f);
    __nv_bfloat162 h01, l01, h23, l23;
    split1(v.x, h01.x, l01.x);
    split1(v.y, h01.y, l01.y);
    split1(v.z, h23.x, l23.x);
    split1(v.w, h23.y, l23.y);
    uint2 uh, ul;
    uh.x = *(uint32_t*)&h01; uh.y = *(uint32_t*)&h23;
    ul.x = *(uint32_t*)&l01; ul.y = *(uint32_t*)&l23;
    *(uint2*)(g_ah + idx) = uh;
    *(uint2*)(g_al + idx) = ul;
    if (mode == 2) *(float4*)(g_h + idx) = v;
}

// ---------------- tanh-dot ----------------
__global__ __launch_bounds__(256) void tanhdot(const float* __restrict__ ba1,
                                               const float* __restrict__ Wa2,
                                               const float* __restrict__ ba2) {
    __shared__ float red[2][4];
    int tid = threadIdx.x, sub = tid >> 7, j = tid & 127;
    int n = blockIdx.x * 2 + sub;
    float t = 0.f;
    if (n < NN)
        t = tanhf(g_yl[(size_t)n * 256 + j] + ba1[j]) * Wa2[j];
#pragma unroll
    for (int o = 16; o; o >>= 1) t += __shfl_down_sync(0xffffffffu, t, o);
    if ((j & 31) == 0) red[sub][j >> 5] = t;
    __syncthreads();
    if (j == 0 && n < NN)
        g_s[n] = red[sub][0] + red[sub][1] + red[sub][2] + red[sub][3] + ba2[0];
}

// ---------------- per-graph softmax ----------------
__global__ void segmax_kernel() {
    int n  = blockIdx.x * blockDim.x + threadIdx.x;
    int nc = min(n, NN - 1);
    int g  = g_batch[nc];
    float v = (n < NN) ? g_s[n] : -3.4e38f;
    int g0 = __shfl_sync(0xffffffffu, g, 0);
    bool uni = __all_sync(0xffffffffu, g == g0);
    if (uni) {
#pragma unroll
        for (int o = 16; o; o >>= 1) v = fmaxf(v, __shfl_down_sync(0xffffffffu, v, o));
        if ((threadIdx.x & 31) == 0) atomicMaxFloat(&g_smax[g0], v);
    } else if (n < NN) {
        atomicMaxFloat(&g_smax[g], v);
    }
}

__global__ void expsum_kernel() {
    int n  = blockIdx.x * blockDim.x + threadIdx.x;
    int nc = min(n, NN - 1);
    int g  = g_batch[nc];
    float e = 0.f;
    if (n < NN) { e = expf(g_s[n] - g_smax[g]); g_w[n] = e; }
    int g0 = __shfl_sync(0xffffffffu, g, 0);
    bool uni = __all_sync(0xffffffffu, g == g0);
    if (uni) {
#pragma unroll
        for (int o = 16; o; o >>= 1) e += __shfl_down_sync(0xffffffffu, e, o);
        if ((threadIdx.x & 31) == 0) atomicAdd(&g_denom[g0], e);
    } else if (n < NN) {
        atomicAdd(&g_denom[g], e);
    }
}

__global__ void weights_kernel() {
    int n = blockIdx.x * blockDim.x + threadIdx.x;
    if (n < NN) g_w[n] = g_w[n] / g_denom[g_batch[n]];
}

// ---------------- weighted pooling ----------------
__global__ void pooled_kernel() {
    int c  = threadIdx.x;
    int r0 = blockIdx.x * 512;
    if (r0 >= NN) return;
    int r1  = min(r0 + 512, NN);
    int cur = g_batch[r0];
    float acc = 0.f;
    for (int r = r0; r < r1; r++) {
        int g = g_batch[r];
        if (g != cur) { atomicAdd(&g_pooled[cur * 256 + c], acc); acc = 0.f; cur = g; }
        acc += g_h[(size_t)r * 256 + c] * g_w[r];
    }
    atomicAdd(&g_pooled[cur * 256 + c], acc);
}

// ---------------- classifier ----------------
__global__ void classifier_kernel(const float* __restrict__ Wc1, const float* __restrict__ bc1,
                                  const float* __restrict__ Wc2, const float* __restrict__ bc2,
                                  float* __restrict__ out) {
    int g = blockIdx.x;
    int j = threadIdx.x;
    float acc = bc1[j];
    for (int k = 0; k < 256; k++) acc += g_pooled[g * 256 + k] * Wc1[k * 128 + j];
    float t = fmaxf(acc, 0.f) * Wc2[j];
#pragma unroll
    for (int o = 16; o; o >>= 1) t += __shfl_down_sync(0xffffffffu, t, o);
    __shared__ float red[4];
    if ((j & 31) == 0) red[j >> 5] = t;
    __syncthreads();
    if (j == 0) out[g] = red[0] + red[1] + red[2] + red[3] + bc2[0];
}

// ---------------- launch ----------------
extern "C" void kernel_launch(void* const* d_in, const int* in_sizes, int n_in,
                              void* d_out, int out_size) {
    const float* x     = (const float*)d_in[0];
    const void*  ei    = d_in[1];
    const void*  batch = d_in[2];
    const float* Wl[3] = {(const float*)d_in[3], (const float*)d_in[8],  (const float*)d_in[13]};
    const float* bl[3] = {(const float*)d_in[4], (const float*)d_in[9],  (const float*)d_in[14]};
    const float* Wr[3] = {(const float*)d_in[5], (const float*)d_in[10], (const float*)d_in[15]};
    const float* gg[3] = {(const float*)d_in[6], (const float*)d_in[11], (const float*)d_in[16]};
    const float* bb[3] = {(const float*)d_in[7], (const float*)d_in[12], (const float*)d_in[17]};
    const float* Wa1 = (const float*)d_in[18];
    const float* ba1 = (const float*)d_in[19];
    const float* Wa2 = (const float*)d_in[20];
    const float* ba2 = (const float*)d_in[21];
    const float* Wc1 = (const float*)d_in[22];
    const float* bc1 = (const float*)d_in[23];
    const float* Wc2 = (const float*)d_in[24];
    const float* bc2 = (const float*)d_in[25];
    float* out = (float*)d_out;

    // launches 1-4: layer-0 GEMM path first (4th launch = gemm_tc -> ncu capture slot)
    detect_dtype<<<1, 32>>>((const unsigned long long*)ei);
    split_a<<<(NN * (KP0 / 2) + 255) / 256, 256>>>(x);
    pack_wbT<<<(512 * (KP0 / 2) + 255) / 256, 256>>>(Wl[0], Wr[0], IND, KP0);
    {
        dim3 ggrid(4, (NN + 127) / 128);
        gemm_tc<<<ggrid, 256>>>(KP0);
    }

    // graph preprocessing
    cvt_edges<<<(NE + 255) / 256, 256>>>(ei);
    cvt_batch_zero<<<(NN + 255) / 256, 256>>>(batch);
    cnt_kernel<<<(NE + 255) / 256, 256>>>();
    scan1<<<NBLK, 256>>>();
    scan2<<<1, 512>>>();
    scan3<<<(NN + 255) / 256, 256>>>();
    place_kernel<<<(NE + 255) / 256, 256>>>();

    for (int L = 0; L < 3; L++) {
        if (L > 0) {
            pack_wbT<<<(512 * (HID / 2) + 255) / 256, 256>>>(Wl[L], Wr[L], HID, HID);
            dim3 ggrid(4, (NN + 127) / 128);
            gemm_tc<<<ggrid, 256>>>(HID);
        }
        zero_stats<<<1, 256>>>();
        agg_combine<<<(NN + 31) / 32, 256>>>(bl[L]);
        finalize_bn<<<1, 256>>>(gg[L], bb[L]);
        bnrelu<<<(NN * 64 + 255) / 256, 256>>>(L < 2 ? 1 : 2);
    }

    // attention score: S = h @ Wa1 via tensor GEMM (N=128 -> g_yl), then tanh-dot
    pack_wa<<<(128 * 128 + 255) / 256, 256>>>(Wa1);
    {
        dim3 sgrid(1, (NN + 127) / 128);
        gemm_tc<<<sgrid, 256>>>(HID);
    }
    tanhdot<<<(NN + 1) / 2, 256>>>(ba1, Wa2, ba2);

    init_pool<<<(NG * HID + 255) / 256, 256>>>();
    segmax_kernel<<<(NN + 255) / 256, 256>>>();
    expsum_kernel<<<(NN + 255) / 256, 256>>>();
    weights_kernel<<<(NN + 255) / 256, 256>>>();
    pooled_kernel<<<(NN + 511) / 512, 256>>>();
    classifier_kernel<<<NG, 128>>>(Wc1, bc1, Wc2, bc2, out);
}

// round 10
// speedup vs baseline: 1.0431x; 1.0431x over previous
#include <cuda_runtime.h>
#include <cuda_bf16.h>
#include <math.h>
#include <stdint.h>

#define NN 100000
#define NE 400000
#define IND 771
#define HID 256
#define NG 64
#define KP0 800            // padded K for layer 0
#define NBLK 391           // ceil(NN/256)

// ---------------- scratch (static device globals; no allocation) ----------------
__device__ float  g_yl[(size_t)NN * 256];    // lin_l pre-agg (also score-GEMM scratch)
__device__ float  g_yr[(size_t)NN * 256];    // lin_r part
__device__ float  g_m[(size_t)NN * 256];     // pre-BN
__device__ float  g_h[(size_t)NN * 256];     // final layer output
__device__ float  g_inv[NN];
__device__ double g_sum[256];
__device__ double g_sumsq[256];
__device__ float  g_scale[256];
__device__ float  g_shift[256];
__device__ float  g_s[NN];
__device__ float  g_w[NN];
__device__ float  g_smax[NG];
__device__ float  g_denom[NG];
__device__ float  g_pooled[NG * HID];
__device__ int    g_is64;
__device__ int    g_src[NE];
__device__ int    g_dst[NE];
__device__ int    g_batch[NN];
// CSR by dst
__device__ int    g_cnt[NN];
__device__ int    g_off[NN];
__device__ int    g_cur[NN];
__device__ int    g_csr[NE];
__device__ int    g_bsum[NBLK];
__device__ int    g_boff[NBLK];
// bf16 split operands
__device__ __nv_bfloat16 g_ah[(size_t)NN * KP0];
__device__ __nv_bfloat16 g_al[(size_t)NN * KP0];
__device__ __nv_bfloat16 g_bh[512 * KP0];
__device__ __nv_bfloat16 g_bl[512 * KP0];

// ---------------- helpers ----------------
__device__ __forceinline__ uint32_t smem_u32(const void* p) {
    uint32_t a;
    asm("{ .reg .u64 t; cvta.to.shared.u64 t, %1; cvt.u32.u64 %0, t; }" : "=r"(a) : "l"(p));
    return a;
}
// 16-row x 32B tiles: toggle 16B half by (row>>2)&1 -> conflict-free ldmatrix + stores
#define SWZ16(b) ((b) ^ ((((b) >> 7) & 1) << 4))

__device__ __forceinline__ void cpasync16(uint32_t dst, const void* src, bool pred) {
    int sz = pred ? 16 : 0;
    asm volatile("cp.async.cg.shared.global [%0], [%1], 16, %2;"
                 :: "r"(dst), "l"(src), "r"(sz) : "memory");
}
__device__ __forceinline__ void cp_commit() {
    asm volatile("cp.async.commit_group;" ::: "memory");
}
__device__ __forceinline__ void cp_wait_all() {
    asm volatile("cp.async.wait_group 0;" ::: "memory");
}
__device__ __forceinline__ void ldsm4(uint32_t* r, uint32_t addr) {
    asm volatile("ldmatrix.sync.aligned.m8n8.x4.shared.b16 {%0,%1,%2,%3}, [%4];"
                 : "=r"(r[0]), "=r"(r[1]), "=r"(r[2]), "=r"(r[3]) : "r"(addr));
}
__device__ __forceinline__ void mma_bf16(float* c, const uint32_t* a, uint32_t b0, uint32_t b1) {
    asm volatile(
        "mma.sync.aligned.m16n8k16.row.col.f32.bf16.bf16.f32 "
        "{%0,%1,%2,%3}, {%4,%5,%6,%7}, {%8,%9}, {%0,%1,%2,%3};"
        : "+f"(c[0]), "+f"(c[1]), "+f"(c[2]), "+f"(c[3])
        : "r"(a[0]), "r"(a[1]), "r"(a[2]), "r"(a[3]), "r"(b0), "r"(b1));
}
__device__ __forceinline__ void atomicMaxFloat(float* addr, float val) {
    int* ai = (int*)addr;
    int old = __float_as_int(*addr);
    while (__int_as_float(old) < val) {
        int assumed = old;
        old = atomicCAS(ai, assumed, __float_as_int(val));
        if (old == assumed) break;
    }
}
__device__ __forceinline__ void split1(float v, __nv_bfloat16& h, __nv_bfloat16& l) {
    h = __float2bfloat16(v);
    l = __float2bfloat16(v - __bfloat162float(h));
}

// ---------------- dtype detection + index normalization ----------------
__global__ void detect_dtype(const unsigned long long* __restrict__ ei) {
    if (threadIdx.x == 0 && blockIdx.x == 0) {
        int is64 = 1;
        for (int i = 0; i < 64; i++)
            if (ei[i] >= (unsigned long long)NN) { is64 = 0; break; }
        g_is64 = is64;
    }
}
__global__ void cvt_edges(const void* __restrict__ ei) {
    int e = blockIdx.x * blockDim.x + threadIdx.x;
    if (e >= NE) return;
    if (g_is64) {
        const long long* p = (const long long*)ei;
        g_src[e] = (int)p[e];
        g_dst[e] = (int)p[NE + e];
    } else {
        const int* p = (const int*)ei;
        g_src[e] = p[e];
        g_dst[e] = p[NE + e];
    }
}
__global__ void cvt_batch_zero(const void* __restrict__ b) {
    int n = blockIdx.x * blockDim.x + threadIdx.x;
    if (n >= NN) return;
    if (g_is64) g_batch[n] = (int)((const long long*)b)[n];
    else        g_batch[n] = ((const int*)b)[n];
    g_cnt[n] = 0;
}

// ---------------- CSR build ----------------
__global__ void cnt_kernel() {
    int e = blockIdx.x * blockDim.x + threadIdx.x;
    if (e < NE) atomicAdd(&g_cnt[g_dst[e]], 1);
}
__global__ void scan1() {
    __shared__ int sm[256];
    int b = blockIdx.x, t = threadIdx.x;
    int i = b * 256 + t;
    int v = (i < NN) ? g_cnt[i] : 0;
    sm[t] = v; __syncthreads();
    for (int o = 1; o < 256; o <<= 1) {
        int u = (t >= o) ? sm[t - o] : 0;
        __syncthreads();
        sm[t] += u;
        __syncthreads();
    }
    if (i < NN) g_off[i] = sm[t] - v;
    if (t == 255) g_bsum[b] = sm[255];
}
__global__ void scan2() {
    __shared__ int sm[512];
    int t = threadIdx.x;
    int v = (t < NBLK) ? g_bsum[t] : 0;
    sm[t] = v; __syncthreads();
    for (int o = 1; o < 512; o <<= 1) {
        int u = (t >= o) ? sm[t - o] : 0;
        __syncthreads();
        sm[t] += u;
        __syncthreads();
    }
    if (t < NBLK) g_boff[t] = sm[t] - v;
}
__global__ void scan3() {
    int i = blockIdx.x * blockDim.x + threadIdx.x;
    if (i < NN) {
        int o = g_off[i] + g_boff[i >> 8];
        g_off[i] = o;
        g_cur[i] = o;
        g_inv[i] = 1.f / fmaxf((float)g_cnt[i], 1.f);
    }
}
__global__ void place_kernel() {
    int e = blockIdx.x * blockDim.x + threadIdx.x;
    if (e < NE) {
        int pos = atomicAdd(&g_cur[g_dst[e]], 1);
        g_csr[pos] = g_src[e];
    }
}

// ---------------- zero / init ----------------
__global__ void zero_stats() {
    int c = threadIdx.x;
    g_sum[c] = 0.0; g_sumsq[c] = 0.0;
}
__global__ void init_pool() {
    int i = blockIdx.x * blockDim.x + threadIdx.x;
    if (i < NG * HID) g_pooled[i] = 0.f;
    if (i < NG) { g_smax[i] = -3.4e38f; g_denom[i] = 0.f; }
}

// ---------------- split x (layer 0 only) ----------------
__global__ void split_a(const float* __restrict__ A) {
    int kp2 = KP0 >> 1;
    int i = blockIdx.x * blockDim.x + threadIdx.x;
    if (i >= NN * kp2) return;
    int n = i / kp2, k2 = (i - n * kp2) * 2;
    float v0 = (k2 < IND)     ? A[(size_t)n * IND + k2]     : 0.f;
    float v1 = (k2 + 1 < IND) ? A[(size_t)n * IND + k2 + 1] : 0.f;
    __nv_bfloat162 hp, lp;
    split1(v0, hp.x, lp.x);
    split1(v1, hp.y, lp.y);
    *(__nv_bfloat162*)(g_ah + (size_t)n * KP0 + k2) = hp;
    *(__nv_bfloat162*)(g_al + (size_t)n * KP0 + k2) = lp;
}

// ---------------- pack [Wl|Wr]^T ----------------
__global__ void pack_wbT(const float* __restrict__ Wl, const float* __restrict__ Wr,
                         int K, int KP) {
    int kp2 = KP >> 1;
    int i = blockIdx.x * blockDim.x + threadIdx.x;
    if (i >= 512 * kp2) return;
    int n = i / kp2, k2 = (i - n * kp2) * 2;
    const float* W = (n < 256) ? Wl : Wr;
    int c = (n < 256) ? n : n - 256;
    float v0 = (k2 < K)     ? W[(size_t)k2 * 256 + c]       : 0.f;
    float v1 = (k2 + 1 < K) ? W[(size_t)(k2 + 1) * 256 + c] : 0.f;
    __nv_bfloat162 hp, lp;
    split1(v0, hp.x, lp.x);
    split1(v1, hp.y, lp.y);
    *(__nv_bfloat162*)(g_bh + (size_t)n * KP + k2) = hp;
    *(__nv_bfloat162*)(g_bl + (size_t)n * KP + k2) = lp;
}

// ---------------- pack Wa1^T (score GEMM B) ----------------
__global__ void pack_wa(const float* __restrict__ Wa1) {
    int i = blockIdx.x * blockDim.x + threadIdx.x;
    if (i >= 128 * 128) return;
    int n = i >> 7, k2 = (i & 127) * 2;
    float v0 = Wa1[(size_t)k2 * 128 + n];
    float v1 = Wa1[(size_t)(k2 + 1) * 128 + n];
    __nv_bfloat162 hp, lp;
    split1(v0, hp.x, lp.x);
    split1(v1, hp.y, lp.y);
    *(__nv_bfloat162*)(g_bh + (size_t)n * 256 + k2) = hp;
    *(__nv_bfloat162*)(g_bl + (size_t)n * 256 + k2) = lp;
}

// ---------------- split-bf16 GEMM: M128 x N128, 8 warps, k16 chunks ----------------
// 2-stage cp.async pipeline (32KB), ONE __syncthreads per chunk, regs capped at 128
// for 2 CTAs/SM. Order: wait -> sync -> ldsm(ch) -> STAGE(ch+1) -> MMA(ch).
// stage (16KB): A_hi 0 | A_lo 4096 | B_hi 8192 | B_lo 12288
__global__ void __launch_bounds__(256, 2) gemm_tc(int KP) {
    __shared__ __align__(128) char sm_[32768];   // 2 x 16KB
    const uint32_t sb = smem_u32(sm_);
    int tid = threadIdx.x, lane = tid & 31, wid = tid >> 5;
    int wm = wid >> 2, wn = wid & 3;         // 2 x 4 warps, warp tile 64x32
    int row0 = blockIdx.y * 128;
    int col0 = blockIdx.x * 128;
    int nch = KP >> 4;

    // per-thread staging sources: thread handles row r, 16B half s16
    int r = tid >> 1, s16 = (tid & 1) * 16;
    bool predA = (row0 + r) < NN;
    const char* pAh = (const char*)g_ah + ((size_t)(row0 + r) * KP) * 2 + s16;
    const char* pAl = (const char*)g_al + ((size_t)(row0 + r) * KP) * 2 + s16;
    const char* pBh = (const char*)g_bh + ((size_t)(col0 + r) * KP) * 2 + s16;
    const char* pBl = (const char*)g_bl + ((size_t)(col0 + r) * KP) * 2 + s16;
    if (!predA) { pAh = (const char*)g_ah + s16; pAl = (const char*)g_al + s16; }
    const uint32_t soff = SWZ16((uint32_t)(r * 32 + s16));

#define STAGE(BUF)                                                   \
    do {                                                             \
        uint32_t stg = sb + (uint32_t)(BUF) * 16384 + soff;          \
        cpasync16(stg,         pAh, predA);                          \
        cpasync16(stg + 4096,  pAl, predA);                          \
        cpasync16(stg + 8192,  pBh, true);                           \
        cpasync16(stg + 12288, pBl, true);                           \
        cp_commit();                                                 \
        pAh += 32; pAl += 32; pBh += 32; pBl += 32;                  \
    } while (0)

    float acc[4][4][4];
#pragma unroll
    for (int a = 0; a < 4; a++)
#pragma unroll
        for (int b = 0; b < 4; b++)
#pragma unroll
            for (int c = 0; c < 4; c++) acc[a][b][c] = 0.f;

    STAGE(0);

    int q = lane >> 3, lr = lane & 7;
    const uint32_t aoff0 = (uint32_t)((wm * 64 + (q & 1) * 8 + lr) * 32 + (q >> 1) * 16);
    const uint32_t boff0 = (uint32_t)((wn * 32 + (q >> 1) * 8 + lr) * 32 + (q & 1) * 16);

    for (int ch = 0; ch < nch; ch++) {
        cp_wait_all();          // stage ch complete (only pending group)
        __syncthreads();        // (a) staged data visible; (b) seals prev ldsm reads

        uint32_t stg = sb + (uint32_t)(ch & 1) * 16384;
        uint32_t Ah[4][4], Al[4][4], Bh[2][4], Bl[2][4];
#pragma unroll
        for (int mi = 0; mi < 4; mi++) {
            uint32_t a = stg + SWZ16(aoff0 + (uint32_t)(mi * 16 * 32));
            ldsm4(Ah[mi], a);
            ldsm4(Al[mi], a + 4096);
        }
#pragma unroll
        for (int p = 0; p < 2; p++) {
            uint32_t a = stg + 8192 + SWZ16(boff0 + (uint32_t)(p * 16 * 32));
            ldsm4(Bh[p], a);
            ldsm4(Bl[p], a + 4096);
        }
        if (ch + 1 < nch) STAGE((ch + 1) & 1);   // writes other buffer: no race

#pragma unroll
        for (int mi = 0; mi < 4; mi++)
#pragma unroll
            for (int ni = 0; ni < 4; ni++) {
                uint32_t bh0 = Bh[ni >> 1][(ni & 1) * 2], bh1 = Bh[ni >> 1][(ni & 1) * 2 + 1];
                uint32_t bl0 = Bl[ni >> 1][(ni & 1) * 2], bl1 = Bl[ni >> 1][(ni & 1) * 2 + 1];
                mma_bf16(acc[mi][ni], Ah[mi], bh0, bh1);
                mma_bf16(acc[mi][ni], Al[mi], bh0, bh1);
                mma_bf16(acc[mi][ni], Ah[mi], bl0, bl1);
            }
    }
#undef STAGE

    float* dstbase = (col0 < 256) ? g_yl : g_yr;
    int cb = col0 & 255;
    int tr = lane >> 2, tc = lane & 3;
#pragma unroll
    for (int mi = 0; mi < 4; mi++)
#pragma unroll
        for (int half = 0; half < 2; half++) {
            int row = row0 + wm * 64 + mi * 16 + tr + half * 8;
            if (row < NN) {
                float* p = dstbase + (size_t)row * 256 + cb + wn * 32 + tc * 2;
#pragma unroll
                for (int ni = 0; ni < 4; ni++) {
                    float2 v = make_float2(acc[mi][ni][half * 2], acc[mi][ni][half * 2 + 1]);
                    *(float2*)(p + ni * 8) = v;
                }
            }
        }
}

// ---------------- CSR aggregation + combine + BN stats (unroll-4 MLP) ----------------
__global__ __launch_bounds__(256) void agg_combine(const float* __restrict__ bl) {
    int c  = threadIdx.x;
    int r0 = blockIdx.x * 32;
    if (r0 >= NN) return;
    int r1 = min(r0 + 32, NN);
    float bias = bl[c];
    float s = 0.f, s2 = 0.f;
    for (int r = r0; r < r1; r++) {
        int beg = g_off[r];
        int end = (r == NN - 1) ? NE : g_off[r + 1];
        float a0 = 0.f, a1 = 0.f, a2 = 0.f, a3 = 0.f;
        int i = beg;
        for (; i + 4 <= end; i += 4) {
            int s0 = g_csr[i], s1 = g_csr[i + 1], s2i = g_csr[i + 2], s3 = g_csr[i + 3];
            float v0 = g_yl[(size_t)s0 * 256 + c];
            float v1 = g_yl[(size_t)s1 * 256 + c];
            float v2 = g_yl[(size_t)s2i * 256 + c];
            float v3 = g_yl[(size_t)s3 * 256 + c];
            a0 += v0; a1 += v1; a2 += v2; a3 += v3;
        }
        for (; i < end; i++) a0 += g_yl[(size_t)g_csr[i] * 256 + c];
        float acc = (a0 + a1) + (a2 + a3);
        float pre = acc * g_inv[r] + bias + g_yr[(size_t)r * 256 + c];
        g_m[(size_t)r * 256 + c] = pre;
        s += pre; s2 += pre * pre;
    }
    atomicAdd(&g_sum[c], (double)s);
    atomicAdd(&g_sumsq[c], (double)s2);
}

__global__ void finalize_bn(const float* __restrict__ gm, const float* __restrict__ bt) {
    int c = threadIdx.x;
    double mean = g_sum[c] / (double)NN;
    double var  = g_sumsq[c] / (double)NN - mean * mean;
    float rstd  = rsqrtf((float)var + 1e-5f);
    float sc    = rstd * gm[c];
    g_scale[c]  = sc;
    g_shift[c]  = bt[c] - (float)mean * sc;
}

// mode 1: bf16 hi/lo only; mode 2: bf16 + fp32 g_h
__global__ void bnrelu(int mode) {
    size_t i = (size_t)blockIdx.x * blockDim.x + threadIdx.x;
    if (i >= (size_t)NN * 64) return;
    size_t idx = i * 4;
    int c = (int)(idx & 255);
    float4 v = *(const float4*)(g_m + idx);
    v.x = fmaxf(v.x * g_scale[c + 0] + g_shift[c + 0], 0.f);
    v.y = fmaxf(v.y * g_scale[c + 1] + g_shift[c + 1], 0.f);
    v.z = fmaxf(v.z * g_scale[c + 2] + g_shift[c + 2], 0.f);
    v.w = fmaxf(v.w * g_scale[c + 3] + g_shift[c + 3], 0.f);
    __nv_bfloat162 h01, l01, h23, l23;
    split1(v.x, h01.x, l01.x);
    split1(v.y, h01.y, l01.y);
    split1(v.z, h23.x, l23.x);
    split1(v.w, h23.y, l23.y);
    uint2 uh, ul;
    uh.x = *(uint32_t*)&h01; uh.y = *(uint32_t*)&h23;
    ul.x = *(uint32_t*)&l01; ul.y = *(uint32_t*)&l23;
    *(uint2*)(g_ah + idx) = uh;
    *(uint2*)(g_al + idx) = ul;
    if (mode == 2) *(float4*)(g_h + idx) = v;
}

// ---------------- tanh-dot ----------------
__global__ __launch_bounds__(256) void tanhdot(const float* __restrict__ ba1,
                                               const float* __restrict__ Wa2,
                                               const float* __restrict__ ba2) {
    __shared__ float red[2][4];
    int tid = threadIdx.x, sub = tid >> 7, j = tid & 127;
    int n = blockIdx.x * 2 + sub;
    float t = 0.f;
    if (n < NN)
        t = tanhf(g_yl[(size_t)n * 256 + j] + ba1[j]) * Wa2[j];
#pragma unroll
    for (int o = 16; o; o >>= 1) t += __shfl_down_sync(0xffffffffu, t, o);
    if ((j & 31) == 0) red[sub][j >> 5] = t;
    __syncthreads();
    if (j == 0 && n < NN)
        g_s[n] = red[sub][0] + red[sub][1] + red[sub][2] + red[sub][3] + ba2[0];
}

// ---------------- per-graph softmax ----------------
__global__ void segmax_kernel() {
    int n  = blockIdx.x * blockDim.x + threadIdx.x;
    int nc = min(n, NN - 1);
    int g  = g_batch[nc];
    float v = (n < NN) ? g_s[n] : -3.4e38f;
    int g0 = __shfl_sync(0xffffffffu, g, 0);
    bool uni = __all_sync(0xffffffffu, g == g0);
    if (uni) {
#pragma unroll
        for (int o = 16; o; o >>= 1) v = fmaxf(v, __shfl_down_sync(0xffffffffu, v, o));
        if ((threadIdx.x & 31) == 0) atomicMaxFloat(&g_smax[g0], v);
    } else if (n < NN) {
        atomicMaxFloat(&g_smax[g], v);
    }
}

__global__ void expsum_kernel() {
    int n  = blockIdx.x * blockDim.x + threadIdx.x;
    int nc = min(n, NN - 1);
    int g  = g_batch[nc];
    float e = 0.f;
    if (n < NN) { e = expf(g_s[n] - g_smax[g]); g_w[n] = e; }
    int g0 = __shfl_sync(0xffffffffu, g, 0);
    bool uni = __all_sync(0xffffffffu, g == g0);
    if (uni) {
#pragma unroll
        for (int o = 16; o; o >>= 1) e += __shfl_down_sync(0xffffffffu, e, o);
        if ((threadIdx.x & 31) == 0) atomicAdd(&g_denom[g0], e);
    } else if (n < NN) {
        atomicAdd(&g_denom[g], e);
    }
}

__global__ void weights_kernel() {
    int n = blockIdx.x * blockDim.x + threadIdx.x;
    if (n < NN) g_w[n] = g_w[n] / g_denom[g_batch[n]];
}

// ---------------- weighted pooling ----------------
__global__ void pooled_kernel() {
    int c  = threadIdx.x;
    int r0 = blockIdx.x * 512;
    if (r0 >= NN) return;
    int r1  = min(r0 + 512, NN);
    int cur = g_batch[r0];
    float acc = 0.f;
    for (int r = r0; r < r1; r++) {
        int g = g_batch[r];
        if (g != cur) { atomicAdd(&g_pooled[cur * 256 + c], acc); acc = 0.f; cur = g; }
        acc += g_h[(size_t)r * 256 + c] * g_w[r];
    }
    atomicAdd(&g_pooled[cur * 256 + c], acc);
}

// ---------------- classifier ----------------
__global__ void classifier_kernel(const float* __restrict__ Wc1, const float* __restrict__ bc1,
                                  const float* __restrict__ Wc2, const float* __restrict__ bc2,
                                  float* __restrict__ out) {
    int g = blockIdx.x;
    int j = threadIdx.x;
    float acc = bc1[j];
    for (int k = 0; k < 256; k++) acc += g_pooled[g * 256 + k] * Wc1[k * 128 + j];
    float t = fmaxf(acc, 0.f) * Wc2[j];
#pragma unroll
    for (int o = 16; o; o >>= 1) t += __shfl_down_sync(0xffffffffu, t, o);
    __shared__ float red[4];
    if ((j & 31) == 0) red[j >> 5] = t;
    __syncthreads();
    if (j == 0) out[g] = red[0] + red[1] + red[2] + red[3] + bc2[0];
}

// ---------------- launch ----------------
extern "C" void kernel_launch(void* const* d_in, const int* in_sizes, int n_in,
                              void* d_out, int out_size) {
    const float* x     = (const float*)d_in[0];
    const void*  ei    = d_in[1];
    const void*  batch = d_in[2];
    const float* Wl[3] = {(const float*)d_in[3], (const float*)d_in[8],  (const float*)d_in[13]};
    const float* bl[3] = {(const float*)d_in[4], (const float*)d_in[9],  (const float*)d_in[14]};
    const float* Wr[3] = {(const float*)d_in[5], (const float*)d_in[10], (const float*)d_in[15]};
    const float* gg[3] = {(const float*)d_in[6], (const float*)d_in[11], (const float*)d_in[16]};
    const float* bb[3] = {(const float*)d_in[7], (const float*)d_in[12], (const float*)d_in[17]};
    const float* Wa1 = (const float*)d_in[18];
    const float* ba1 = (const float*)d_in[19];
    const float* Wa2 = (const float*)d_in[20];
    const float* ba2 = (const float*)d_in[21];
    const float* Wc1 = (const float*)d_in[22];
    const float* bc1 = (const float*)d_in[23];
    const float* Wc2 = (const float*)d_in[24];
    const float* bc2 = (const float*)d_in[25];
    float* out = (float*)d_out;

    // launches 1-4: layer-0 GEMM path first (4th launch = gemm_tc -> ncu capture slot)
    detect_dtype<<<1, 32>>>((const unsigned long long*)ei);
    split_a<<<(NN * (KP0 / 2) + 255) / 256, 256>>>(x);
    pack_wbT<<<(512 * (KP0 / 2) + 255) / 256, 256>>>(Wl[0], Wr[0], IND, KP0);
    {
        dim3 ggrid(4, (NN + 127) / 128);
        gemm_tc<<<ggrid, 256>>>(KP0);
    }

    // graph preprocessing
    cvt_edges<<<(NE + 255) / 256, 256>>>(ei);
    cvt_batch_zero<<<(NN + 255) / 256, 256>>>(batch);
    cnt_kernel<<<(NE + 255) / 256, 256>>>();
    scan1<<<NBLK, 256>>>();
    scan2<<<1, 512>>>();
    scan3<<<(NN + 255) / 256, 256>>>();
    place_kernel<<<(NE + 255) / 256, 256>>>();

    for (int L = 0; L < 3; L++) {
        if (L > 0) {
            pack_wbT<<<(512 * (HID / 2) + 255) / 256, 256>>>(Wl[L], Wr[L], HID, HID);
            dim3 ggrid(4, (NN + 127) / 128);
            gemm_tc<<<ggrid, 256>>>(HID);
        }
        zero_stats<<<1, 256>>>();
        agg_combine<<<(NN + 31) / 32, 256>>>(bl[L]);
        finalize_bn<<<1, 256>>>(gg[L], bb[L]);
        bnrelu<<<(NN * 64 + 255) / 256, 256>>>(L < 2 ? 1 : 2);
    }

    // attention score: S = h @ Wa1 via tensor GEMM (N=128 -> g_yl), then tanh-dot
    pack_wa<<<(128 * 128 + 255) / 256, 256>>>(Wa1);
    {
        dim3 sgrid(1, (NN + 127) / 128);
        gemm_tc<<<sgrid, 256>>>(HID);
    }
    tanhdot<<<(NN + 1) / 2, 256>>>(ba1, Wa2, ba2);

    init_pool<<<(NG * HID + 255) / 256, 256>>>();
    segmax_kernel<<<(NN + 255) / 256, 256>>>();
    expsum_kernel<<<(NN + 255) / 256, 256>>>();
    weights_kernel<<<(NN + 255) / 256, 256>>>();
    pooled_kernel<<<(NN + 511) / 512, 256>>>();
    classifier_kernel<<<NG, 128>>>(Wc1, bc1, Wc2, bc2, out);
}

// round 11
// speedup vs baseline: 1.0897x; 1.0446x over previous
#include <cuda_runtime.h>
#include <cuda_bf16.h>
#include <math.h>
#include <stdint.h>

#define NN 100000
#define NE 400000
#define IND 771
#define HID 256
#define NG 64
#define KP0 800            // padded K for layer 0
#define NBLK 391           // ceil(NN/256)

// ---------------- scratch (static device globals; no allocation) ----------------
__device__ float  g_yl[(size_t)NN * 256];    // lin_l pre-agg (also score-GEMM scratch)
__device__ float  g_yr[(size_t)NN * 256];    // lin_r part
__device__ float  g_m[(size_t)NN * 256];     // pre-BN
__device__ float  g_inv[NN];
__device__ double g_sum[256];
__device__ double g_sumsq[256];
__device__ float  g_scale[256];
__device__ float  g_shift[256];
__device__ float  g_s[NN];
__device__ float  g_w[NN];
__device__ float  g_smax[NG];
__device__ float  g_denom[NG];
__device__ float  g_pooled[NG * HID];
__device__ int    g_is64;
__device__ int    g_src[NE];
__device__ int    g_dst[NE];
__device__ int    g_batch[NN];
// CSR by dst
__device__ int    g_cnt[NN];
__device__ int    g_off[NN];
__device__ int    g_cur[NN];
__device__ int    g_csr[NE];
__device__ int    g_bsum[NBLK];
__device__ int    g_boff[NBLK];
// bf16 split operands
__device__ __nv_bfloat16 g_ah[(size_t)NN * KP0];
__device__ __nv_bfloat16 g_al[(size_t)NN * KP0];
__device__ __nv_bfloat16 g_bh[512 * KP0];
__device__ __nv_bfloat16 g_bl[512 * KP0];

// ---------------- helpers ----------------
__device__ __forceinline__ uint32_t smem_u32(const void* p) {
    uint32_t a;
    asm("{ .reg .u64 t; cvta.to.shared.u64 t, %1; cvt.u32.u64 %0, t; }" : "=r"(a) : "l"(p));
    return a;
}
// 16-row x 32B tiles: toggle 16B half by (row>>2)&1 -> conflict-free ldmatrix + stores
#define SWZ16(b) ((b) ^ ((((b) >> 7) & 1) << 4))

__device__ __forceinline__ void cpasync16(uint32_t dst, const void* src, bool pred) {
    int sz = pred ? 16 : 0;
    asm volatile("cp.async.cg.shared.global [%0], [%1], 16, %2;"
                 :: "r"(dst), "l"(src), "r"(sz) : "memory");
}
__device__ __forceinline__ void cp_commit() {
    asm volatile("cp.async.commit_group;" ::: "memory");
}
__device__ __forceinline__ void cp_wait1() {
    asm volatile("cp.async.wait_group 1;" ::: "memory");
}
__device__ __forceinline__ void ldsm4(uint32_t* r, uint32_t addr) {
    asm volatile("ldmatrix.sync.aligned.m8n8.x4.shared.b16 {%0,%1,%2,%3}, [%4];"
                 : "=r"(r[0]), "=r"(r[1]), "=r"(r[2]), "=r"(r[3]) : "r"(addr));
}
__device__ __forceinline__ void mma_bf16(float* c, const uint32_t* a, uint32_t b0, uint32_t b1) {
    asm volatile(
        "mma.sync.aligned.m16n8k16.row.col.f32.bf16.bf16.f32 "
        "{%0,%1,%2,%3}, {%4,%5,%6,%7}, {%8,%9}, {%0,%1,%2,%3};"
        : "+f"(c[0]), "+f"(c[1]), "+f"(c[2]), "+f"(c[3])
        : "r"(a[0]), "r"(a[1]), "r"(a[2]), "r"(a[3]), "r"(b0), "r"(b1));
}
__device__ __forceinline__ void atomicMaxFloat(float* addr, float val) {
    int* ai = (int*)addr;
    int old = __float_as_int(*addr);
    while (__int_as_float(old) < val) {
        int assumed = old;
        old = atomicCAS(ai, assumed, __float_as_int(val));
        if (old == assumed) break;
    }
}
__device__ __forceinline__ void split1(float v, __nv_bfloat16& h, __nv_bfloat16& l) {
    h = __float2bfloat16(v);
    l = __float2bfloat16(v - __bfloat162float(h));
}

// ---------------- dtype detection + index normalization ----------------
__global__ void detect_dtype(const unsigned long long* __restrict__ ei) {
    if (threadIdx.x == 0 && blockIdx.x == 0) {
        int is64 = 1;
        for (int i = 0; i < 64; i++)
            if (ei[i] >= (unsigned long long)NN) { is64 = 0; break; }
        g_is64 = is64;
    }
}
__global__ void cvt_edges(const void* __restrict__ ei) {
    int e = blockIdx.x * blockDim.x + threadIdx.x;
    if (e >= NE) return;
    if (g_is64) {
        const long long* p = (const long long*)ei;
        g_src[e] = (int)p[e];
        g_dst[e] = (int)p[NE + e];
    } else {
        const int* p = (const int*)ei;
        g_src[e] = p[e];
        g_dst[e] = p[NE + e];
    }
}
__global__ void cvt_batch_zero(const void* __restrict__ b) {
    int n = blockIdx.x * blockDim.x + threadIdx.x;
    if (n >= NN) return;
    if (g_is64) g_batch[n] = (int)((const long long*)b)[n];
    else        g_batch[n] = ((const int*)b)[n];
    g_cnt[n] = 0;
}

// ---------------- CSR build ----------------
__global__ void cnt_kernel() {
    int e = blockIdx.x * blockDim.x + threadIdx.x;
    if (e < NE) atomicAdd(&g_cnt[g_dst[e]], 1);
}
__global__ void scan1() {
    __shared__ int sm[256];
    int b = blockIdx.x, t = threadIdx.x;
    int i = b * 256 + t;
    int v = (i < NN) ? g_cnt[i] : 0;
    sm[t] = v; __syncthreads();
    for (int o = 1; o < 256; o <<= 1) {
        int u = (t >= o) ? sm[t - o] : 0;
        __syncthreads();
        sm[t] += u;
        __syncthreads();
    }
    if (i < NN) g_off[i] = sm[t] - v;
    if (t == 255) g_bsum[b] = sm[255];
}
__global__ void scan2() {
    __shared__ int sm[512];
    int t = threadIdx.x;
    int v = (t < NBLK) ? g_bsum[t] : 0;
    sm[t] = v; __syncthreads();
    for (int o = 1; o < 512; o <<= 1) {
        int u = (t >= o) ? sm[t - o] : 0;
        __syncthreads();
        sm[t] += u;
        __syncthreads();
    }
    if (t < NBLK) g_boff[t] = sm[t] - v;
}
__global__ void scan3() {
    int i = blockIdx.x * blockDim.x + threadIdx.x;
    if (i < NN) {
        int o = g_off[i] + g_boff[i >> 8];
        g_off[i] = o;
        g_cur[i] = o;
        g_inv[i] = 1.f / fmaxf((float)g_cnt[i], 1.f);
    }
}
__global__ void place_kernel() {
    int e = blockIdx.x * blockDim.x + threadIdx.x;
    if (e < NE) {
        int pos = atomicAdd(&g_cur[g_dst[e]], 1);
        g_csr[pos] = g_src[e];
    }
}

// ---------------- zero / init ----------------
__global__ void zero_stats() {
    int c = threadIdx.x;
    g_sum[c] = 0.0; g_sumsq[c] = 0.0;
}
__global__ void init_pool() {
    int i = blockIdx.x * blockDim.x + threadIdx.x;
    if (i < NG * HID) g_pooled[i] = 0.f;
    if (i < NG) { g_smax[i] = -3.4e38f; g_denom[i] = 0.f; }
}

// ---------------- split x (layer 0 only) ----------------
__global__ void split_a(const float* __restrict__ A) {
    int kp2 = KP0 >> 1;
    int i = blockIdx.x * blockDim.x + threadIdx.x;
    if (i >= NN * kp2) return;
    int n = i / kp2, k2 = (i - n * kp2) * 2;
    float v0 = (k2 < IND)     ? A[(size_t)n * IND + k2]     : 0.f;
    float v1 = (k2 + 1 < IND) ? A[(size_t)n * IND + k2 + 1] : 0.f;
    __nv_bfloat162 hp, lp;
    split1(v0, hp.x, lp.x);
    split1(v1, hp.y, lp.y);
    *(__nv_bfloat162*)(g_ah + (size_t)n * KP0 + k2) = hp;
    *(__nv_bfloat162*)(g_al + (size_t)n * KP0 + k2) = lp;
}

// ---------------- pack [Wl|Wr]^T ----------------
__global__ void pack_wbT(const float* __restrict__ Wl, const float* __restrict__ Wr,
                         int K, int KP) {
    int kp2 = KP >> 1;
    int i = blockIdx.x * blockDim.x + threadIdx.x;
    if (i >= 512 * kp2) return;
    int n = i / kp2, k2 = (i - n * kp2) * 2;
    const float* W = (n < 256) ? Wl : Wr;
    int c = (n < 256) ? n : n - 256;
    float v0 = (k2 < K)     ? W[(size_t)k2 * 256 + c]       : 0.f;
    float v1 = (k2 + 1 < K) ? W[(size_t)(k2 + 1) * 256 + c] : 0.f;
    __nv_bfloat162 hp, lp;
    split1(v0, hp.x, lp.x);
    split1(v1, hp.y, lp.y);
    *(__nv_bfloat162*)(g_bh + (size_t)n * KP + k2) = hp;
    *(__nv_bfloat162*)(g_bl + (size_t)n * KP + k2) = lp;
}

// ---------------- pack Wa1^T (score GEMM B) ----------------
__global__ void pack_wa(const float* __restrict__ Wa1) {
    int i = blockIdx.x * blockDim.x + threadIdx.x;
    if (i >= 128 * 128) return;
    int n = i >> 7, k2 = (i & 127) * 2;
    float v0 = Wa1[(size_t)k2 * 128 + n];
    float v1 = Wa1[(size_t)(k2 + 1) * 128 + n];
    __nv_bfloat162 hp, lp;
    split1(v0, hp.x, lp.x);
    split1(v1, hp.y, lp.y);
    *(__nv_bfloat162*)(g_bh + (size_t)n * 256 + k2) = hp;
    *(__nv_bfloat162*)(g_bl + (size_t)n * 256 + k2) = lp;
}

// ---------------- split-bf16 GEMM: M128 x N128, 8 warps, k16 chunks ----------------
// R8 pipeline structure (proven best): 2-stage, wait_group 1, stage ch+1 at TOP of
// iter ch (full-iteration prefetch distance), two __syncthreads per chunk.
// Deltas vs R8: precomputed cp.async pointers (+32/chunk), 2-CTA/SM reg cap.
// stage (16KB): A_hi 0 | A_lo 4096 | B_hi 8192 | B_lo 12288
__global__ void __launch_bounds__(256, 2) gemm_tc(int KP) {
    __shared__ __align__(128) char sm_[32768];   // 2 x 16KB
    const uint32_t sb = smem_u32(sm_);
    int tid = threadIdx.x, lane = tid & 31, wid = tid >> 5;
    int wm = wid >> 2, wn = wid & 3;         // 2 x 4 warps, warp tile 64x32
    int row0 = blockIdx.y * 128;
    int col0 = blockIdx.x * 128;
    int nch = KP >> 4;

    // per-thread staging sources: thread handles row r, 16B half s16
    int r = tid >> 1, s16 = (tid & 1) * 16;
    bool predA = (row0 + r) < NN;
    const char* pAh = (const char*)g_ah + ((size_t)(row0 + r) * KP) * 2 + s16;
    const char* pAl = (const char*)g_al + ((size_t)(row0 + r) * KP) * 2 + s16;
    const char* pBh = (const char*)g_bh + ((size_t)(col0 + r) * KP) * 2 + s16;
    const char* pBl = (const char*)g_bl + ((size_t)(col0 + r) * KP) * 2 + s16;
    if (!predA) { pAh = (const char*)g_ah + s16; pAl = (const char*)g_al + s16; }
    const uint32_t soff = SWZ16((uint32_t)(r * 32 + s16));

#define STAGE(BUF)                                                   \
    do {                                                             \
        uint32_t stg = sb + (uint32_t)(BUF) * 16384 + soff;          \
        cpasync16(stg,         pAh, predA);                          \
        cpasync16(stg + 4096,  pAl, predA);                          \
        cpasync16(stg + 8192,  pBh, true);                           \
        cpasync16(stg + 12288, pBl, true);                           \
        cp_commit();                                                 \
        pAh += 32; pAl += 32; pBh += 32; pBl += 32;                  \
    } while (0)

    float acc[4][4][4];
#pragma unroll
    for (int a = 0; a < 4; a++)
#pragma unroll
        for (int b = 0; b < 4; b++)
#pragma unroll
            for (int c = 0; c < 4; c++) acc[a][b][c] = 0.f;

    STAGE(0);

    int q = lane >> 3, lr = lane & 7;
    const uint32_t aoff0 = (uint32_t)((wm * 64 + (q & 1) * 8 + lr) * 32 + (q >> 1) * 16);
    const uint32_t boff0 = (uint32_t)((wn * 32 + (q >> 1) * 8 + lr) * 32 + (q & 1) * 16);

    for (int ch = 0; ch < nch; ch++) {
        // prefetch chunk ch+1 into other buffer (full-iteration distance)
        if (ch + 1 < nch) {
            STAGE((ch + 1) & 1);
        } else {
            cp_commit();   // keep group count in lockstep for wait1
        }
        cp_wait1();        // waits for stage ch only; stage ch+1 stays in flight
        __syncthreads();

        uint32_t stg = sb + (uint32_t)(ch & 1) * 16384;
        uint32_t Ah[4][4], Al[4][4], Bh[2][4], Bl[2][4];
#pragma unroll
        for (int mi = 0; mi < 4; mi++) {
            uint32_t a = stg + SWZ16(aoff0 + (uint32_t)(mi * 16 * 32));
            ldsm4(Ah[mi], a);
            ldsm4(Al[mi], a + 4096);
        }
#pragma unroll
        for (int p = 0; p < 2; p++) {
            uint32_t a = stg + 8192 + SWZ16(boff0 + (uint32_t)(p * 16 * 32));
            ldsm4(Bh[p], a);
            ldsm4(Bl[p], a + 4096);
        }
#pragma unroll
        for (int mi = 0; mi < 4; mi++)
#pragma unroll
            for (int ni = 0; ni < 4; ni++) {
                uint32_t bh0 = Bh[ni >> 1][(ni & 1) * 2], bh1 = Bh[ni >> 1][(ni & 1) * 2 + 1];
                uint32_t bl0 = Bl[ni >> 1][(ni & 1) * 2], bl1 = Bl[ni >> 1][(ni & 1) * 2 + 1];
                mma_bf16(acc[mi][ni], Ah[mi], bh0, bh1);
                mma_bf16(acc[mi][ni], Al[mi], bh0, bh1);
                mma_bf16(acc[mi][ni], Ah[mi], bl0, bl1);
            }
        __syncthreads();   // seals this buffer's reads before it is re-staged
    }
#undef STAGE

    float* dstbase = (col0 < 256) ? g_yl : g_yr;
    int cb = col0 & 255;
    int tr = lane >> 2, tc = lane & 3;
#pragma unroll
    for (int mi = 0; mi < 4; mi++)
#pragma unroll
        for (int half = 0; half < 2; half++) {
            int row = row0 + wm * 64 + mi * 16 + tr + half * 8;
            if (row < NN) {
                float* p = dstbase + (size_t)row * 256 + cb + wn * 32 + tc * 2;
#pragma unroll
                for (int ni = 0; ni < 4; ni++) {
                    float2 v = make_float2(acc[mi][ni][half * 2], acc[mi][ni][half * 2 + 1]);
                    *(float2*)(p + ni * 8) = v;
                }
            }
        }
}

// ---------------- CSR aggregation + combine + BN stats (unroll-4 MLP) ----------------
__global__ __launch_bounds__(256) void agg_combine(const float* __restrict__ bl) {
    int c  = threadIdx.x;
    int r0 = blockIdx.x * 32;
    if (r0 >= NN) return;
    int r1 = min(r0 + 32, NN);
    float bias = bl[c];
    float s = 0.f, s2 = 0.f;
    for (int r = r0; r < r1; r++) {
        int beg = g_off[r];
        int end = (r == NN - 1) ? NE : g_off[r + 1];
        float a0 = 0.f, a1 = 0.f, a2 = 0.f, a3 = 0.f;
        int i = beg;
        for (; i + 4 <= end; i += 4) {
            int s0 = g_csr[i], s1 = g_csr[i + 1], s2i = g_csr[i + 2], s3 = g_csr[i + 3];
            float v0 = g_yl[(size_t)s0 * 256 + c];
            float v1 = g_yl[(size_t)s1 * 256 + c];
            float v2 = g_yl[(size_t)s2i * 256 + c];
            float v3 = g_yl[(size_t)s3 * 256 + c];
            a0 += v0; a1 += v1; a2 += v2; a3 += v3;
        }
        for (; i < end; i++) a0 += g_yl[(size_t)g_csr[i] * 256 + c];
        float acc = (a0 + a1) + (a2 + a3);
        float pre = acc * g_inv[r] + bias + g_yr[(size_t)r * 256 + c];
        g_m[(size_t)r * 256 + c] = pre;
        s += pre; s2 += pre * pre;
    }
    atomicAdd(&g_sum[c], (double)s);
    atomicAdd(&g_sumsq[c], (double)s2);
}

__global__ void finalize_bn(const float* __restrict__ gm, const float* __restrict__ bt) {
    int c = threadIdx.x;
    double mean = g_sum[c] / (double)NN;
    double var  = g_sumsq[c] / (double)NN - mean * mean;
    float rstd  = rsqrtf((float)var + 1e-5f);
    float sc    = rstd * gm[c];
    g_scale[c]  = sc;
    g_shift[c]  = bt[c] - (float)mean * sc;
}

// bnrelu: always writes bf16 hi/lo split (next GEMM input; hi+lo reconstructs fp32)
__global__ void bnrelu() {
    size_t i = (size_t)blockIdx.x * blockDim.x + threadIdx.x;
    if (i >= (size_t)NN * 64) return;
    size_t idx = i * 4;
    int c = (int)(idx & 255);
    float4 v = *(const float4*)(g_m + idx);
    v.x = fmaxf(v.x * g_scale[c + 0] + g_shift[c + 0], 0.f);
    v.y = fmaxf(v.y * g_scale[c + 1] + g_shift[c + 1], 0.f);
    v.z = fmaxf(v.z * g_scale[c + 2] + g_shift[c + 2], 0.f);
    v.w = fmaxf(v.w * g_scale[c + 3] + g_shift[c + 3], 0.f);
    __nv_bfloat162 h01, l01, h23, l23;
    split1(v.x, h01.x, l01.x);
    split1(v.y, h01.y, l01.y);
    split1(v.z, h23.x, l23.x);
    split1(v.w, h23.y, l23.y);
    uint2 uh, ul;
    uh.x = *(uint32_t*)&h01; uh.y = *(uint32_t*)&h23;
    ul.x = *(uint32_t*)&l01; ul.y = *(uint32_t*)&l23;
    *(uint2*)(g_ah + idx) = uh;
    *(uint2*)(g_al + idx) = ul;
}

// ---------------- tanh-dot ----------------
__global__ __launch_bounds__(256) void tanhdot(const float* __restrict__ ba1,
                                               const float* __restrict__ Wa2,
                                               const float* __restrict__ ba2) {
    __shared__ float red[2][4];
    int tid = threadIdx.x, sub = tid >> 7, j = tid & 127;
    int n = blockIdx.x * 2 + sub;
    float t = 0.f;
    if (n < NN)
        t = tanhf(g_yl[(size_t)n * 256 + j] + ba1[j]) * Wa2[j];
#pragma unroll
    for (int o = 16; o; o >>= 1) t += __shfl_down_sync(0xffffffffu, t, o);
    if ((j & 31) == 0) red[sub][j >> 5] = t;
    __syncthreads();
    if (j == 0 && n < NN)
        g_s[n] = red[sub][0] + red[sub][1] + red[sub][2] + red[sub][3] + ba2[0];
}

// ---------------- per-graph softmax ----------------
__global__ void segmax_kernel() {
    int n  = blockIdx.x * blockDim.x + threadIdx.x;
    int nc = min(n, NN - 1);
    int g  = g_batch[nc];
    float v = (n < NN) ? g_s[n] : -3.4e38f;
    int g0 = __shfl_sync(0xffffffffu, g, 0);
    bool uni = __all_sync(0xffffffffu, g == g0);
    if (uni) {
#pragma unroll
        for (int o = 16; o; o >>= 1) v = fmaxf(v, __shfl_down_sync(0xffffffffu, v, o));
        if ((threadIdx.x & 31) == 0) atomicMaxFloat(&g_smax[g0], v);
    } else if (n < NN) {
        atomicMaxFloat(&g_smax[g], v);
    }
}

__global__ void expsum_kernel() {
    int n  = blockIdx.x * blockDim.x + threadIdx.x;
    int nc = min(n, NN - 1);
    int g  = g_batch[nc];
    float e = 0.f;
    if (n < NN) { e = expf(g_s[n] - g_smax[g]); g_w[n] = e; }
    int g0 = __shfl_sync(0xffffffffu, g, 0);
    bool uni = __all_sync(0xffffffffu, g == g0);
    if (uni) {
#pragma unroll
        for (int o = 16; o; o >>= 1) e += __shfl_down_sync(0xffffffffu, e, o);
        if ((threadIdx.x & 31) == 0) atomicAdd(&g_denom[g0], e);
    } else if (n < NN) {
        atomicAdd(&g_denom[g], e);
    }
}

__global__ void weights_kernel() {
    int n = blockIdx.x * blockDim.x + threadIdx.x;
    if (n < NN) g_w[n] = g_w[n] / g_denom[g_batch[n]];
}

// ---------------- weighted pooling (h reconstructed from bf16 hi+lo) ----------------
__global__ void pooled_kernel() {
    int c  = threadIdx.x;
    int r0 = blockIdx.x * 512;
    if (r0 >= NN) return;
    int r1  = min(r0 + 512, NN);
    int cur = g_batch[r0];
    float acc = 0.f;
    for (int r = r0; r < r1; r++) {
        int g = g_batch[r];
        if (g != cur) { atomicAdd(&g_pooled[cur * 256 + c], acc); acc = 0.f; cur = g; }
        float h = __bfloat162float(g_ah[(size_t)r * 256 + c]) +
                  __bfloat162float(g_al[(size_t)r * 256 + c]);
        acc += h * g_w[r];
    }
    atomicAdd(&g_pooled[cur * 256 + c], acc);
}

// ---------------- classifier ----------------
__global__ void classifier_kernel(const float* __restrict__ Wc1, const float* __restrict__ bc1,
                                  const float* __restrict__ Wc2, const float* __restrict__ bc2,
                                  float* __restrict__ out) {
    int g = blockIdx.x;
    int j = threadIdx.x;
    float acc = bc1[j];
    for (int k = 0; k < 256; k++) acc += g_pooled[g * 256 + k] * Wc1[k * 128 + j];
    float t = fmaxf(acc, 0.f) * Wc2[j];
#pragma unroll
    for (int o = 16; o; o >>= 1) t += __shfl_down_sync(0xffffffffu, t, o);
    __shared__ float red[4];
    if ((j & 31) == 0) red[j >> 5] = t;
    __syncthreads();
    if (j == 0) out[g] = red[0] + red[1] + red[2] + red[3] + bc2[0];
}

// ---------------- launch ----------------
extern "C" void kernel_launch(void* const* d_in, const int* in_sizes, int n_in,
                              void* d_out, int out_size) {
    const float* x     = (const float*)d_in[0];
    const void*  ei    = d_in[1];
    const void*  batch = d_in[2];
    const float* Wl[3] = {(const float*)d_in[3], (const float*)d_in[8],  (const float*)d_in[13]};
    const float* bl[3] = {(const float*)d_in[4], (const float*)d_in[9],  (const float*)d_in[14]};
    const float* Wr[3] = {(const float*)d_in[5], (const float*)d_in[10], (const float*)d_in[15]};
    const float* gg[3] = {(const float*)d_in[6], (const float*)d_in[11], (const float*)d_in[16]};
    const float* bb[3] = {(const float*)d_in[7], (const float*)d_in[12], (const float*)d_in[17]};
    const float* Wa1 = (const float*)d_in[18];
    const float* ba1 = (const float*)d_in[19];
    const float* Wa2 = (const float*)d_in[20];
    const float* ba2 = (const float*)d_in[21];
    const float* Wc1 = (const float*)d_in[22];
    const float* bc1 = (const float*)d_in[23];
    const float* Wc2 = (const float*)d_in[24];
    const float* bc2 = (const float*)d_in[25];
    float* out = (float*)d_out;

    // launches 1-4: layer-0 GEMM path first (4th launch = gemm_tc -> ncu capture slot)
    detect_dtype<<<1, 32>>>((const unsigned long long*)ei);
    split_a<<<(NN * (KP0 / 2) + 255) / 256, 256>>>(x);
    pack_wbT<<<(512 * (KP0 / 2) + 255) / 256, 256>>>(Wl[0], Wr[0], IND, KP0);
    {
        dim3 ggrid(4, (NN + 127) / 128);
        gemm_tc<<<ggrid, 256>>>(KP0);
    }

    // graph preprocessing
    cvt_edges<<<(NE + 255) / 256, 256>>>(ei);
    cvt_batch_zero<<<(NN + 255) / 256, 256>>>(batch);
    cnt_kernel<<<(NE + 255) / 256, 256>>>();
    scan1<<<NBLK, 256>>>();
    scan2<<<1, 512>>>();
    scan3<<<(NN + 255) / 256, 256>>>();
    place_kernel<<<(NE + 255) / 256, 256>>>();

    for (int L = 0; L < 3; L++) {
        if (L > 0) {
            pack_wbT<<<(512 * (HID / 2) + 255) / 256, 256>>>(Wl[L], Wr[L], HID, HID);
            dim3 ggrid(4, (NN + 127) / 128);
            gemm_tc<<<ggrid, 256>>>(HID);
        }
        zero_stats<<<1, 256>>>();
        agg_combine<<<(NN + 31) / 32, 256>>>(bl[L]);
        finalize_bn<<<1, 256>>>(gg[L], bb[L]);
        bnrelu<<<(NN * 64 + 255) / 256, 256>>>();
    }

    // attention score: S = h @ Wa1 via tensor GEMM (N=128 -> g_yl), then tanh-dot
    pack_wa<<<(128 * 128 + 255) / 256, 256>>>(Wa1);
    {
        dim3 sgrid(1, (NN + 127) / 128);
        gemm_tc<<<sgrid, 256>>>(HID);
    }
    tanhdot<<<(NN + 1) / 2, 256>>>(ba1, Wa2, ba2);

    init_pool<<<(NG * HID + 255) / 256, 256>>>();
    segmax_kernel<<<(NN + 255) / 256, 256>>>();
    expsum_kernel<<<(NN + 255) / 256, 256>>>();
    weights_kernel<<<(NN + 255) / 256, 256>>>();
    pooled_kernel<<<(NN + 511) / 512, 256>>>();
    classifier_kernel<<<NG, 128>>>(Wc1, bc1, Wc2, bc2, out);
}

// round 13
// speedup vs baseline: 1.0976x; 1.0073x over previous
#include <cuda_runtime.h>
#include <cuda_bf16.h>
#include <math.h>
#include <stdint.h>

#define NN 100000
#define NE 400000
#define IND 771
#define HID 256
#define NG 64
#define KP0 800            // padded K for layer 0
#define NBLK 391           // ceil(NN/256)

// ---------------- scratch (static device globals; no allocation) ----------------
__device__ float  g_yl[(size_t)NN * 256];    // lin_l pre-agg (also score-GEMM scratch)
__device__ float  g_yr[(size_t)NN * 256];    // lin_r part
__device__ float  g_m[(size_t)NN * 256];     // pre-BN
__device__ float  g_inv[NN];
__device__ double g_sum[256];
__device__ double g_sumsq[256];
__device__ float  g_scale[256];
__device__ float  g_shift[256];
__device__ float  g_s[NN];
__device__ float  g_w[NN];
__device__ float  g_smax[NG];
__device__ float  g_denom[NG];
__device__ float  g_pooled[NG * HID];
__device__ int    g_is64;
__device__ int    g_src[NE];
__device__ int    g_dst[NE];
__device__ int    g_batch[NN];
// CSR by dst
__device__ int    g_cnt[NN];
__device__ int    g_off[NN];
__device__ int    g_cur[NN];
__device__ int    g_csr[NE];
__device__ int    g_bsum[NBLK];
__device__ int    g_boff[NBLK];
// bf16 split operands
__device__ __nv_bfloat16 g_ah[(size_t)NN * KP0];
__device__ __nv_bfloat16 g_al[(size_t)NN * KP0];
__device__ __nv_bfloat16 g_bh[512 * KP0];
__device__ __nv_bfloat16 g_bl[512 * KP0];

// ---------------- helpers ----------------
__device__ __forceinline__ uint32_t smem_u32(const void* p) {
    uint32_t a;
    asm("{ .reg .u64 t; cvta.to.shared.u64 t, %1; cvt.u32.u64 %0, t; }" : "=r"(a) : "l"(p));
    return a;
}
// 16-row x 32B tiles: toggle 16B half by (row>>2)&1 -> conflict-free ldmatrix + stores
#define SWZ16(b) ((b) ^ ((((b) >> 7) & 1) << 4))

__device__ __forceinline__ void cpasync16(uint32_t dst, const void* src, bool pred) {
    int sz = pred ? 16 : 0;
    asm volatile("cp.async.cg.shared.global [%0], [%1], 16, %2;"
                 :: "r"(dst), "l"(src), "r"(sz) : "memory");
}
__device__ __forceinline__ void cp_commit() {
    asm volatile("cp.async.commit_group;" ::: "memory");
}
__device__ __forceinline__ void cp_wait1() {
    asm volatile("cp.async.wait_group 1;" ::: "memory");
}
__device__ __forceinline__ void ldsm4(uint32_t* r, uint32_t addr) {
    asm volatile("ldmatrix.sync.aligned.m8n8.x4.shared.b16 {%0,%1,%2,%3}, [%4];"
                 : "=r"(r[0]), "=r"(r[1]), "=r"(r[2]), "=r"(r[3]) : "r"(addr));
}
__device__ __forceinline__ void mma_bf16(float* c, const uint32_t* a, uint32_t b0, uint32_t b1) {
    asm volatile(
        "mma.sync.aligned.m16n8k16.row.col.f32.bf16.bf16.f32 "
        "{%0,%1,%2,%3}, {%4,%5,%6,%7}, {%8,%9}, {%0,%1,%2,%3};"
        : "+f"(c[0]), "+f"(c[1]), "+f"(c[2]), "+f"(c[3])
        : "r"(a[0]), "r"(a[1]), "r"(a[2]), "r"(a[3]), "r"(b0), "r"(b1));
}
__device__ __forceinline__ void atomicMaxFloat(float* addr, float val) {
    int* ai = (int*)addr;
    int old = __float_as_int(*addr);
    while (__int_as_float(old) < val) {
        int assumed = old;
        old = atomicCAS(ai, assumed, __float_as_int(val));
        if (old == assumed) break;
    }
}
__device__ __forceinline__ void split1(float v, __nv_bfloat16& h, __nv_bfloat16& l) {
    h = __float2bfloat16(v);
    l = __float2bfloat16(v - __bfloat162float(h));
}

// ---------------- dtype detection + index normalization ----------------
__global__ void detect_dtype(const unsigned long long* __restrict__ ei) {
    if (threadIdx.x == 0 && blockIdx.x == 0) {
        int is64 = 1;
        for (int i = 0; i < 64; i++)
            if (ei[i] >= (unsigned long long)NN) { is64 = 0; break; }
        g_is64 = is64;
    }
}
__global__ void cvt_edges(const void* __restrict__ ei) {
    int e = blockIdx.x * blockDim.x + threadIdx.x;
    if (e >= NE) return;
    if (g_is64) {
        const long long* p = (const long long*)ei;
        g_src[e] = (int)p[e];
        g_dst[e] = (int)p[NE + e];
    } else {
        const int* p = (const int*)ei;
        g_src[e] = p[e];
        g_dst[e] = p[NE + e];
    }
}
__global__ void cvt_batch_zero(const void* __restrict__ b) {
    int n = blockIdx.x * blockDim.x + threadIdx.x;
    if (n >= NN) return;
    if (g_is64) g_batch[n] = (int)((const long long*)b)[n];
    else        g_batch[n] = ((const int*)b)[n];
    g_cnt[n] = 0;
}

// ---------------- CSR build ----------------
__global__ void cnt_kernel() {
    int e = blockIdx.x * blockDim.x + threadIdx.x;
    if (e < NE) atomicAdd(&g_cnt[g_dst[e]], 1);
}
__global__ void scan1() {
    __shared__ int sm[256];
    int b = blockIdx.x, t = threadIdx.x;
    int i = b * 256 + t;
    int v = (i < NN) ? g_cnt[i] : 0;
    sm[t] = v; __syncthreads();
    for (int o = 1; o < 256; o <<= 1) {
        int u = (t >= o) ? sm[t - o] : 0;
        __syncthreads();
        sm[t] += u;
        __syncthreads();
    }
    if (i < NN) g_off[i] = sm[t] - v;
    if (t == 255) g_bsum[b] = sm[255];
}
__global__ void scan2() {
    __shared__ int sm[512];
    int t = threadIdx.x;
    int v = (t < NBLK) ? g_bsum[t] : 0;
    sm[t] = v; __syncthreads();
    for (int o = 1; o < 512; o <<= 1) {
        int u = (t >= o) ? sm[t - o] : 0;
        __syncthreads();
        sm[t] += u;
        __syncthreads();
    }
    if (t < NBLK) g_boff[t] = sm[t] - v;
}
__global__ void scan3() {
    int i = blockIdx.x * blockDim.x + threadIdx.x;
    if (i < NN) {
        int o = g_off[i] + g_boff[i >> 8];
        g_off[i] = o;
        g_cur[i] = o;
        g_inv[i] = 1.f / fmaxf((float)g_cnt[i], 1.f);
    }
}
__global__ void place_kernel() {
    int e = blockIdx.x * blockDim.x + threadIdx.x;
    if (e < NE) {
        int pos = atomicAdd(&g_cur[g_dst[e]], 1);
        g_csr[pos] = g_src[e];
    }
}

// ---------------- zero / init ----------------
__global__ void zero_stats() {
    int c = threadIdx.x;
    g_sum[c] = 0.0; g_sumsq[c] = 0.0;
}
__global__ void init_pool() {
    int i = blockIdx.x * blockDim.x + threadIdx.x;
    if (i < NG * HID) g_pooled[i] = 0.f;
    if (i < NG) { g_smax[i] = -3.4e38f; g_denom[i] = 0.f; }
}

// ---------------- split x (layer 0 only) ----------------
__global__ void split_a(const float* __restrict__ A) {
    int kp2 = KP0 >> 1;
    int i = blockIdx.x * blockDim.x + threadIdx.x;
    if (i >= NN * kp2) return;
    int n = i / kp2, k2 = (i - n * kp2) * 2;
    float v0 = (k2 < IND)     ? A[(size_t)n * IND + k2]     : 0.f;
    float v1 = (k2 + 1 < IND) ? A[(size_t)n * IND + k2 + 1] : 0.f;
    __nv_bfloat162 hp, lp;
    split1(v0, hp.x, lp.x);
    split1(v1, hp.y, lp.y);
    *(__nv_bfloat162*)(g_ah + (size_t)n * KP0 + k2) = hp;
    *(__nv_bfloat162*)(g_al + (size_t)n * KP0 + k2) = lp;
}

// ---------------- pack [Wl|Wr]^T ----------------
__global__ void pack_wbT(const float* __restrict__ Wl, const float* __restrict__ Wr,
                         int K, int KP) {
    int kp2 = KP >> 1;
    int i = blockIdx.x * blockDim.x + threadIdx.x;
    if (i >= 512 * kp2) return;
    int n = i / kp2, k2 = (i - n * kp2) * 2;
    const float* W = (n < 256) ? Wl : Wr;
    int c = (n < 256) ? n : n - 256;
    float v0 = (k2 < K)     ? W[(size_t)k2 * 256 + c]       : 0.f;
    float v1 = (k2 + 1 < K) ? W[(size_t)(k2 + 1) * 256 + c] : 0.f;
    __nv_bfloat162 hp, lp;
    split1(v0, hp.x, lp.x);
    split1(v1, hp.y, lp.y);
    *(__nv_bfloat162*)(g_bh + (size_t)n * KP + k2) = hp;
    *(__nv_bfloat162*)(g_bl + (size_t)n * KP + k2) = lp;
}

// ---------------- pack Wa1^T (score GEMM B) ----------------
__global__ void pack_wa(const float* __restrict__ Wa1) {
    int i = blockIdx.x * blockDim.x + threadIdx.x;
    if (i >= 128 * 128) return;
    int n = i >> 7, k2 = (i & 127) * 2;
    float v0 = Wa1[(size_t)k2 * 128 + n];
    float v1 = Wa1[(size_t)(k2 + 1) * 128 + n];
    __nv_bfloat162 hp, lp;
    split1(v0, hp.x, lp.x);
    split1(v1, hp.y, lp.y);
    *(__nv_bfloat162*)(g_bh + (size_t)n * 256 + k2) = hp;
    *(__nv_bfloat162*)(g_bl + (size_t)n * 256 + k2) = lp;
}

// ---------------- split-bf16 GEMM: M128 x N128, 8 warps, k16 chunks ----------------
// 3-stage cp.async pipeline (48KB), ONE __syncthreads per chunk, prefetch distance 2.
// iter ch: wait_group 1 (group ch done) -> __syncthreads (visibility + seals iter
// ch-1 reads) -> STAGE((ch+2)%3) (safe: = buf((ch-1)%3), readers sealed; differs
// from ldsm buf ch%3) -> ldsm(ch) -> MMA(ch).
// stage (16KB): A_hi 0 | A_lo 4096 | B_hi 8192 | B_lo 12288
__global__ void __launch_bounds__(256, 2) gemm_tc(int KP) {
    __shared__ __align__(128) char sm_[49152];   // 3 x 16KB
    const uint32_t sb = smem_u32(sm_);
    int tid = threadIdx.x, lane = tid & 31, wid = tid >> 5;
    int wm = wid >> 2, wn = wid & 3;         // 2 x 4 warps, warp tile 64x32
    int row0 = blockIdx.y * 128;
    int col0 = blockIdx.x * 128;
    int nch = KP >> 4;

    // per-thread staging sources: thread handles row r, 16B half s16
    int r = tid >> 1, s16 = (tid & 1) * 16;
    bool predA = (row0 + r) < NN;
    const char* pAh = (const char*)g_ah + ((size_t)(row0 + r) * KP) * 2 + s16;
    const char* pAl = (const char*)g_al + ((size_t)(row0 + r) * KP) * 2 + s16;
    const char* pBh = (const char*)g_bh + ((size_t)(col0 + r) * KP) * 2 + s16;
    const char* pBl = (const char*)g_bl + ((size_t)(col0 + r) * KP) * 2 + s16;
    if (!predA) { pAh = (const char*)g_ah + s16; pAl = (const char*)g_al + s16; }
    const uint32_t soff = SWZ16((uint32_t)(r * 32 + s16));

#define STAGE(BUF)                                                   \
    do {                                                             \
        uint32_t stg = sb + (uint32_t)(BUF) * 16384 + soff;          \
        cpasync16(stg,         pAh, predA);                          \
        cpasync16(stg + 4096,  pAl, predA);                          \
        cpasync16(stg + 8192,  pBh, true);                           \
        cpasync16(stg + 12288, pBl, true);                           \
        cp_commit();                                                 \
        pAh += 32; pAl += 32; pBh += 32; pBl += 32;                  \
    } while (0)

    float acc[4][4][4];
#pragma unroll
    for (int a = 0; a < 4; a++)
#pragma unroll
        for (int b = 0; b < 4; b++)
#pragma unroll
            for (int c = 0; c < 4; c++) acc[a][b][c] = 0.f;

    STAGE(0);
    STAGE(1);

    int q = lane >> 3, lr = lane & 7;
    const uint32_t aoff0 = (uint32_t)((wm * 64 + (q & 1) * 8 + lr) * 32 + (q >> 1) * 16);
    const uint32_t boff0 = (uint32_t)((wn * 32 + (q >> 1) * 8 + lr) * 32 + (q & 1) * 16);

    int bufS = 2, bufC = 0;   // staging buf (ch+2)%3, compute buf ch%3
    for (int ch = 0; ch < nch; ch++) {
        cp_wait1();            // oldest pending (group ch) complete; ch+1 in flight
        __syncthreads();       // visibility of all threads' copies + seals iter ch-1 reads

        if (ch + 2 < nch) {
            STAGE(bufS);       // writes buf((ch-1)%3): readers sealed by barrier
        } else {
            cp_commit();       // keep group count in lockstep
        }
        bufS = (bufS == 2) ? 0 : bufS + 1;

        uint32_t stg = sb + (uint32_t)bufC * 16384;
        bufC = (bufC == 2) ? 0 : bufC + 1;

        uint32_t Ah[4][4], Al[4][4], Bh[2][4], Bl[2][4];
#pragma unroll
        for (int mi = 0; mi < 4; mi++) {
            uint32_t a = stg + SWZ16(aoff0 + (uint32_t)(mi * 16 * 32));
            ldsm4(Ah[mi], a);
            ldsm4(Al[mi], a + 4096);
        }
#pragma unroll
        for (int p = 0; p < 2; p++) {
            uint32_t a = stg + 8192 + SWZ16(boff0 + (uint32_t)(p * 16 * 32));
            ldsm4(Bh[p], a);
            ldsm4(Bl[p], a + 4096);
        }
#pragma unroll
        for (int mi = 0; mi < 4; mi++)
#pragma unroll
            for (int ni = 0; ni < 4; ni++) {
                uint32_t bh0 = Bh[ni >> 1][(ni & 1) * 2], bh1 = Bh[ni >> 1][(ni & 1) * 2 + 1];
                uint32_t bl0 = Bl[ni >> 1][(ni & 1) * 2], bl1 = Bl[ni >> 1][(ni & 1) * 2 + 1];
                mma_bf16(acc[mi][ni], Ah[mi], bh0, bh1);
                mma_bf16(acc[mi][ni], Al[mi], bh0, bh1);
                mma_bf16(acc[mi][ni], Ah[mi], bl0, bl1);
            }
    }
#undef STAGE

    float* dstbase = (col0 < 256) ? g_yl : g_yr;
    int cb = col0 & 255;
    int tr = lane >> 2, tc = lane & 3;
#pragma unroll
    for (int mi = 0; mi < 4; mi++)
#pragma unroll
        for (int half = 0; half < 2; half++) {
            int row = row0 + wm * 64 + mi * 16 + tr + half * 8;
            if (row < NN) {
                float* p = dstbase + (size_t)row * 256 + cb + wn * 32 + tc * 2;
#pragma unroll
                for (int ni = 0; ni < 4; ni++) {
                    float2 v = make_float2(acc[mi][ni][half * 2], acc[mi][ni][half * 2 + 1]);
                    *(float2*)(p + ni * 8) = v;
                }
            }
        }
}

// ---------------- CSR aggregation + combine + BN stats (unroll-4 MLP) ----------------
__global__ __launch_bounds__(256) void agg_combine(const float* __restrict__ bl) {
    int c  = threadIdx.x;
    int r0 = blockIdx.x * 32;
    if (r0 >= NN) return;
    int r1 = min(r0 + 32, NN);
    float bias = bl[c];
    float s = 0.f, s2 = 0.f;
    for (int r = r0; r < r1; r++) {
        int beg = g_off[r];
        int end = (r == NN - 1) ? NE : g_off[r + 1];
        float a0 = 0.f, a1 = 0.f, a2 = 0.f, a3 = 0.f;
        int i = beg;
        for (; i + 4 <= end; i += 4) {
            int s0 = g_csr[i], s1 = g_csr[i + 1], s2i = g_csr[i + 2], s3 = g_csr[i + 3];
            float v0 = g_yl[(size_t)s0 * 256 + c];
            float v1 = g_yl[(size_t)s1 * 256 + c];
            float v2 = g_yl[(size_t)s2i * 256 + c];
            float v3 = g_yl[(size_t)s3 * 256 + c];
            a0 += v0; a1 += v1; a2 += v2; a3 += v3;
        }
        for (; i < end; i++) a0 += g_yl[(size_t)g_csr[i] * 256 + c];
        float acc = (a0 + a1) + (a2 + a3);
        float pre = acc * g_inv[r] + bias + g_yr[(size_t)r * 256 + c];
        g_m[(size_t)r * 256 + c] = pre;
        s += pre; s2 += pre * pre;
    }
    atomicAdd(&g_sum[c], (double)s);
    atomicAdd(&g_sumsq[c], (double)s2);
}

// finalize + self-reset stats for the next layer
__global__ void finalize_bn(const float* __restrict__ gm, const float* __restrict__ bt) {
    int c = threadIdx.x;
    double mean = g_sum[c] / (double)NN;
    double var  = g_sumsq[c] / (double)NN - mean * mean;
    float rstd  = rsqrtf((float)var + 1e-5f);
    float sc    = rstd * gm[c];
    g_scale[c]  = sc;
    g_shift[c]  = bt[c] - (float)mean * sc;
    g_sum[c] = 0.0; g_sumsq[c] = 0.0;
}

// bnrelu: writes bf16 hi/lo split (next GEMM input; hi+lo reconstructs fp32)
__global__ void bnrelu() {
    size_t i = (size_t)blockIdx.x * blockDim.x + threadIdx.x;
    if (i >= (size_t)NN * 64) return;
    size_t idx = i * 4;
    int c = (int)(idx & 255);
    float4 v = *(const float4*)(g_m + idx);
    v.x = fmaxf(v.x * g_scale[c + 0] + g_shift[c + 0], 0.f);
    v.y = fmaxf(v.y * g_scale[c + 1] + g_shift[c + 1], 0.f);
    v.z = fmaxf(v.z * g_scale[c + 2] + g_shift[c + 2], 0.f);
    v.w = fmaxf(v.w * g_scale[c + 3] + g_shift[c + 3], 0.f);
    __nv_bfloat162 h01, l01, h23, l23;
    split1(v.x, h01.x, l01.x);
    split1(v.y, h01.y, l01.y);
    split1(v.z, h23.x, l23.x);
    split1(v.w, h23.y, l23.y);
    uint2 uh, ul;
    uh.x = *(uint32_t*)&h01; uh.y = *(uint32_t*)&h23;
    ul.x = *(uint32_t*)&l01; ul.y = *(uint32_t*)&l23;
    *(uint2*)(g_ah + idx) = uh;
    *(uint2*)(g_al + idx) = ul;
}

// ---------------- tanh-dot ----------------
__global__ __launch_bounds__(256) void tanhdot(const float* __restrict__ ba1,
                                               const float* __restrict__ Wa2,
                                               const float* __restrict__ ba2) {
    __shared__ float red[2][4];
    int tid = threadIdx.x, sub = tid >> 7, j = tid & 127;
    int n = blockIdx.x * 2 + sub;
    float t = 0.f;
    if (n < NN)
        t = tanhf(g_yl[(size_t)n * 256 + j] + ba1[j]) * Wa2[j];
#pragma unroll
    for (int o = 16; o; o >>= 1) t += __shfl_down_sync(0xffffffffu, t, o);
    if ((j & 31) == 0) red[sub][j >> 5] = t;
    __syncthreads();
    if (j == 0 && n < NN)
        g_s[n] = red[sub][0] + red[sub][1] + red[sub][2] + red[sub][3] + ba2[0];
}

// ---------------- per-graph softmax ----------------
__global__ void segmax_kernel() {
    int n  = blockIdx.x * blockDim.x + threadIdx.x;
    int nc = min(n, NN - 1);
    int g  = g_batch[nc];
    float v = (n < NN) ? g_s[n] : -3.4e38f;
    int g0 = __shfl_sync(0xffffffffu, g, 0);
    bool uni = __all_sync(0xffffffffu, g == g0);
    if (uni) {
#pragma unroll
        for (int o = 16; o; o >>= 1) v = fmaxf(v, __shfl_down_sync(0xffffffffu, v, o));
        if ((threadIdx.x & 31) == 0) atomicMaxFloat(&g_smax[g0], v);
    } else if (n < NN) {
        atomicMaxFloat(&g_smax[g], v);
    }
}

__global__ void expsum_kernel() {
    int n  = blockIdx.x * blockDim.x + threadIdx.x;
    int nc = min(n, NN - 1);
    int g  = g_batch[nc];
    float e = 0.f;
    if (n < NN) { e = expf(g_s[n] - g_smax[g]); g_w[n] = e; }
    int g0 = __shfl_sync(0xffffffffu, g, 0);
    bool uni = __all_sync(0xffffffffu, g == g0);
    if (uni) {
#pragma unroll
        for (int o = 16; o; o >>= 1) e += __shfl_down_sync(0xffffffffu, e, o);
        if ((threadIdx.x & 31) == 0) atomicAdd(&g_denom[g0], e);
    } else if (n < NN) {
        atomicAdd(&g_denom[g], e);
    }
}

__global__ void weights_kernel() {
    int n = blockIdx.x * blockDim.x + threadIdx.x;
    if (n < NN) g_w[n] = g_w[n] / g_denom[g_batch[n]];
}

// ---------------- weighted pooling (h reconstructed from bf16 hi+lo) ----------------
__global__ void pooled_kernel() {
    int c  = threadIdx.x;
    int r0 = blockIdx.x * 512;
    if (r0 >= NN) return;
    int r1  = min(r0 + 512, NN);
    int cur = g_batch[r0];
    float acc = 0.f;
    for (int r = r0; r < r1; r++) {
        int g = g_batch[r];
        if (g != cur) { atomicAdd(&g_pooled[cur * 256 + c], acc); acc = 0.f; cur = g; }
        float h = __bfloat162float(g_ah[(size_t)r * 256 + c]) +
                  __bfloat162float(g_al[(size_t)r * 256 + c]);
        acc += h * g_w[r];
    }
    atomicAdd(&g_pooled[cur * 256 + c], acc);
}

// ---------------- classifier ----------------
__global__ void classifier_kernel(const float* __restrict__ Wc1, const float* __restrict__ bc1,
                                  const float* __restrict__ Wc2, const float* __restrict__ bc2,
                                  float* __restrict__ out) {
    int g = blockIdx.x;
    int j = threadIdx.x;
    float acc = bc1[j];
    for (int k = 0; k < 256; k++) acc += g_pooled[g * 256 + k] * Wc1[k * 128 + j];
    float t = fmaxf(acc, 0.f) * Wc2[j];
#pragma unroll
    for (int o = 16; o; o >>= 1) t += __shfl_down_sync(0xffffffffu, t, o);
    __shared__ float red[4];
    if ((j & 31) == 0) red[j >> 5] = t;
    __syncthreads();
    if (j == 0) out[g] = red[0] + red[1] + red[2] + red[3] + bc2[0];
}

// ---------------- launch ----------------
extern "C" void kernel_launch(void* const* d_in, const int* in_sizes, int n_in,
                              void* d_out, int out_size) {
    const float* x     = (const float*)d_in[0];
    const void*  ei    = d_in[1];
    const void*  batch = d_in[2];
    const float* Wl[3] = {(const float*)d_in[3], (const float*)d_in[8],  (const float*)d_in[13]};
    const float* bl[3] = {(const float*)d_in[4], (const float*)d_in[9],  (const float*)d_in[14]};
    const float* Wr[3] = {(const float*)d_in[5], (const float*)d_in[10], (const float*)d_in[15]};
    const float* gg[3] = {(const float*)d_in[6], (const float*)d_in[11], (const float*)d_in[16]};
    const float* bb[3] = {(const float*)d_in[7], (const float*)d_in[12], (const float*)d_in[17]};
    const float* Wa1 = (const float*)d_in[18];
    const float* ba1 = (const float*)d_in[19];
    const float* Wa2 = (const float*)d_in[20];
    const float* ba2 = (const float*)d_in[21];
    const float* Wc1 = (const float*)d_in[22];
    const float* bc1 = (const float*)d_in[23];
    const float* Wc2 = (const float*)d_in[24];
    const float* bc2 = (const float*)d_in[25];
    float* out = (float*)d_out;

    // launches 1-4: layer-0 GEMM path first (4th launch = gemm_tc -> ncu capture slot)
    detect_dtype<<<1, 32>>>((const unsigned long long*)ei);
    split_a<<<(NN * (KP0 / 2) + 255) / 256, 256>>>(x);
    pack_wbT<<<(512 * (KP0 / 2) + 255) / 256, 256>>>(Wl[0], Wr[0], IND, KP0);
    {
        dim3 ggrid(4, (NN + 127) / 128);
        gemm_tc<<<ggrid, 256>>>(KP0);
    }

    // graph preprocessing
    cvt_edges<<<(NE + 255) / 256, 256>>>(ei);
    cvt_batch_zero<<<(NN + 255) / 256, 256>>>(batch);
    cnt_kernel<<<(NE + 255) / 256, 256>>>();
    scan1<<<NBLK, 256>>>();
    scan2<<<1, 512>>>();
    scan3<<<(NN + 255) / 256, 256>>>();
    place_kernel<<<(NE + 255) / 256, 256>>>();
    zero_stats<<<1, 256>>>();   // once; finalize_bn self-resets thereafter

    for (int L = 0; L < 3; L++) {
        if (L > 0) {
            pack_wbT<<<(512 * (HID / 2) + 255) / 256, 256>>>(Wl[L], Wr[L], HID, HID);
            dim3 ggrid(4, (NN + 127) / 128);
            gemm_tc<<<ggrid, 256>>>(HID);
        }
        agg_combine<<<(NN + 31) / 32, 256>>>(bl[L]);
        finalize_bn<<<1, 256>>>(gg[L], bb[L]);
        bnrelu<<<(NN * 64 + 255) / 256, 256>>>();
    }

    // attention score: S = h @ Wa1 via tensor GEMM (N=128 -> g_yl), then tanh-dot
    pack_wa<<<(128 * 128 + 255) / 256, 256>>>(Wa1);
    {
        dim3 sgrid(1, (NN + 127) / 128);
        gemm_tc<<<sgrid, 256>>>(HID);
    }
    tanhdot<<<(NN + 1) / 2, 256>>>(ba1, Wa2, ba2);

    init_pool<<<(NG * HID + 255) / 256, 256>>>();
    segmax_kernel<<<(NN + 255) / 256, 256>>>();
    expsum_kernel<<<(NN + 255) / 256, 256>>>();
    weights_kernel<<<(NN + 255) / 256, 256>>>();
    pooled_kernel<<<(NN + 511) / 512, 256>>>();
    classifier_kernel<<<NG, 128>>>(Wc1, bc1, Wc2, bc2, out);
}

// round 14
// speedup vs baseline: 1.1125x; 1.0135x over previous
#include <cuda_runtime.h>
#include <cuda_bf16.h>
#include <math.h>
#include <stdint.h>

#define NN 100000
#define NE 400000
#define IND 771
#define HID 256
#define NG 64
#define KP0 800            // padded K for layer 0
#define NBLK 391           // ceil(NN/256)

// ---------------- scratch (static device globals; no allocation) ----------------
__device__ float  g_yl[(size_t)NN * 256];    // lin_l pre-agg (also score-GEMM scratch)
__device__ float  g_yr[(size_t)NN * 256];    // lin_r part
__device__ float  g_m[(size_t)NN * 256];     // pre-BN
__device__ float  g_inv[NN];
__device__ double g_sum[256];
__device__ double g_sumsq[256];
__device__ float  g_scale[256];
__device__ float  g_shift[256];
__device__ float  g_s[NN];
__device__ float  g_w[NN];
__device__ float  g_pooled[NG * HID];
__device__ int    g_is64;
__device__ int    g_src[NE];
__device__ int    g_dst[NE];
__device__ int    g_batch[NN];
// CSR by dst
__device__ int    g_cnt[NN];
__device__ int    g_off[NN];
__device__ int    g_cur[NN];
__device__ int    g_csr[NE];
__device__ int    g_bsum[NBLK];
__device__ int    g_boff[NBLK];
// bf16 split operands
__device__ __nv_bfloat16 g_ah[(size_t)NN * KP0];
__device__ __nv_bfloat16 g_al[(size_t)NN * KP0];
__device__ __nv_bfloat16 g_bh[512 * KP0];
__device__ __nv_bfloat16 g_bl[512 * KP0];

// ---------------- helpers ----------------
__device__ __forceinline__ uint32_t smem_u32(const void* p) {
    uint32_t a;
    asm("{ .reg .u64 t; cvta.to.shared.u64 t, %1; cvt.u32.u64 %0, t; }" : "=r"(a) : "l"(p));
    return a;
}
// 16-row x 32B tiles: toggle 16B half by (row>>2)&1 -> conflict-free ldmatrix + stores
#define SWZ16(b) ((b) ^ ((((b) >> 7) & 1) << 4))

__device__ __forceinline__ void cpasync16(uint32_t dst, const void* src, bool pred) {
    int sz = pred ? 16 : 0;
    asm volatile("cp.async.cg.shared.global [%0], [%1], 16, %2;"
                 :: "r"(dst), "l"(src), "r"(sz) : "memory");
}
__device__ __forceinline__ void cp_commit() {
    asm volatile("cp.async.commit_group;" ::: "memory");
}
__device__ __forceinline__ void cp_wait1() {
    asm volatile("cp.async.wait_group 1;" ::: "memory");
}
__device__ __forceinline__ void ldsm4(uint32_t* r, uint32_t addr) {
    asm volatile("ldmatrix.sync.aligned.m8n8.x4.shared.b16 {%0,%1,%2,%3}, [%4];"
                 : "=r"(r[0]), "=r"(r[1]), "=r"(r[2]), "=r"(r[3]) : "r"(addr));
}
__device__ __forceinline__ void mma_bf16(float* c, const uint32_t* a, uint32_t b0, uint32_t b1) {
    asm volatile(
        "mma.sync.aligned.m16n8k16.row.col.f32.bf16.bf16.f32 "
        "{%0,%1,%2,%3}, {%4,%5,%6,%7}, {%8,%9}, {%0,%1,%2,%3};"
        : "+f"(c[0]), "+f"(c[1]), "+f"(c[2]), "+f"(c[3])
        : "r"(a[0]), "r"(a[1]), "r"(a[2]), "r"(a[3]), "r"(b0), "r"(b1));
}
__device__ __forceinline__ void split1(float v, __nv_bfloat16& h, __nv_bfloat16& l) {
    h = __float2bfloat16(v);
    l = __float2bfloat16(v - __bfloat162float(h));
}

// ---------------- dtype detection + index normalization ----------------
__global__ void detect_dtype(const unsigned long long* __restrict__ ei) {
    if (threadIdx.x == 0 && blockIdx.x == 0) {
        int is64 = 1;
        for (int i = 0; i < 64; i++)
            if (ei[i] >= (unsigned long long)NN) { is64 = 0; break; }
        g_is64 = is64;
    }
}
// zeroes g_cnt too -> must run BEFORE cvt_edges (which counts)
__global__ void cvt_batch_zero(const void* __restrict__ b) {
    int n = blockIdx.x * blockDim.x + threadIdx.x;
    if (n >= NN) return;
    if (g_is64) g_batch[n] = (int)((const long long*)b)[n];
    else        g_batch[n] = ((const int*)b)[n];
    g_cnt[n] = 0;
}
// convert edges + count degrees in one pass
__global__ void cvt_edges(const void* __restrict__ ei) {
    int e = blockIdx.x * blockDim.x + threadIdx.x;
    if (e >= NE) return;
    int s, d;
    if (g_is64) {
        const long long* p = (const long long*)ei;
        s = (int)p[e];
        d = (int)p[NE + e];
    } else {
        const int* p = (const int*)ei;
        s = p[e];
        d = p[NE + e];
    }
    g_src[e] = s;
    g_dst[e] = d;
    atomicAdd(&g_cnt[d], 1);
}

// ---------------- CSR build ----------------
__global__ void scan1() {
    __shared__ int sm[256];
    int b = blockIdx.x, t = threadIdx.x;
    int i = b * 256 + t;
    int v = (i < NN) ? g_cnt[i] : 0;
    sm[t] = v; __syncthreads();
    for (int o = 1; o < 256; o <<= 1) {
        int u = (t >= o) ? sm[t - o] : 0;
        __syncthreads();
        sm[t] += u;
        __syncthreads();
    }
    if (i < NN) g_off[i] = sm[t] - v;
    if (t == 255) g_bsum[b] = sm[255];
}
__global__ void scan2() {
    __shared__ int sm[512];
    int t = threadIdx.x;
    int v = (t < NBLK) ? g_bsum[t] : 0;
    sm[t] = v; __syncthreads();
    for (int o = 1; o < 512; o <<= 1) {
        int u = (t >= o) ? sm[t - o] : 0;
        __syncthreads();
        sm[t] += u;
        __syncthreads();
    }
    if (t < NBLK) g_boff[t] = sm[t] - v;
}
__global__ void scan3() {
    int i = blockIdx.x * blockDim.x + threadIdx.x;
    if (i < NN) {
        int o = g_off[i] + g_boff[i >> 8];
        g_off[i] = o;
        g_cur[i] = o;
        g_inv[i] = 1.f / fmaxf((float)g_cnt[i], 1.f);
    }
}
__global__ void place_kernel() {
    int e = blockIdx.x * blockDim.x + threadIdx.x;
    if (e < NE) {
        int pos = atomicAdd(&g_cur[g_dst[e]], 1);
        g_csr[pos] = g_src[e];
    }
}

// ---------------- zero / init ----------------
__global__ void zero_stats() {
    int c = threadIdx.x;
    g_sum[c] = 0.0; g_sumsq[c] = 0.0;
}
__global__ void init_pool() {
    int i = blockIdx.x * blockDim.x + threadIdx.x;
    if (i < NG * HID) g_pooled[i] = 0.f;
}

// ---------------- split x (layer 0 only) ----------------
__global__ void split_a(const float* __restrict__ A) {
    int kp2 = KP0 >> 1;
    int i = blockIdx.x * blockDim.x + threadIdx.x;
    if (i >= NN * kp2) return;
    int n = i / kp2, k2 = (i - n * kp2) * 2;
    float v0 = (k2 < IND)     ? A[(size_t)n * IND + k2]     : 0.f;
    float v1 = (k2 + 1 < IND) ? A[(size_t)n * IND + k2 + 1] : 0.f;
    __nv_bfloat162 hp, lp;
    split1(v0, hp.x, lp.x);
    split1(v1, hp.y, lp.y);
    *(__nv_bfloat162*)(g_ah + (size_t)n * KP0 + k2) = hp;
    *(__nv_bfloat162*)(g_al + (size_t)n * KP0 + k2) = lp;
}

// ---------------- pack [Wl|Wr]^T ----------------
__global__ void pack_wbT(const float* __restrict__ Wl, const float* __restrict__ Wr,
                         int K, int KP) {
    int kp2 = KP >> 1;
    int i = blockIdx.x * blockDim.x + threadIdx.x;
    if (i >= 512 * kp2) return;
    int n = i / kp2, k2 = (i - n * kp2) * 2;
    const float* W = (n < 256) ? Wl : Wr;
    int c = (n < 256) ? n : n - 256;
    float v0 = (k2 < K)     ? W[(size_t)k2 * 256 + c]       : 0.f;
    float v1 = (k2 + 1 < K) ? W[(size_t)(k2 + 1) * 256 + c] : 0.f;
    __nv_bfloat162 hp, lp;
    split1(v0, hp.x, lp.x);
    split1(v1, hp.y, lp.y);
    *(__nv_bfloat162*)(g_bh + (size_t)n * KP + k2) = hp;
    *(__nv_bfloat162*)(g_bl + (size_t)n * KP + k2) = lp;
}

// ---------------- pack Wa1^T (score GEMM B) ----------------
__global__ void pack_wa(const float* __restrict__ Wa1) {
    int i = blockIdx.x * blockDim.x + threadIdx.x;
    if (i >= 128 * 128) return;
    int n = i >> 7, k2 = (i & 127) * 2;
    float v0 = Wa1[(size_t)k2 * 128 + n];
    float v1 = Wa1[(size_t)(k2 + 1) * 128 + n];
    __nv_bfloat162 hp, lp;
    split1(v0, hp.x, lp.x);
    split1(v1, hp.y, lp.y);
    *(__nv_bfloat162*)(g_bh + (size_t)n * 256 + k2) = hp;
    *(__nv_bfloat162*)(g_bl + (size_t)n * 256 + k2) = lp;
}

// ---------------- split-bf16 GEMM: M128 x N128, 8 warps, k16 chunks ----------------
// 3-stage cp.async pipeline (48KB), ONE __syncthreads per chunk, prefetch distance 2.
// iter ch: wait_group 1 (group ch done) -> __syncthreads -> STAGE((ch+2)%3) ->
// ldsm(ch) -> MMA(ch).   [R13 structure, frozen]
__global__ void __launch_bounds__(256, 2) gemm_tc(int KP) {
    __shared__ __align__(128) char sm_[49152];   // 3 x 16KB
    const uint32_t sb = smem_u32(sm_);
    int tid = threadIdx.x, lane = tid & 31, wid = tid >> 5;
    int wm = wid >> 2, wn = wid & 3;         // 2 x 4 warps, warp tile 64x32
    int row0 = blockIdx.y * 128;
    int col0 = blockIdx.x * 128;
    int nch = KP >> 4;

    int r = tid >> 1, s16 = (tid & 1) * 16;
    bool predA = (row0 + r) < NN;
    const char* pAh = (const char*)g_ah + ((size_t)(row0 + r) * KP) * 2 + s16;
    const char* pAl = (const char*)g_al + ((size_t)(row0 + r) * KP) * 2 + s16;
    const char* pBh = (const char*)g_bh + ((size_t)(col0 + r) * KP) * 2 + s16;
    const char* pBl = (const char*)g_bl + ((size_t)(col0 + r) * KP) * 2 + s16;
    if (!predA) { pAh = (const char*)g_ah + s16; pAl = (const char*)g_al + s16; }
    const uint32_t soff = SWZ16((uint32_t)(r * 32 + s16));

#define STAGE(BUF)                                                   \
    do {                                                             \
        uint32_t stg = sb + (uint32_t)(BUF) * 16384 + soff;          \
        cpasync16(stg,         pAh, predA);                          \
        cpasync16(stg + 4096,  pAl, predA);                          \
        cpasync16(stg + 8192,  pBh, true);                           \
        cpasync16(stg + 12288, pBl, true);                           \
        cp_commit();                                                 \
        pAh += 32; pAl += 32; pBh += 32; pBl += 32;                  \
    } while (0)

    float acc[4][4][4];
#pragma unroll
    for (int a = 0; a < 4; a++)
#pragma unroll
        for (int b = 0; b < 4; b++)
#pragma unroll
            for (int c = 0; c < 4; c++) acc[a][b][c] = 0.f;

    STAGE(0);
    STAGE(1);

    int q = lane >> 3, lr = lane & 7;
    const uint32_t aoff0 = (uint32_t)((wm * 64 + (q & 1) * 8 + lr) * 32 + (q >> 1) * 16);
    const uint32_t boff0 = (uint32_t)((wn * 32 + (q >> 1) * 8 + lr) * 32 + (q & 1) * 16);

    int bufS = 2, bufC = 0;
    for (int ch = 0; ch < nch; ch++) {
        cp_wait1();            // oldest pending (group ch) complete
        __syncthreads();       // visibility + seals iter ch-1 reads

        if (ch + 2 < nch) {
            STAGE(bufS);       // writes buf((ch-1)%3): readers sealed
        } else {
            cp_commit();
        }
        bufS = (bufS == 2) ? 0 : bufS + 1;

        uint32_t stg = sb + (uint32_t)bufC * 16384;
        bufC = (bufC == 2) ? 0 : bufC + 1;

        uint32_t Ah[4][4], Al[4][4], Bh[2][4], Bl[2][4];
#pragma unroll
        for (int mi = 0; mi < 4; mi++) {
            uint32_t a = stg + SWZ16(aoff0 + (uint32_t)(mi * 16 * 32));
            ldsm4(Ah[mi], a);
            ldsm4(Al[mi], a + 4096);
        }
#pragma unroll
        for (int p = 0; p < 2; p++) {
            uint32_t a = stg + 8192 + SWZ16(boff0 + (uint32_t)(p * 16 * 32));
            ldsm4(Bh[p], a);
            ldsm4(Bl[p], a + 4096);
        }
#pragma unroll
        for (int mi = 0; mi < 4; mi++)
#pragma unroll
            for (int ni = 0; ni < 4; ni++) {
                uint32_t bh0 = Bh[ni >> 1][(ni & 1) * 2], bh1 = Bh[ni >> 1][(ni & 1) * 2 + 1];
                uint32_t bl0 = Bl[ni >> 1][(ni & 1) * 2], bl1 = Bl[ni >> 1][(ni & 1) * 2 + 1];
                mma_bf16(acc[mi][ni], Ah[mi], bh0, bh1);
                mma_bf16(acc[mi][ni], Al[mi], bh0, bh1);
                mma_bf16(acc[mi][ni], Ah[mi], bl0, bl1);
            }
    }
#undef STAGE

    float* dstbase = (col0 < 256) ? g_yl : g_yr;
    int cb = col0 & 255;
    int tr = lane >> 2, tc = lane & 3;
#pragma unroll
    for (int mi = 0; mi < 4; mi++)
#pragma unroll
        for (int half = 0; half < 2; half++) {
            int row = row0 + wm * 64 + mi * 16 + tr + half * 8;
            if (row < NN) {
                float* p = dstbase + (size_t)row * 256 + cb + wn * 32 + tc * 2;
#pragma unroll
                for (int ni = 0; ni < 4; ni++) {
                    float2 v = make_float2(acc[mi][ni][half * 2], acc[mi][ni][half * 2 + 1]);
                    *(float2*)(p + ni * 8) = v;
                }
            }
        }
}

// ---------------- CSR aggregation + combine + BN stats (unroll-4 MLP) ----------------
__global__ __launch_bounds__(256) void agg_combine(const float* __restrict__ bl) {
    int c  = threadIdx.x;
    int r0 = blockIdx.x * 32;
    if (r0 >= NN) return;
    int r1 = min(r0 + 32, NN);
    float bias = bl[c];
    float s = 0.f, s2 = 0.f;
    for (int r = r0; r < r1; r++) {
        int beg = g_off[r];
        int end = (r == NN - 1) ? NE : g_off[r + 1];
        float a0 = 0.f, a1 = 0.f, a2 = 0.f, a3 = 0.f;
        int i = beg;
        for (; i + 4 <= end; i += 4) {
            int s0 = g_csr[i], s1 = g_csr[i + 1], s2i = g_csr[i + 2], s3 = g_csr[i + 3];
            float v0 = g_yl[(size_t)s0 * 256 + c];
            float v1 = g_yl[(size_t)s1 * 256 + c];
            float v2 = g_yl[(size_t)s2i * 256 + c];
            float v3 = g_yl[(size_t)s3 * 256 + c];
            a0 += v0; a1 += v1; a2 += v2; a3 += v3;
        }
        for (; i < end; i++) a0 += g_yl[(size_t)g_csr[i] * 256 + c];
        float acc = (a0 + a1) + (a2 + a3);
        float pre = acc * g_inv[r] + bias + g_yr[(size_t)r * 256 + c];
        g_m[(size_t)r * 256 + c] = pre;
        s += pre; s2 += pre * pre;
    }
    atomicAdd(&g_sum[c], (double)s);
    atomicAdd(&g_sumsq[c], (double)s2);
}

// finalize + self-reset stats for the next layer
__global__ void finalize_bn(const float* __restrict__ gm, const float* __restrict__ bt) {
    int c = threadIdx.x;
    double mean = g_sum[c] / (double)NN;
    double var  = g_sumsq[c] / (double)NN - mean * mean;
    float rstd  = rsqrtf((float)var + 1e-5f);
    float sc    = rstd * gm[c];
    g_scale[c]  = sc;
    g_shift[c]  = bt[c] - (float)mean * sc;
    g_sum[c] = 0.0; g_sumsq[c] = 0.0;
}

// bnrelu: writes bf16 hi/lo split (next GEMM input; hi+lo reconstructs fp32)
__global__ void bnrelu() {
    size_t i = (size_t)blockIdx.x * blockDim.x + threadIdx.x;
    if (i >= (size_t)NN * 64) return;
    size_t idx = i * 4;
    int c = (int)(idx & 255);
    float4 v = *(const float4*)(g_m + idx);
    v.x = fmaxf(v.x * g_scale[c + 0] + g_shift[c + 0], 0.f);
    v.y = fmaxf(v.y * g_scale[c + 1] + g_shift[c + 1], 0.f);
    v.z = fmaxf(v.z * g_scale[c + 2] + g_shift[c + 2], 0.f);
    v.w = fmaxf(v.w * g_scale[c + 3] + g_shift[c + 3], 0.f);
    __nv_bfloat162 h01, l01, h23, l23;
    split1(v.x, h01.x, l01.x);
    split1(v.y, h01.y, l01.y);
    split1(v.z, h23.x, l23.x);
    split1(v.w, h23.y, l23.y);
    uint2 uh, ul;
    uh.x = *(uint32_t*)&h01; uh.y = *(uint32_t*)&h23;
    ul.x = *(uint32_t*)&l01; ul.y = *(uint32_t*)&l23;
    *(uint2*)(g_ah + idx) = uh;
    *(uint2*)(g_al + idx) = ul;
}

// ---------------- tanh-dot ----------------
__global__ __launch_bounds__(256) void tanhdot(const float* __restrict__ ba1,
                                               const float* __restrict__ Wa2,
                                               const float* __restrict__ ba2) {
    __shared__ float red[2][4];
    int tid = threadIdx.x, sub = tid >> 7, j = tid & 127;
    int n = blockIdx.x * 2 + sub;
    float t = 0.f;
    if (n < NN)
        t = tanhf(g_yl[(size_t)n * 256 + j] + ba1[j]) * Wa2[j];
#pragma unroll
    for (int o = 16; o; o >>= 1) t += __shfl_down_sync(0xffffffffu, t, o);
    if ((j & 31) == 0) red[sub][j >> 5] = t;
    __syncthreads();
    if (j == 0 && n < NN)
        g_s[n] = red[sub][0] + red[sub][1] + red[sub][2] + red[sub][3] + ba2[0];
}

// ---------------- fused per-graph softmax: one block per graph ----------------
// batch is sorted: graph g occupies contiguous [s, e). Three passes in-block.
__global__ __launch_bounds__(256) void softmax_fused() {
    int g = blockIdx.x, tid = threadIdx.x;
    // binary search graph range
    int a = 0, b = NN;
    while (a < b) { int m = (a + b) >> 1; if (g_batch[m] < g) a = m + 1; else b = m; }
    int s = a;
    a = 0; b = NN;
    while (a < b) { int m = (a + b) >> 1; if (g_batch[m] < g + 1) a = m + 1; else b = m; }
    int e = a;
    if (s >= e) return;

    __shared__ float red[8];
    __shared__ float s_mx, s_sum;

    // pass 1: max
    float mx = -3.4e38f;
    for (int n = s + tid; n < e; n += 256) mx = fmaxf(mx, g_s[n]);
#pragma unroll
    for (int o = 16; o; o >>= 1) mx = fmaxf(mx, __shfl_down_sync(0xffffffffu, mx, o));
    if ((tid & 31) == 0) red[tid >> 5] = mx;
    __syncthreads();
    if (tid == 0) {
        float m2 = red[0];
#pragma unroll
        for (int w = 1; w < 8; w++) m2 = fmaxf(m2, red[w]);
        s_mx = m2;
    }
    __syncthreads();
    float gmx = s_mx;

    // pass 2: exp + sum
    float sum = 0.f;
    for (int n = s + tid; n < e; n += 256) {
        float ev = expf(g_s[n] - gmx);
        g_w[n] = ev;
        sum += ev;
    }
#pragma unroll
    for (int o = 16; o; o >>= 1) sum += __shfl_down_sync(0xffffffffu, sum, o);
    if ((tid & 31) == 0) red[tid >> 5] = sum;
    __syncthreads();
    if (tid == 0) {
        float t = 0.f;
#pragma unroll
        for (int w = 0; w < 8; w++) t += red[w];
        s_sum = t;
    }
    __syncthreads();

    // pass 3: normalize
    float inv = 1.f / s_sum;
    for (int n = s + tid; n < e; n += 256) g_w[n] *= inv;
}

// ---------------- weighted pooling (h reconstructed from bf16 hi+lo) ----------------
__global__ void pooled_kernel() {
    int c  = threadIdx.x;
    int r0 = blockIdx.x * 512;
    if (r0 >= NN) return;
    int r1  = min(r0 + 512, NN);
    int cur = g_batch[r0];
    float acc = 0.f;
    for (int r = r0; r < r1; r++) {
        int g = g_batch[r];
        if (g != cur) { atomicAdd(&g_pooled[cur * 256 + c], acc); acc = 0.f; cur = g; }
        float h = __bfloat162float(g_ah[(size_t)r * 256 + c]) +
                  __bfloat162float(g_al[(size_t)r * 256 + c]);
        acc += h * g_w[r];
    }
    atomicAdd(&g_pooled[cur * 256 + c], acc);
}

// ---------------- classifier ----------------
__global__ void classifier_kernel(const float* __restrict__ Wc1, const float* __restrict__ bc1,
                                  const float* __restrict__ Wc2, const float* __restrict__ bc2,
                                  float* __restrict__ out) {
    int g = blockIdx.x;
    int j = threadIdx.x;
    float acc = bc1[j];
    for (int k = 0; k < 256; k++) acc += g_pooled[g * 256 + k] * Wc1[k * 128 + j];
    float t = fmaxf(acc, 0.f) * Wc2[j];
#pragma unroll
    for (int o = 16; o; o >>= 1) t += __shfl_down_sync(0xffffffffu, t, o);
    __shared__ float red[4];
    if ((j & 31) == 0) red[j >> 5] = t;
    __syncthreads();
    if (j == 0) out[g] = red[0] + red[1] + red[2] + red[3] + bc2[0];
}

// ---------------- launch ----------------
extern "C" void kernel_launch(void* const* d_in, const int* in_sizes, int n_in,
                              void* d_out, int out_size) {
    const float* x     = (const float*)d_in[0];
    const void*  ei    = d_in[1];
    const void*  batch = d_in[2];
    const float* Wl[3] = {(const float*)d_in[3], (const float*)d_in[8],  (const float*)d_in[13]};
    const float* bl[3] = {(const float*)d_in[4], (const float*)d_in[9],  (const float*)d_in[14]};
    const float* Wr[3] = {(const float*)d_in[5], (const float*)d_in[10], (const float*)d_in[15]};
    const float* gg[3] = {(const float*)d_in[6], (const float*)d_in[11], (const float*)d_in[16]};
    const float* bb[3] = {(const float*)d_in[7], (const float*)d_in[12], (const float*)d_in[17]};
    const float* Wa1 = (const float*)d_in[18];
    const float* ba1 = (const float*)d_in[19];
    const float* Wa2 = (const float*)d_in[20];
    const float* ba2 = (const float*)d_in[21];
    const float* Wc1 = (const float*)d_in[22];
    const float* bc1 = (const float*)d_in[23];
    const float* Wc2 = (const float*)d_in[24];
    const float* bc2 = (const float*)d_in[25];
    float* out = (float*)d_out;

    // launches 1-4: layer-0 GEMM path first (4th launch = gemm_tc -> ncu capture slot)
    detect_dtype<<<1, 32>>>((const unsigned long long*)ei);
    split_a<<<(NN * (KP0 / 2) + 255) / 256, 256>>>(x);
    pack_wbT<<<(512 * (KP0 / 2) + 255) / 256, 256>>>(Wl[0], Wr[0], IND, KP0);
    {
        dim3 ggrid(4, (NN + 127) / 128);
        gemm_tc<<<ggrid, 256>>>(KP0);
    }

    // graph preprocessing (cvt_batch_zero zeroes g_cnt -> must precede cvt_edges)
    cvt_batch_zero<<<(NN + 255) / 256, 256>>>(batch);
    cvt_edges<<<(NE + 255) / 256, 256>>>(ei);
    scan1<<<NBLK, 256>>>();
    scan2<<<1, 512>>>();
    scan3<<<(NN + 255) / 256, 256>>>();
    place_kernel<<<(NE + 255) / 256, 256>>>();
    zero_stats<<<1, 256>>>();   // once; finalize_bn self-resets thereafter

    for (int L = 0; L < 3; L++) {
        if (L > 0) {
            pack_wbT<<<(512 * (HID / 2) + 255) / 256, 256>>>(Wl[L], Wr[L], HID, HID);
            dim3 ggrid(4, (NN + 127) / 128);
            gemm_tc<<<ggrid, 256>>>(HID);
        }
        agg_combine<<<(NN + 31) / 32, 256>>>(bl[L]);
        finalize_bn<<<1, 256>>>(gg[L], bb[L]);
        bnrelu<<<(NN * 64 + 255) / 256, 256>>>();
    }

    // attention score: S = h @ Wa1 via tensor GEMM (N=128 -> g_yl), then tanh-dot
    pack_wa<<<(128 * 128 + 255) / 256, 256>>>(Wa1);
    {
        dim3 sgrid(1, (NN + 127) / 128);
        gemm_tc<<<sgrid, 256>>>(HID);
    }
    tanhdot<<<(NN + 1) / 2, 256>>>(ba1, Wa2, ba2);

    init_pool<<<(NG * HID + 255) / 256, 256>>>();
    softmax_fused<<<NG, 256>>>();
    pooled_kernel<<<(NN + 511) / 512, 256>>>();
    classifier_kernel<<<NG, 128>>>(Wc1, bc1, Wc2, bc2, out);
}

// round 15
// speedup vs baseline: 1.1451x; 1.0293x over previous
#include <cuda_runtime.h>
#include <cuda_bf16.h>
#include <math.h>
#include <stdint.h>

#define NN 100000
#define NE 400000
#define IND 771
#define HID 256
#define NG 64
#define KP0 784            // padded K for layer 0 (49 chunks of 16)
#define NBLK 391           // ceil(NN/256)

// ---------------- scratch (static device globals; no allocation) ----------------
__device__ float  g_yl[(size_t)NN * 256];    // lin_l pre-agg
__device__ float  g_yr[(size_t)NN * 256];    // lin_r part
__device__ float  g_m[(size_t)NN * 256];     // pre-BN
__device__ float  g_inv[NN];
__device__ double g_sum[256];
__device__ double g_sumsq[256];
__device__ float  g_scale[256];
__device__ float  g_shift[256];
__device__ float  g_s[NN];
__device__ float  g_w[NN];
__device__ float  g_pooled[NG * HID];
__device__ int    g_is64;
__device__ int    g_src[NE];
__device__ int    g_dst[NE];
__device__ int    g_batch[NN];
// CSR by dst
__device__ int    g_cnt[NN];
__device__ int    g_off[NN];
__device__ int    g_cur[NN];
__device__ int    g_csr[NE];
__device__ int    g_bsum[NBLK];
__device__ int    g_boff[NBLK];
// bf16 split operands
__device__ __nv_bfloat16 g_ah[(size_t)NN * KP0];
__device__ __nv_bfloat16 g_al[(size_t)NN * KP0];
__device__ __nv_bfloat16 g_bh[512 * KP0];
__device__ __nv_bfloat16 g_bl[512 * KP0];

// ---------------- helpers ----------------
__device__ __forceinline__ uint32_t smem_u32(const void* p) {
    uint32_t a;
    asm("{ .reg .u64 t; cvta.to.shared.u64 t, %1; cvt.u32.u64 %0, t; }" : "=r"(a) : "l"(p));
    return a;
}
#define SWZ16(b) ((b) ^ ((((b) >> 7) & 1) << 4))

__device__ __forceinline__ void cpasync16(uint32_t dst, const void* src, bool pred) {
    int sz = pred ? 16 : 0;
    asm volatile("cp.async.cg.shared.global [%0], [%1], 16, %2;"
                 :: "r"(dst), "l"(src), "r"(sz) : "memory");
}
__device__ __forceinline__ void cp_commit() {
    asm volatile("cp.async.commit_group;" ::: "memory");
}
__device__ __forceinline__ void cp_wait1() {
    asm volatile("cp.async.wait_group 1;" ::: "memory");
}
__device__ __forceinline__ void ldsm4(uint32_t* r, uint32_t addr) {
    asm volatile("ldmatrix.sync.aligned.m8n8.x4.shared.b16 {%0,%1,%2,%3}, [%4];"
                 : "=r"(r[0]), "=r"(r[1]), "=r"(r[2]), "=r"(r[3]) : "r"(addr));
}
__device__ __forceinline__ void mma_bf16(float* c, const uint32_t* a, uint32_t b0, uint32_t b1) {
    asm volatile(
        "mma.sync.aligned.m16n8k16.row.col.f32.bf16.bf16.f32 "
        "{%0,%1,%2,%3}, {%4,%5,%6,%7}, {%8,%9}, {%0,%1,%2,%3};"
        : "+f"(c[0]), "+f"(c[1]), "+f"(c[2]), "+f"(c[3])
        : "r"(a[0]), "r"(a[1]), "r"(a[2]), "r"(a[3]), "r"(b0), "r"(b1));
}
__device__ __forceinline__ void split1(float v, __nv_bfloat16& h, __nv_bfloat16& l) {
    h = __float2bfloat16(v);
    l = __float2bfloat16(v - __bfloat162float(h));
}

// ---------------- dtype detection + index normalization ----------------
__global__ void detect_dtype(const unsigned long long* __restrict__ ei) {
    if (threadIdx.x == 0 && blockIdx.x == 0) {
        int is64 = 1;
        for (int i = 0; i < 64; i++)
            if (ei[i] >= (unsigned long long)NN) { is64 = 0; break; }
        g_is64 = is64;
    }
}
// zeroes g_cnt too -> must run BEFORE cvt_edges (which counts)
__global__ void cvt_batch_zero(const void* __restrict__ b) {
    int n = blockIdx.x * blockDim.x + threadIdx.x;
    if (n >= NN) return;
    if (g_is64) g_batch[n] = (int)((const long long*)b)[n];
    else        g_batch[n] = ((const int*)b)[n];
    g_cnt[n] = 0;
}
// convert edges + count degrees in one pass
__global__ void cvt_edges(const void* __restrict__ ei) {
    int e = blockIdx.x * blockDim.x + threadIdx.x;
    if (e >= NE) return;
    int s, d;
    if (g_is64) {
        const long long* p = (const long long*)ei;
        s = (int)p[e];
        d = (int)p[NE + e];
    } else {
        const int* p = (const int*)ei;
        s = p[e];
        d = p[NE + e];
    }
    g_src[e] = s;
    g_dst[e] = d;
    atomicAdd(&g_cnt[d], 1);
}

// ---------------- CSR build ----------------
__global__ void scan1() {
    __shared__ int sm[256];
    int b = blockIdx.x, t = threadIdx.x;
    int i = b * 256 + t;
    int v = (i < NN) ? g_cnt[i] : 0;
    sm[t] = v; __syncthreads();
    for (int o = 1; o < 256; o <<= 1) {
        int u = (t >= o) ? sm[t - o] : 0;
        __syncthreads();
        sm[t] += u;
        __syncthreads();
    }
    if (i < NN) g_off[i] = sm[t] - v;
    if (t == 255) g_bsum[b] = sm[255];
}
__global__ void scan2() {
    __shared__ int sm[512];
    int t = threadIdx.x;
    int v = (t < NBLK) ? g_bsum[t] : 0;
    sm[t] = v; __syncthreads();
    for (int o = 1; o < 512; o <<= 1) {
        int u = (t >= o) ? sm[t - o] : 0;
        __syncthreads();
        sm[t] += u;
        __syncthreads();
    }
    if (t < NBLK) g_boff[t] = sm[t] - v;
}
__global__ void scan3() {
    int i = blockIdx.x * blockDim.x + threadIdx.x;
    if (i < NN) {
        int o = g_off[i] + g_boff[i >> 8];
        g_off[i] = o;
        g_cur[i] = o;
        g_inv[i] = 1.f / fmaxf((float)g_cnt[i], 1.f);
    }
}
__global__ void place_kernel() {
    int e = blockIdx.x * blockDim.x + threadIdx.x;
    if (e < NE) {
        int pos = atomicAdd(&g_cur[g_dst[e]], 1);
        g_csr[pos] = g_src[e];
    }
}

// ---------------- zero / init ----------------
__global__ void zero_stats() {
    int c = threadIdx.x;
    g_sum[c] = 0.0; g_sumsq[c] = 0.0;
}
__global__ void init_pool() {
    int i = blockIdx.x * blockDim.x + threadIdx.x;
    if (i < NG * HID) g_pooled[i] = 0.f;
}

// ---------------- split x (layer 0 only) ----------------
__global__ void split_a(const float* __restrict__ A) {
    int kp2 = KP0 >> 1;
    int i = blockIdx.x * blockDim.x + threadIdx.x;
    if (i >= NN * kp2) return;
    int n = i / kp2, k2 = (i - n * kp2) * 2;
    float v0 = (k2 < IND)     ? A[(size_t)n * IND + k2]     : 0.f;
    float v1 = (k2 + 1 < IND) ? A[(size_t)n * IND + k2 + 1] : 0.f;
    __nv_bfloat162 hp, lp;
    split1(v0, hp.x, lp.x);
    split1(v1, hp.y, lp.y);
    *(__nv_bfloat162*)(g_ah + (size_t)n * KP0 + k2) = hp;
    *(__nv_bfloat162*)(g_al + (size_t)n * KP0 + k2) = lp;
}

// ---------------- pack [Wl|Wr]^T ----------------
__global__ void pack_wbT(const float* __restrict__ Wl, const float* __restrict__ Wr,
                         int K, int KP) {
    int kp2 = KP >> 1;
    int i = blockIdx.x * blockDim.x + threadIdx.x;
    if (i >= 512 * kp2) return;
    int n = i / kp2, k2 = (i - n * kp2) * 2;
    const float* W = (n < 256) ? Wl : Wr;
    int c = (n < 256) ? n : n - 256;
    float v0 = (k2 < K)     ? W[(size_t)k2 * 256 + c]       : 0.f;
    float v1 = (k2 + 1 < K) ? W[(size_t)(k2 + 1) * 256 + c] : 0.f;
    __nv_bfloat162 hp, lp;
    split1(v0, hp.x, lp.x);
    split1(v1, hp.y, lp.y);
    *(__nv_bfloat162*)(g_bh + (size_t)n * KP + k2) = hp;
    *(__nv_bfloat162*)(g_bl + (size_t)n * KP + k2) = lp;
}

// ---------------- pack Wa1^T (score GEMM B) ----------------
__global__ void pack_wa(const float* __restrict__ Wa1) {
    int i = blockIdx.x * blockDim.x + threadIdx.x;
    if (i >= 128 * 128) return;
    int n = i >> 7, k2 = (i & 127) * 2;
    float v0 = Wa1[(size_t)k2 * 128 + n];
    float v1 = Wa1[(size_t)(k2 + 1) * 128 + n];
    __nv_bfloat162 hp, lp;
    split1(v0, hp.x, lp.x);
    split1(v1, hp.y, lp.y);
    *(__nv_bfloat162*)(g_bh + (size_t)n * 256 + k2) = hp;
    *(__nv_bfloat162*)(g_bl + (size_t)n * 256 + k2) = lp;
}

// ---------------- split-bf16 GEMM: M128 x N128, 8 warps, k16 chunks ----------------
// 3-stage cp.async pipeline (48KB), ONE __syncthreads per chunk, prefetch distance 2.
// iter ch: wait_group 1 -> __syncthreads -> STAGE((ch+2)%3) -> ldsm(ch) -> MMA(ch).
// SCORE=1: epilogue computes g_s[row] = ba2 + sum_j tanh(acc[j]+ba1[j])*Wa2[j]
// (separate instantiation: zero impact on the SCORE=0 binary).
template <int SCORE>
__global__ void __launch_bounds__(256, 2) gemm_tc(int KP,
                                                  const float* __restrict__ ba1,
                                                  const float* __restrict__ Wa2,
                                                  const float* __restrict__ ba2) {
    __shared__ __align__(128) char sm_[49152];   // 3 x 16KB
    const uint32_t sb = smem_u32(sm_);
    int tid = threadIdx.x, lane = tid & 31, wid = tid >> 5;
    int wm = wid >> 2, wn = wid & 3;         // 2 x 4 warps, warp tile 64x32
    int row0 = blockIdx.y * 128;
    int col0 = blockIdx.x * 128;
    int nch = KP >> 4;

    int r = tid >> 1, s16 = (tid & 1) * 16;
    bool predA = (row0 + r) < NN;
    const char* pAh = (const char*)g_ah + ((size_t)(row0 + r) * KP) * 2 + s16;
    const char* pAl = (const char*)g_al + ((size_t)(row0 + r) * KP) * 2 + s16;
    const char* pBh = (const char*)g_bh + ((size_t)(col0 + r) * KP) * 2 + s16;
    const char* pBl = (const char*)g_bl + ((size_t)(col0 + r) * KP) * 2 + s16;
    if (!predA) { pAh = (const char*)g_ah + s16; pAl = (const char*)g_al + s16; }
    const uint32_t soff = SWZ16((uint32_t)(r * 32 + s16));

#define STAGE(BUF)                                                   \
    do {                                                             \
        uint32_t stg = sb + (uint32_t)(BUF) * 16384 + soff;          \
        cpasync16(stg,         pAh, predA);                          \
        cpasync16(stg + 4096,  pAl, predA);                          \
        cpasync16(stg + 8192,  pBh, true);                           \
        cpasync16(stg + 12288, pBl, true);                           \
        cp_commit();                                                 \
        pAh += 32; pAl += 32; pBh += 32; pBl += 32;                  \
    } while (0)

    float acc[4][4][4];
#pragma unroll
    for (int a = 0; a < 4; a++)
#pragma unroll
        for (int b = 0; b < 4; b++)
#pragma unroll
            for (int c = 0; c < 4; c++) acc[a][b][c] = 0.f;

    STAGE(0);
    STAGE(1);

    int q = lane >> 3, lr = lane & 7;
    const uint32_t aoff0 = (uint32_t)((wm * 64 + (q & 1) * 8 + lr) * 32 + (q >> 1) * 16);
    const uint32_t boff0 = (uint32_t)((wn * 32 + (q >> 1) * 8 + lr) * 32 + (q & 1) * 16);

    int bufS = 2, bufC = 0;
    for (int ch = 0; ch < nch; ch++) {
        cp_wait1();            // oldest pending (group ch) complete
        __syncthreads();       // visibility + seals iter ch-1 reads

        if (ch + 2 < nch) {
            STAGE(bufS);       // writes buf((ch-1)%3): readers sealed
        } else {
            cp_commit();
        }
        bufS = (bufS == 2) ? 0 : bufS + 1;

        uint32_t stg = sb + (uint32_t)bufC * 16384;
        bufC = (bufC == 2) ? 0 : bufC + 1;

        uint32_t Ah[4][4], Al[4][4], Bh[2][4], Bl[2][4];
#pragma unroll
        for (int mi = 0; mi < 4; mi++) {
            uint32_t a = stg + SWZ16(aoff0 + (uint32_t)(mi * 16 * 32));
            ldsm4(Ah[mi], a);
            ldsm4(Al[mi], a + 4096);
        }
#pragma unroll
        for (int p = 0; p < 2; p++) {
            uint32_t a = stg + 8192 + SWZ16(boff0 + (uint32_t)(p * 16 * 32));
            ldsm4(Bh[p], a);
            ldsm4(Bl[p], a + 4096);
        }
#pragma unroll
        for (int mi = 0; mi < 4; mi++)
#pragma unroll
            for (int ni = 0; ni < 4; ni++) {
                uint32_t bh0 = Bh[ni >> 1][(ni & 1) * 2], bh1 = Bh[ni >> 1][(ni & 1) * 2 + 1];
                uint32_t bl0 = Bl[ni >> 1][(ni & 1) * 2], bl1 = Bl[ni >> 1][(ni & 1) * 2 + 1];
                mma_bf16(acc[mi][ni], Ah[mi], bh0, bh1);
                mma_bf16(acc[mi][ni], Al[mi], bh0, bh1);
                mma_bf16(acc[mi][ni], Ah[mi], bl0, bl1);
            }
    }
#undef STAGE

    int tr = lane >> 2, tc = lane & 3;
    if (SCORE) {
        // fused tanh-dot epilogue (col0 == 0, cols 0..127)
        __syncthreads();                       // all cp.async groups drained; smem reusable
        float* red = (float*)sm_;
        if (tid < 128) red[tid] = 0.f;
        __syncthreads();
#pragma unroll
        for (int mi = 0; mi < 4; mi++)
#pragma unroll
            for (int half = 0; half < 2; half++) {
                float t = 0.f;
#pragma unroll
                for (int ni = 0; ni < 4; ni++) {
                    int col = wn * 32 + tc * 2 + ni * 8;
                    t += tanhf(acc[mi][ni][half * 2]     + ba1[col])     * Wa2[col];
                    t += tanhf(acc[mi][ni][half * 2 + 1] + ba1[col + 1]) * Wa2[col + 1];
                }
                t += __shfl_xor_sync(0xffffffffu, t, 1);
                t += __shfl_xor_sync(0xffffffffu, t, 2);
                if (tc == 0)
                    atomicAdd(&red[wm * 64 + mi * 16 + tr + half * 8], t);
            }
        __syncthreads();
        if (tid < 128) {
            int row = row0 + tid;
            if (row < NN) g_s[row] = red[tid] + ba2[0];
        }
        return;
    }

    float* dstbase = (col0 < 256) ? g_yl : g_yr;
    int cb = col0 & 255;
#pragma unroll
    for (int mi = 0; mi < 4; mi++)
#pragma unroll
        for (int half = 0; half < 2; half++) {
            int row = row0 + wm * 64 + mi * 16 + tr + half * 8;
            if (row < NN) {
                float* p = dstbase + (size_t)row * 256 + cb + wn * 32 + tc * 2;
#pragma unroll
                for (int ni = 0; ni < 4; ni++) {
                    float2 v = make_float2(acc[mi][ni][half * 2], acc[mi][ni][half * 2 + 1]);
                    *(float2*)(p + ni * 8) = v;
                }
            }
        }
}

// ---------------- CSR aggregation + combine + BN stats (unroll-4 MLP) ----------------
__global__ __launch_bounds__(256) void agg_combine(const float* __restrict__ bl) {
    int c  = threadIdx.x;
    int r0 = blockIdx.x * 32;
    if (r0 >= NN) return;
    int r1 = min(r0 + 32, NN);
    float bias = bl[c];
    float s = 0.f, s2 = 0.f;
    for (int r = r0; r < r1; r++) {
        int beg = g_off[r];
        int end = (r == NN - 1) ? NE : g_off[r + 1];
        float a0 = 0.f, a1 = 0.f, a2 = 0.f, a3 = 0.f;
        int i = beg;
        for (; i + 4 <= end; i += 4) {
            int s0 = g_csr[i], s1 = g_csr[i + 1], s2i = g_csr[i + 2], s3 = g_csr[i + 3];
            float v0 = g_yl[(size_t)s0 * 256 + c];
            float v1 = g_yl[(size_t)s1 * 256 + c];
            float v2 = g_yl[(size_t)s2i * 256 + c];
            float v3 = g_yl[(size_t)s3 * 256 + c];
            a0 += v0; a1 += v1; a2 += v2; a3 += v3;
        }
        for (; i < end; i++) a0 += g_yl[(size_t)g_csr[i] * 256 + c];
        float acc = (a0 + a1) + (a2 + a3);
        float pre = acc * g_inv[r] + bias + g_yr[(size_t)r * 256 + c];
        g_m[(size_t)r * 256 + c] = pre;
        s += pre; s2 += pre * pre;
    }
    atomicAdd(&g_sum[c], (double)s);
    atomicAdd(&g_sumsq[c], (double)s2);
}

// finalize + self-reset stats for the next layer
__global__ void finalize_bn(const float* __restrict__ gm, const float* __restrict__ bt) {
    int c = threadIdx.x;
    double mean = g_sum[c] / (double)NN;
    double var  = g_sumsq[c] / (double)NN - mean * mean;
    float rstd  = rsqrtf((float)var + 1e-5f);
    float sc    = rstd * gm[c];
    g_scale[c]  = sc;
    g_shift[c]  = bt[c] - (float)mean * sc;
    g_sum[c] = 0.0; g_sumsq[c] = 0.0;
}

// bnrelu: writes bf16 hi/lo split (next GEMM input; hi+lo reconstructs fp32)
__global__ void bnrelu() {
    size_t i = (size_t)blockIdx.x * blockDim.x + threadIdx.x;
    if (i >= (size_t)NN * 64) return;
    size_t idx = i * 4;
    int c = (int)(idx & 255);
    float4 v = *(const float4*)(g_m + idx);
    v.x = fmaxf(v.x * g_scale[c + 0] + g_shift[c + 0], 0.f);
    v.y = fmaxf(v.y * g_scale[c + 1] + g_shift[c + 1], 0.f);
    v.z = fmaxf(v.z * g_scale[c + 2] + g_shift[c + 2], 0.f);
    v.w = fmaxf(v.w * g_scale[c + 3] + g_shift[c + 3], 0.f);
    __nv_bfloat162 h01, l01, h23, l23;
    split1(v.x, h01.x, l01.x);
    split1(v.y, h01.y, l01.y);
    split1(v.z, h23.x, l23.x);
    split1(v.w, h23.y, l23.y);
    uint2 uh, ul;
    uh.x = *(uint32_t*)&h01; uh.y = *(uint32_t*)&h23;
    ul.x = *(uint32_t*)&l01; ul.y = *(uint32_t*)&l23;
    *(uint2*)(g_ah + idx) = uh;
    *(uint2*)(g_al + idx) = ul;
}

// ---------------- fused per-graph softmax: one block per graph ----------------
__global__ __launch_bounds__(256) void softmax_fused() {
    int g = blockIdx.x, tid = threadIdx.x;
    int a = 0, b = NN;
    while (a < b) { int m = (a + b) >> 1; if (g_batch[m] < g) a = m + 1; else b = m; }
    int s = a;
    a = 0; b = NN;
    while (a < b) { int m = (a + b) >> 1; if (g_batch[m] < g + 1) a = m + 1; else b = m; }
    int e = a;
    if (s >= e) return;

    __shared__ float red[8];
    __shared__ float s_mx, s_sum;

    float mx = -3.4e38f;
    for (int n = s + tid; n < e; n += 256) mx = fmaxf(mx, g_s[n]);
#pragma unroll
    for (int o = 16; o; o >>= 1) mx = fmaxf(mx, __shfl_down_sync(0xffffffffu, mx, o));
    if ((tid & 31) == 0) red[tid >> 5] = mx;
    __syncthreads();
    if (tid == 0) {
        float m2 = red[0];
#pragma unroll
        for (int w = 1; w < 8; w++) m2 = fmaxf(m2, red[w]);
        s_mx = m2;
    }
    __syncthreads();
    float gmx = s_mx;

    float sum = 0.f;
    for (int n = s + tid; n < e; n += 256) {
        float ev = expf(g_s[n] - gmx);
        g_w[n] = ev;
        sum += ev;
    }
#pragma unroll
    for (int o = 16; o; o >>= 1) sum += __shfl_down_sync(0xffffffffu, sum, o);
    if ((tid & 31) == 0) red[tid >> 5] = sum;
    __syncthreads();
    if (tid == 0) {
        float t = 0.f;
#pragma unroll
        for (int w = 0; w < 8; w++) t += red[w];
        s_sum = t;
    }
    __syncthreads();

    float inv = 1.f / s_sum;
    for (int n = s + tid; n < e; n += 256) g_w[n] *= inv;
}

// ---------------- weighted pooling (h reconstructed from bf16 hi+lo) ----------------
__global__ void pooled_kernel() {
    int c  = threadIdx.x;
    int r0 = blockIdx.x * 512;
    if (r0 >= NN) return;
    int r1  = min(r0 + 512, NN);
    int cur = g_batch[r0];
    float acc = 0.f;
    for (int r = r0; r < r1; r++) {
        int g = g_batch[r];
        if (g != cur) { atomicAdd(&g_pooled[cur * 256 + c], acc); acc = 0.f; cur = g; }
        float h = __bfloat162float(g_ah[(size_t)r * 256 + c]) +
                  __bfloat162float(g_al[(size_t)r * 256 + c]);
        acc += h * g_w[r];
    }
    atomicAdd(&g_pooled[cur * 256 + c], acc);
}

// ---------------- classifier ----------------
__global__ void classifier_kernel(const float* __restrict__ Wc1, const float* __restrict__ bc1,
                                  const float* __restrict__ Wc2, const float* __restrict__ bc2,
                                  float* __restrict__ out) {
    int g = blockIdx.x;
    int j = threadIdx.x;
    float acc = bc1[j];
    for (int k = 0; k < 256; k++) acc += g_pooled[g * 256 + k] * Wc1[k * 128 + j];
    float t = fmaxf(acc, 0.f) * Wc2[j];
#pragma unroll
    for (int o = 16; o; o >>= 1) t += __shfl_down_sync(0xffffffffu, t, o);
    __shared__ float red[4];
    if ((j & 31) == 0) red[j >> 5] = t;
    __syncthreads();
    if (j == 0) out[g] = red[0] + red[1] + red[2] + red[3] + bc2[0];
}

// ---------------- launch ----------------
extern "C" void kernel_launch(void* const* d_in, const int* in_sizes, int n_in,
                              void* d_out, int out_size) {
    const float* x     = (const float*)d_in[0];
    const void*  ei    = d_in[1];
    const void*  batch = d_in[2];
    const float* Wl[3] = {(const float*)d_in[3], (const float*)d_in[8],  (const float*)d_in[13]};
    const float* bl[3] = {(const float*)d_in[4], (const float*)d_in[9],  (const float*)d_in[14]};
    const float* Wr[3] = {(const float*)d_in[5], (const float*)d_in[10], (const float*)d_in[15]};
    const float* gg[3] = {(const float*)d_in[6], (const float*)d_in[11], (const float*)d_in[16]};
    const float* bb[3] = {(const float*)d_in[7], (const float*)d_in[12], (const float*)d_in[17]};
    const float* Wa1 = (const float*)d_in[18];
    const float* ba1 = (const float*)d_in[19];
    const float* Wa2 = (const float*)d_in[20];
    const float* ba2 = (const float*)d_in[21];
    const float* Wc1 = (const float*)d_in[22];
    const float* bc1 = (const float*)d_in[23];
    const float* Wc2 = (const float*)d_in[24];
    const float* bc2 = (const float*)d_in[25];
    float* out = (float*)d_out;

    // launches 1-4: layer-0 GEMM path first (4th launch = gemm_tc -> ncu capture slot)
    detect_dtype<<<1, 32>>>((const unsigned long long*)ei);
    split_a<<<(NN * (KP0 / 2) + 255) / 256, 256>>>(x);
    pack_wbT<<<(512 * (KP0 / 2) + 255) / 256, 256>>>(Wl[0], Wr[0], IND, KP0);
    {
        dim3 ggrid(4, (NN + 127) / 128);
        gemm_tc<0><<<ggrid, 256>>>(KP0, nullptr, nullptr, nullptr);
    }

    // graph preprocessing (cvt_batch_zero zeroes g_cnt -> must precede cvt_edges)
    cvt_batch_zero<<<(NN + 255) / 256, 256>>>(batch);
    cvt_edges<<<(NE + 255) / 256, 256>>>(ei);
    scan1<<<NBLK, 256>>>();
    scan2<<<1, 512>>>();
    scan3<<<(NN + 255) / 256, 256>>>();
    place_kernel<<<(NE + 255) / 256, 256>>>();
    zero_stats<<<1, 256>>>();   // once; finalize_bn self-resets thereafter

    for (int L = 0; L < 3; L++) {
        if (L > 0) {
            pack_wbT<<<(512 * (HID / 2) + 255) / 256, 256>>>(Wl[L], Wr[L], HID, HID);
            dim3 ggrid(4, (NN + 127) / 128);
            gemm_tc<0><<<ggrid, 256>>>(HID, nullptr, nullptr, nullptr);
        }
        agg_combine<<<(NN + 31) / 32, 256>>>(bl[L]);
        finalize_bn<<<1, 256>>>(gg[L], bb[L]);
        bnrelu<<<(NN * 64 + 255) / 256, 256>>>();
    }

    // attention score: fused S = h @ Wa1 -> tanh-dot epilogue writes g_s directly
    pack_wa<<<(128 * 128 + 255) / 256, 256>>>(Wa1);
    {
        dim3 sgrid(1, (NN + 127) / 128);
        gemm_tc<1><<<sgrid, 256>>>(HID, ba1, Wa2, ba2);
    }

    init_pool<<<(NG * HID + 255) / 256, 256>>>();
    softmax_fused<<<NG, 256>>>();
    pooled_kernel<<<(NN + 511) / 512, 256>>>();
    classifier_kernel<<<NG, 128>>>(Wc1, bc1, Wc2, bc2, out);
}

// round 16
// speedup vs baseline: 1.1554x; 1.0090x over previous
#include <cuda_runtime.h>
#include <cuda_bf16.h>
#include <math.h>
#include <stdint.h>

#define NN 100000
#define NE 400000
#define IND 771
#define HID 256
#define NG 64
#define KP0 784            // padded K for layer 0 (49 chunks of 16)
#define NBLK 391           // ceil(NN/256)

// ---------------- scratch (static device globals; no allocation) ----------------
__device__ float  g_yl[(size_t)NN * 256];    // lin_l pre-agg
__device__ float  g_yr[(size_t)NN * 256];    // lin_r part
__device__ float  g_m[(size_t)NN * 256];     // pre-BN
__device__ float  g_inv[NN];
__device__ float  g_sumf[3 * 256];           // per-layer BN stats (float, RED atomics)
__device__ float  g_sumsqf[3 * 256];
__device__ float  g_s[NN];
__device__ float  g_w[NN];
__device__ float  g_pooled[NG * HID];
__device__ int    g_is64;
__device__ int    g_src[NE];
__device__ int    g_dst[NE];
__device__ int    g_batch[NN];
// CSR by dst
__device__ int    g_cnt[NN];
__device__ int    g_off[NN];
__device__ int    g_cur[NN];
__device__ int    g_csr[NE];
__device__ int    g_bsum[NBLK];
__device__ int    g_boff[NBLK];
// bf16 split operands
__device__ __nv_bfloat16 g_ah[(size_t)NN * KP0];
__device__ __nv_bfloat16 g_al[(size_t)NN * KP0];
__device__ __nv_bfloat16 g_bh[512 * KP0];
__device__ __nv_bfloat16 g_bl[512 * KP0];

// ---------------- helpers ----------------
__device__ __forceinline__ uint32_t smem_u32(const void* p) {
    uint32_t a;
    asm("{ .reg .u64 t; cvta.to.shared.u64 t, %1; cvt.u32.u64 %0, t; }" : "=r"(a) : "l"(p));
    return a;
}
#define SWZ16(b) ((b) ^ ((((b) >> 7) & 1) << 4))

__device__ __forceinline__ void cpasync16(uint32_t dst, const void* src, bool pred) {
    int sz = pred ? 16 : 0;
    asm volatile("cp.async.cg.shared.global [%0], [%1], 16, %2;"
                 :: "r"(dst), "l"(src), "r"(sz) : "memory");
}
__device__ __forceinline__ void cp_commit() {
    asm volatile("cp.async.commit_group;" ::: "memory");
}
__device__ __forceinline__ void cp_wait1() {
    asm volatile("cp.async.wait_group 1;" ::: "memory");
}
__device__ __forceinline__ void ldsm4(uint32_t* r, uint32_t addr) {
    asm volatile("ldmatrix.sync.aligned.m8n8.x4.shared.b16 {%0,%1,%2,%3}, [%4];"
                 : "=r"(r[0]), "=r"(r[1]), "=r"(r[2]), "=r"(r[3]) : "r"(addr));
}
__device__ __forceinline__ void mma_bf16(float* c, const uint32_t* a, uint32_t b0, uint32_t b1) {
    asm volatile(
        "mma.sync.aligned.m16n8k16.row.col.f32.bf16.bf16.f32 "
        "{%0,%1,%2,%3}, {%4,%5,%6,%7}, {%8,%9}, {%0,%1,%2,%3};"
        : "+f"(c[0]), "+f"(c[1]), "+f"(c[2]), "+f"(c[3])
        : "r"(a[0]), "r"(a[1]), "r"(a[2]), "r"(a[3]), "r"(b0), "r"(b1));
}
__device__ __forceinline__ void split1(float v, __nv_bfloat16& h, __nv_bfloat16& l) {
    h = __float2bfloat16(v);
    l = __float2bfloat16(v - __bfloat162float(h));
}

// ---------------- dtype detection + index normalization ----------------
__global__ void detect_dtype(const unsigned long long* __restrict__ ei) {
    if (threadIdx.x == 0 && blockIdx.x == 0) {
        int is64 = 1;
        for (int i = 0; i < 64; i++)
            if (ei[i] >= (unsigned long long)NN) { is64 = 0; break; }
        g_is64 = is64;
    }
}
// zeroes g_cnt too -> must run BEFORE cvt_edges (which counts)
__global__ void cvt_batch_zero(const void* __restrict__ b) {
    int n = blockIdx.x * blockDim.x + threadIdx.x;
    if (n >= NN) return;
    if (g_is64) g_batch[n] = (int)((const long long*)b)[n];
    else        g_batch[n] = ((const int*)b)[n];
    g_cnt[n] = 0;
}
// convert edges + count degrees in one pass
__global__ void cvt_edges(const void* __restrict__ ei) {
    int e = blockIdx.x * blockDim.x + threadIdx.x;
    if (e >= NE) return;
    int s, d;
    if (g_is64) {
        const long long* p = (const long long*)ei;
        s = (int)p[e];
        d = (int)p[NE + e];
    } else {
        const int* p = (const int*)ei;
        s = p[e];
        d = p[NE + e];
    }
    g_src[e] = s;
    g_dst[e] = d;
    atomicAdd(&g_cnt[d], 1);
}

// ---------------- CSR build ----------------
__global__ void scan1() {
    __shared__ int sm[256];
    int b = blockIdx.x, t = threadIdx.x;
    int i = b * 256 + t;
    int v = (i < NN) ? g_cnt[i] : 0;
    sm[t] = v; __syncthreads();
    for (int o = 1; o < 256; o <<= 1) {
        int u = (t >= o) ? sm[t - o] : 0;
        __syncthreads();
        sm[t] += u;
        __syncthreads();
    }
    if (i < NN) g_off[i] = sm[t] - v;
    if (t == 255) g_bsum[b] = sm[255];
}
__global__ void scan2() {
    __shared__ int sm[512];
    int t = threadIdx.x;
    int v = (t < NBLK) ? g_bsum[t] : 0;
    sm[t] = v; __syncthreads();
    for (int o = 1; o < 512; o <<= 1) {
        int u = (t >= o) ? sm[t - o] : 0;
        __syncthreads();
        sm[t] += u;
        __syncthreads();
    }
    if (t < NBLK) g_boff[t] = sm[t] - v;
}
// scan3 also zeroes all 3 layers' BN stats (replaces zero_stats launch)
__global__ void scan3() {
    int i = blockIdx.x * blockDim.x + threadIdx.x;
    if (i < 768) { g_sumf[i] = 0.f; g_sumsqf[i] = 0.f; }
    if (i < NN) {
        int o = g_off[i] + g_boff[i >> 8];
        g_off[i] = o;
        g_cur[i] = o;
        g_inv[i] = 1.f / fmaxf((float)g_cnt[i], 1.f);
    }
}
__global__ void place_kernel() {
    int e = blockIdx.x * blockDim.x + threadIdx.x;
    if (e < NE) {
        int pos = atomicAdd(&g_cur[g_dst[e]], 1);
        g_csr[pos] = g_src[e];
    }
}

// ---------------- split x (layer 0 only) ----------------
__global__ void split_a(const float* __restrict__ A) {
    int kp2 = KP0 >> 1;
    int i = blockIdx.x * blockDim.x + threadIdx.x;
    if (i >= NN * kp2) return;
    int n = i / kp2, k2 = (i - n * kp2) * 2;
    float v0 = (k2 < IND)     ? A[(size_t)n * IND + k2]     : 0.f;
    float v1 = (k2 + 1 < IND) ? A[(size_t)n * IND + k2 + 1] : 0.f;
    __nv_bfloat162 hp, lp;
    split1(v0, hp.x, lp.x);
    split1(v1, hp.y, lp.y);
    *(__nv_bfloat162*)(g_ah + (size_t)n * KP0 + k2) = hp;
    *(__nv_bfloat162*)(g_al + (size_t)n * KP0 + k2) = lp;
}

// ---------------- pack [Wl|Wr]^T ----------------
__global__ void pack_wbT(const float* __restrict__ Wl, const float* __restrict__ Wr,
                         int K, int KP) {
    int kp2 = KP >> 1;
    int i = blockIdx.x * blockDim.x + threadIdx.x;
    if (i >= 512 * kp2) return;
    int n = i / kp2, k2 = (i - n * kp2) * 2;
    const float* W = (n < 256) ? Wl : Wr;
    int c = (n < 256) ? n : n - 256;
    float v0 = (k2 < K)     ? W[(size_t)k2 * 256 + c]       : 0.f;
    float v1 = (k2 + 1 < K) ? W[(size_t)(k2 + 1) * 256 + c] : 0.f;
    __nv_bfloat162 hp, lp;
    split1(v0, hp.x, lp.x);
    split1(v1, hp.y, lp.y);
    *(__nv_bfloat162*)(g_bh + (size_t)n * KP + k2) = hp;
    *(__nv_bfloat162*)(g_bl + (size_t)n * KP + k2) = lp;
}

// ---------------- pack Wa1^T (score GEMM B) ----------------
__global__ void pack_wa(const float* __restrict__ Wa1) {
    int i = blockIdx.x * blockDim.x + threadIdx.x;
    if (i >= 128 * 128) return;
    int n = i >> 7, k2 = (i & 127) * 2;
    float v0 = Wa1[(size_t)k2 * 128 + n];
    float v1 = Wa1[(size_t)(k2 + 1) * 128 + n];
    __nv_bfloat162 hp, lp;
    split1(v0, hp.x, lp.x);
    split1(v1, hp.y, lp.y);
    *(__nv_bfloat162*)(g_bh + (size_t)n * 256 + k2) = hp;
    *(__nv_bfloat162*)(g_bl + (size_t)n * 256 + k2) = lp;
}

// ---------------- split-bf16 GEMM: M128 x N128, 8 warps, k16 chunks ----------------
// 3-stage cp.async pipeline (48KB), ONE __syncthreads per chunk, prefetch distance 2.
// iter ch: wait_group 1 -> __syncthreads -> STAGE((ch+2)%3) -> ldsm(ch) -> MMA(ch).
// SCORE=1: epilogue computes g_s[row] = ba2 + sum_j tanh(acc[j]+ba1[j])*Wa2[j].
template <int SCORE>
__global__ void __launch_bounds__(256, 2) gemm_tc(int KP,
                                                  const float* __restrict__ ba1,
                                                  const float* __restrict__ Wa2,
                                                  const float* __restrict__ ba2) {
    __shared__ __align__(128) char sm_[49152];   // 3 x 16KB
    const uint32_t sb = smem_u32(sm_);
    int tid = threadIdx.x, lane = tid & 31, wid = tid >> 5;
    int wm = wid >> 2, wn = wid & 3;         // 2 x 4 warps, warp tile 64x32
    int row0 = blockIdx.y * 128;
    int col0 = blockIdx.x * 128;
    int nch = KP >> 4;

    int r = tid >> 1, s16 = (tid & 1) * 16;
    bool predA = (row0 + r) < NN;
    const char* pAh = (const char*)g_ah + ((size_t)(row0 + r) * KP) * 2 + s16;
    const char* pAl = (const char*)g_al + ((size_t)(row0 + r) * KP) * 2 + s16;
    const char* pBh = (const char*)g_bh + ((size_t)(col0 + r) * KP) * 2 + s16;
    const char* pBl = (const char*)g_bl + ((size_t)(col0 + r) * KP) * 2 + s16;
    if (!predA) { pAh = (const char*)g_ah + s16; pAl = (const char*)g_al + s16; }
    const uint32_t soff = SWZ16((uint32_t)(r * 32 + s16));

#define STAGE(BUF)                                                   \
    do {                                                             \
        uint32_t stg = sb + (uint32_t)(BUF) * 16384 + soff;          \
        cpasync16(stg,         pAh, predA);                          \
        cpasync16(stg + 4096,  pAl, predA);                          \
        cpasync16(stg + 8192,  pBh, true);                           \
        cpasync16(stg + 12288, pBl, true);                           \
        cp_commit();                                                 \
        pAh += 32; pAl += 32; pBh += 32; pBl += 32;                  \
    } while (0)

    float acc[4][4][4];
#pragma unroll
    for (int a = 0; a < 4; a++)
#pragma unroll
        for (int b = 0; b < 4; b++)
#pragma unroll
            for (int c = 0; c < 4; c++) acc[a][b][c] = 0.f;

    STAGE(0);
    STAGE(1);

    int q = lane >> 3, lr = lane & 7;
    const uint32_t aoff0 = (uint32_t)((wm * 64 + (q & 1) * 8 + lr) * 32 + (q >> 1) * 16);
    const uint32_t boff0 = (uint32_t)((wn * 32 + (q >> 1) * 8 + lr) * 32 + (q & 1) * 16);

    int bufS = 2, bufC = 0;
    for (int ch = 0; ch < nch; ch++) {
        cp_wait1();            // oldest pending (group ch) complete
        __syncthreads();       // visibility + seals iter ch-1 reads

        if (ch + 2 < nch) {
            STAGE(bufS);       // writes buf((ch-1)%3): readers sealed
        } else {
            cp_commit();
        }
        bufS = (bufS == 2) ? 0 : bufS + 1;

        uint32_t stg = sb + (uint32_t)bufC * 16384;
        bufC = (bufC == 2) ? 0 : bufC + 1;

        uint32_t Ah[4][4], Al[4][4], Bh[2][4], Bl[2][4];
#pragma unroll
        for (int mi = 0; mi < 4; mi++) {
            uint32_t a = stg + SWZ16(aoff0 + (uint32_t)(mi * 16 * 32));
            ldsm4(Ah[mi], a);
            ldsm4(Al[mi], a + 4096);
        }
#pragma unroll
        for (int p = 0; p < 2; p++) {
            uint32_t a = stg + 8192 + SWZ16(boff0 + (uint32_t)(p * 16 * 32));
            ldsm4(Bh[p], a);
            ldsm4(Bl[p], a + 4096);
        }
#pragma unroll
        for (int mi = 0; mi < 4; mi++)
#pragma unroll
            for (int ni = 0; ni < 4; ni++) {
                uint32_t bh0 = Bh[ni >> 1][(ni & 1) * 2], bh1 = Bh[ni >> 1][(ni & 1) * 2 + 1];
                uint32_t bl0 = Bl[ni >> 1][(ni & 1) * 2], bl1 = Bl[ni >> 1][(ni & 1) * 2 + 1];
                mma_bf16(acc[mi][ni], Ah[mi], bh0, bh1);
                mma_bf16(acc[mi][ni], Al[mi], bh0, bh1);
                mma_bf16(acc[mi][ni], Ah[mi], bl0, bl1);
            }
    }
#undef STAGE

    int tr = lane >> 2, tc = lane & 3;
    if (SCORE) {
        __syncthreads();
        float* red = (float*)sm_;
        if (tid < 128) red[tid] = 0.f;
        __syncthreads();
#pragma unroll
        for (int mi = 0; mi < 4; mi++)
#pragma unroll
            for (int half = 0; half < 2; half++) {
                float t = 0.f;
#pragma unroll
                for (int ni = 0; ni < 4; ni++) {
                    int col = wn * 32 + tc * 2 + ni * 8;
                    t += tanhf(acc[mi][ni][half * 2]     + ba1[col])     * Wa2[col];
                    t += tanhf(acc[mi][ni][half * 2 + 1] + ba1[col + 1]) * Wa2[col + 1];
                }
                t += __shfl_xor_sync(0xffffffffu, t, 1);
                t += __shfl_xor_sync(0xffffffffu, t, 2);
                if (tc == 0)
                    atomicAdd(&red[wm * 64 + mi * 16 + tr + half * 8], t);
            }
        __syncthreads();
        if (tid < 128) {
            int row = row0 + tid;
            if (row < NN) g_s[row] = red[tid] + ba2[0];
        }
        return;
    }

    float* dstbase = (col0 < 256) ? g_yl : g_yr;
    int cb = col0 & 255;
#pragma unroll
    for (int mi = 0; mi < 4; mi++)
#pragma unroll
        for (int half = 0; half < 2; half++) {
            int row = row0 + wm * 64 + mi * 16 + tr + half * 8;
            if (row < NN) {
                float* p = dstbase + (size_t)row * 256 + cb + wn * 32 + tc * 2;
#pragma unroll
                for (int ni = 0; ni < 4; ni++) {
                    float2 v = make_float2(acc[mi][ni][half * 2], acc[mi][ni][half * 2 + 1]);
                    *(float2*)(p + ni * 8) = v;
                }
            }
        }
}

// ---------------- CSR aggregation + combine + BN stats (float RED atomics) ----------------
__global__ __launch_bounds__(256) void agg_combine(const float* __restrict__ bl, int L) {
    int c  = threadIdx.x;
    int r0 = blockIdx.x * 32;
    if (r0 >= NN) return;
    int r1 = min(r0 + 32, NN);
    float bias = bl[c];
    float s = 0.f, s2 = 0.f;
    for (int r = r0; r < r1; r++) {
        int beg = g_off[r];
        int end = (r == NN - 1) ? NE : g_off[r + 1];
        float a0 = 0.f, a1 = 0.f, a2 = 0.f, a3 = 0.f;
        int i = beg;
        for (; i + 4 <= end; i += 4) {
            int s0 = g_csr[i], s1 = g_csr[i + 1], s2i = g_csr[i + 2], s3 = g_csr[i + 3];
            float v0 = g_yl[(size_t)s0 * 256 + c];
            float v1 = g_yl[(size_t)s1 * 256 + c];
            float v2 = g_yl[(size_t)s2i * 256 + c];
            float v3 = g_yl[(size_t)s3 * 256 + c];
            a0 += v0; a1 += v1; a2 += v2; a3 += v3;
        }
        for (; i < end; i++) a0 += g_yl[(size_t)g_csr[i] * 256 + c];
        float acc = (a0 + a1) + (a2 + a3);
        float pre = acc * g_inv[r] + bias + g_yr[(size_t)r * 256 + c];
        g_m[(size_t)r * 256 + c] = pre;
        s += pre; s2 += pre * pre;
    }
    atomicAdd(&g_sumf[L * 256 + c], s);
    atomicAdd(&g_sumsqf[L * 256 + c], s2);
}

// bnrelu: inline BN finalize (per-block smem precompute) + relu + bf16 hi/lo split.
// One block = 64 rows x 256 channels (16384 floats = 4096 float4; 256 thr x 16).
__global__ __launch_bounds__(256) void bnrelu(int L, const float* __restrict__ gm,
                                              const float* __restrict__ bt) {
    __shared__ float s_sc[256], s_sh[256];
    int t = threadIdx.x;
    {
        float mean = g_sumf[L * 256 + t] * (1.f / NN);
        float var  = g_sumsqf[L * 256 + t] * (1.f / NN) - mean * mean;
        float sc   = rsqrtf(var + 1e-5f) * gm[t];
        s_sc[t] = sc;
        s_sh[t] = bt[t] - mean * sc;
    }
    __syncthreads();
    size_t f4base = (size_t)blockIdx.x * 4096;   // float4 index base
    const size_t f4max = (size_t)NN * 64;
#pragma unroll 4
    for (int k = 0; k < 16; k++) {
        size_t fi = f4base + (size_t)k * 256 + t;
        if (fi >= f4max) break;
        size_t idx = fi * 4;
        int c = (int)(idx & 255);
        float4 v = *(const float4*)(g_m + idx);
        v.x = fmaxf(v.x * s_sc[c + 0] + s_sh[c + 0], 0.f);
        v.y = fmaxf(v.y * s_sc[c + 1] + s_sh[c + 1], 0.f);
        v.z = fmaxf(v.z * s_sc[c + 2] + s_sh[c + 2], 0.f);
        v.w = fmaxf(v.w * s_sc[c + 3] + s_sh[c + 3], 0.f);
        __nv_bfloat162 h01, l01, h23, l23;
        split1(v.x, h01.x, l01.x);
        split1(v.y, h01.y, l01.y);
        split1(v.z, h23.x, l23.x);
        split1(v.w, h23.y, l23.y);
        uint2 uh, ul;
        uh.x = *(uint32_t*)&h01; uh.y = *(uint32_t*)&h23;
        ul.x = *(uint32_t*)&l01; ul.y = *(uint32_t*)&l23;
        *(uint2*)(g_ah + idx) = uh;
        *(uint2*)(g_al + idx) = ul;
    }
}

// ---------------- fused per-graph softmax (also zeroes its pooled row) ----------------
__global__ __launch_bounds__(256) void softmax_fused() {
    int g = blockIdx.x, tid = threadIdx.x;
    for (int i = tid; i < 256; i += 256) g_pooled[g * 256 + i] = 0.f;

    int a = 0, b = NN;
    while (a < b) { int m = (a + b) >> 1; if (g_batch[m] < g) a = m + 1; else b = m; }
    int s = a;
    a = 0; b = NN;
    while (a < b) { int m = (a + b) >> 1; if (g_batch[m] < g + 1) a = m + 1; else b = m; }
    int e = a;
    if (s >= e) return;

    __shared__ float red[8];
    __shared__ float s_mx, s_sum;

    float mx = -3.4e38f;
    for (int n = s + tid; n < e; n += 256) mx = fmaxf(mx, g_s[n]);
#pragma unroll
    for (int o = 16; o; o >>= 1) mx = fmaxf(mx, __shfl_down_sync(0xffffffffu, mx, o));
    if ((tid & 31) == 0) red[tid >> 5] = mx;
    __syncthreads();
    if (tid == 0) {
        float m2 = red[0];
#pragma unroll
        for (int w = 1; w < 8; w++) m2 = fmaxf(m2, red[w]);
        s_mx = m2;
    }
    __syncthreads();
    float gmx = s_mx;

    float sum = 0.f;
    for (int n = s + tid; n < e; n += 256) {
        float ev = expf(g_s[n] - gmx);
        g_w[n] = ev;
        sum += ev;
    }
#pragma unroll
    for (int o = 16; o; o >>= 1) sum += __shfl_down_sync(0xffffffffu, sum, o);
    if ((tid & 31) == 0) red[tid >> 5] = sum;
    __syncthreads();
    if (tid == 0) {
        float t = 0.f;
#pragma unroll
        for (int w = 0; w < 8; w++) t += red[w];
        s_sum = t;
    }
    __syncthreads();

    float inv = 1.f / s_sum;
    for (int n = s + tid; n < e; n += 256) g_w[n] *= inv;
}

// ---------------- weighted pooling (h reconstructed from bf16 hi+lo) ----------------
__global__ void pooled_kernel() {
    int c  = threadIdx.x;
    int r0 = blockIdx.x * 512;
    if (r0 >= NN) return;
    int r1  = min(r0 + 512, NN);
    int cur = g_batch[r0];
    float acc = 0.f;
    for (int r = r0; r < r1; r++) {
        int g = g_batch[r];
        if (g != cur) { atomicAdd(&g_pooled[cur * 256 + c], acc); acc = 0.f; cur = g; }
        float h = __bfloat162float(g_ah[(size_t)r * 256 + c]) +
                  __bfloat162float(g_al[(size_t)r * 256 + c]);
        acc += h * g_w[r];
    }
    atomicAdd(&g_pooled[cur * 256 + c], acc);
}

// ---------------- classifier ----------------
__global__ void classifier_kernel(const float* __restrict__ Wc1, const float* __restrict__ bc1,
                                  const float* __restrict__ Wc2, const float* __restrict__ bc2,
                                  float* __restrict__ out) {
    int g = blockIdx.x;
    int j = threadIdx.x;
    float acc = bc1[j];
    for (int k = 0; k < 256; k++) acc += g_pooled[g * 256 + k] * Wc1[k * 128 + j];
    float t = fmaxf(acc, 0.f) * Wc2[j];
#pragma unroll
    for (int o = 16; o; o >>= 1) t += __shfl_down_sync(0xffffffffu, t, o);
    __shared__ float red[4];
    if ((j & 31) == 0) red[j >> 5] = t;
    __syncthreads();
    if (j == 0) out[g] = red[0] + red[1] + red[2] + red[3] + bc2[0];
}

// ---------------- launch ----------------
extern "C" void kernel_launch(void* const* d_in, const int* in_sizes, int n_in,
                              void* d_out, int out_size) {
    const float* x     = (const float*)d_in[0];
    const void*  ei    = d_in[1];
    const void*  batch = d_in[2];
    const float* Wl[3] = {(const float*)d_in[3], (const float*)d_in[8],  (const float*)d_in[13]};
    const float* bl[3] = {(const float*)d_in[4], (const float*)d_in[9],  (const float*)d_in[14]};
    const float* Wr[3] = {(const float*)d_in[5], (const float*)d_in[10], (const float*)d_in[15]};
    const float* gg[3] = {(const float*)d_in[6], (const float*)d_in[11], (const float*)d_in[16]};
    const float* bb[3] = {(const float*)d_in[7], (const float*)d_in[12], (const float*)d_in[17]};
    const float* Wa1 = (const float*)d_in[18];
    const float* ba1 = (const float*)d_in[19];
    const float* Wa2 = (const float*)d_in[20];
    const float* ba2 = (const float*)d_in[21];
    const float* Wc1 = (const float*)d_in[22];
    const float* bc1 = (const float*)d_in[23];
    const float* Wc2 = (const float*)d_in[24];
    const float* bc2 = (const float*)d_in[25];
    float* out = (float*)d_out;

    // launches 1-4: layer-0 GEMM path first (4th launch = gemm_tc -> ncu capture slot)
    detect_dtype<<<1, 32>>>((const unsigned long long*)ei);
    split_a<<<(NN * (KP0 / 2) + 255) / 256, 256>>>(x);
    pack_wbT<<<(512 * (KP0 / 2) + 255) / 256, 256>>>(Wl[0], Wr[0], IND, KP0);
    {
        dim3 ggrid(4, (NN + 127) / 128);
        gemm_tc<0><<<ggrid, 256>>>(KP0, nullptr, nullptr, nullptr);
    }

    // graph preprocessing (cvt_batch_zero zeroes g_cnt -> must precede cvt_edges;
    // scan3 zeroes all per-layer BN stats)
    cvt_batch_zero<<<(NN + 255) / 256, 256>>>(batch);
    cvt_edges<<<(NE + 255) / 256, 256>>>(ei);
    scan1<<<NBLK, 256>>>();
    scan2<<<1, 512>>>();
    scan3<<<(NN + 255) / 256, 256>>>();
    place_kernel<<<(NE + 255) / 256, 256>>>();

    for (int L = 0; L < 3; L++) {
        if (L > 0) {
            pack_wbT<<<(512 * (HID / 2) + 255) / 256, 256>>>(Wl[L], Wr[L], HID, HID);
            dim3 ggrid(4, (NN + 127) / 128);
            gemm_tc<0><<<ggrid, 256>>>(HID, nullptr, nullptr, nullptr);
        }
        agg_combine<<<(NN + 31) / 32, 256>>>(bl[L], L);
        bnrelu<<<(NN + 63) / 64, 256>>>(L, gg[L], bb[L]);
    }

    // attention score: fused S = h @ Wa1 -> tanh-dot epilogue writes g_s directly
    pack_wa<<<(128 * 128 + 255) / 256, 256>>>(Wa1);
    {
        dim3 sgrid(1, (NN + 127) / 128);
        gemm_tc<1><<<sgrid, 256>>>(HID, ba1, Wa2, ba2);
    }

    softmax_fused<<<NG, 256>>>();
    pooled_kernel<<<(NN + 511) / 512, 256>>>();
    classifier_kernel<<<NG, 128>>>(Wc1, bc1, Wc2, bc2, out);
}

// round 17
// speedup vs baseline: 1.2963x; 1.1219x over previous
#include <cuda_runtime.h>
#include <cuda_bf16.h>
#include <math.h>
#include <stdint.h>

#define NN 100000
#define NE 400000
#define IND 771
#define HID 256
#define NG 64
#define KP0 784            // padded K for layer 0 (49 chunks of 16)
#define NBLK 391           // ceil(NN/256)

// ---------------- scratch (static device globals; no allocation) ----------------
__device__ float  g_yl[(size_t)NN * 256];    // lin_l pre-agg
__device__ float  g_yr[(size_t)NN * 256];    // lin_r part
__device__ float  g_m[(size_t)NN * 256];     // pre-BN
__device__ float  g_inv[NN];
__device__ float  g_sumf[3 * 256];           // per-layer BN stats (float, RED atomics)
__device__ float  g_sumsqf[3 * 256];
__device__ float  g_s[NN];
__device__ float  g_w[NN];
__device__ float  g_pooled[NG * HID];
__device__ int    g_is64;
__device__ int    g_src[NE];
__device__ int    g_dst[NE];
__device__ int    g_batch[NN];
// CSR by dst
__device__ int    g_cnt[NN];
__device__ int    g_off[NN];
__device__ int    g_cur[NN];
__device__ int    g_csr[NE];
__device__ int    g_bsum[NBLK];
__device__ int    g_boff[NBLK];
// bf16 split operands
__device__ __nv_bfloat16 g_ah[(size_t)NN * KP0];
__device__ __nv_bfloat16 g_al[(size_t)NN * KP0];
__device__ __nv_bfloat16 g_bh[512 * KP0];
__device__ __nv_bfloat16 g_bl[512 * KP0];

// ---------------- helpers ----------------
__device__ __forceinline__ uint32_t smem_u32(const void* p) {
    uint32_t a;
    asm("{ .reg .u64 t; cvta.to.shared.u64 t, %1; cvt.u32.u64 %0, t; }" : "=r"(a) : "l"(p));
    return a;
}
#define SWZ16(b) ((b) ^ ((((b) >> 7) & 1) << 4))

__device__ __forceinline__ void cpasync16(uint32_t dst, const void* src, bool pred) {
    int sz = pred ? 16 : 0;
    asm volatile("cp.async.cg.shared.global [%0], [%1], 16, %2;"
                 :: "r"(dst), "l"(src), "r"(sz) : "memory");
}
__device__ __forceinline__ void cp_commit() {
    asm volatile("cp.async.commit_group;" ::: "memory");
}
__device__ __forceinline__ void cp_wait1() {
    asm volatile("cp.async.wait_group 1;" ::: "memory");
}
__device__ __forceinline__ void ldsm4(uint32_t* r, uint32_t addr) {
    asm volatile("ldmatrix.sync.aligned.m8n8.x4.shared.b16 {%0,%1,%2,%3}, [%4];"
                 : "=r"(r[0]), "=r"(r[1]), "=r"(r[2]), "=r"(r[3]) : "r"(addr));
}
__device__ __forceinline__ void mma_bf16(float* c, const uint32_t* a, uint32_t b0, uint32_t b1) {
    asm volatile(
        "mma.sync.aligned.m16n8k16.row.col.f32.bf16.bf16.f32 "
        "{%0,%1,%2,%3}, {%4,%5,%6,%7}, {%8,%9}, {%0,%1,%2,%3};"
        : "+f"(c[0]), "+f"(c[1]), "+f"(c[2]), "+f"(c[3])
        : "r"(a[0]), "r"(a[1]), "r"(a[2]), "r"(a[3]), "r"(b0), "r"(b1));
}
__device__ __forceinline__ void split1(float v, __nv_bfloat16& h, __nv_bfloat16& l) {
    h = __float2bfloat16(v);
    l = __float2bfloat16(v - __bfloat162float(h));
}

// ---------------- dtype detection + index normalization ----------------
__global__ void detect_dtype(const unsigned long long* __restrict__ ei) {
    if (threadIdx.x == 0 && blockIdx.x == 0) {
        int is64 = 1;
        for (int i = 0; i < 64; i++)
            if (ei[i] >= (unsigned long long)NN) { is64 = 0; break; }
        g_is64 = is64;
    }
}
// zeroes g_cnt too -> must run BEFORE cvt_edges (which counts)
__global__ void cvt_batch_zero(const void* __restrict__ b) {
    int n = blockIdx.x * blockDim.x + threadIdx.x;
    if (n >= NN) return;
    if (g_is64) g_batch[n] = (int)((const long long*)b)[n];
    else        g_batch[n] = ((const int*)b)[n];
    g_cnt[n] = 0;
}
// convert edges + count degrees in one pass
__global__ void cvt_edges(const void* __restrict__ ei) {
    int e = blockIdx.x * blockDim.x + threadIdx.x;
    if (e >= NE) return;
    int s, d;
    if (g_is64) {
        const long long* p = (const long long*)ei;
        s = (int)p[e];
        d = (int)p[NE + e];
    } else {
        const int* p = (const int*)ei;
        s = p[e];
        d = p[NE + e];
    }
    g_src[e] = s;
    g_dst[e] = d;
    atomicAdd(&g_cnt[d], 1);
}

// ---------------- CSR build ----------------
__global__ void scan1() {
    __shared__ int sm[256];
    int b = blockIdx.x, t = threadIdx.x;
    int i = b * 256 + t;
    int v = (i < NN) ? g_cnt[i] : 0;
    sm[t] = v; __syncthreads();
    for (int o = 1; o < 256; o <<= 1) {
        int u = (t >= o) ? sm[t - o] : 0;
        __syncthreads();
        sm[t] += u;
        __syncthreads();
    }
    if (i < NN) g_off[i] = sm[t] - v;
    if (t == 255) g_bsum[b] = sm[255];
}
__global__ void scan2() {
    __shared__ int sm[512];
    int t = threadIdx.x;
    int v = (t < NBLK) ? g_bsum[t] : 0;
    sm[t] = v; __syncthreads();
    for (int o = 1; o < 512; o <<= 1) {
        int u = (t >= o) ? sm[t - o] : 0;
        __syncthreads();
        sm[t] += u;
        __syncthreads();
    }
    if (t < NBLK) g_boff[t] = sm[t] - v;
}
// scan3 also zeroes all 3 layers' BN stats (replaces zero_stats launch)
__global__ void scan3() {
    int i = blockIdx.x * blockDim.x + threadIdx.x;
    if (i < 768) { g_sumf[i] = 0.f; g_sumsqf[i] = 0.f; }
    if (i < NN) {
        int o = g_off[i] + g_boff[i >> 8];
        g_off[i] = o;
        g_cur[i] = o;
        g_inv[i] = 1.f / fmaxf((float)g_cnt[i], 1.f);
    }
}
__global__ void place_kernel() {
    int e = blockIdx.x * blockDim.x + threadIdx.x;
    if (e < NE) {
        int pos = atomicAdd(&g_cur[g_dst[e]], 1);
        g_csr[pos] = g_src[e];
    }
}

// ---------------- split x (layer 0 only) ----------------
__global__ void split_a(const float* __restrict__ A) {
    int kp2 = KP0 >> 1;
    int i = blockIdx.x * blockDim.x + threadIdx.x;
    if (i >= NN * kp2) return;
    int n = i / kp2, k2 = (i - n * kp2) * 2;
    float v0 = (k2 < IND)     ? A[(size_t)n * IND + k2]     : 0.f;
    float v1 = (k2 + 1 < IND) ? A[(size_t)n * IND + k2 + 1] : 0.f;
    __nv_bfloat162 hp, lp;
    split1(v0, hp.x, lp.x);
    split1(v1, hp.y, lp.y);
    *(__nv_bfloat162*)(g_ah + (size_t)n * KP0 + k2) = hp;
    *(__nv_bfloat162*)(g_al + (size_t)n * KP0 + k2) = lp;
}

// ---------------- pack [Wl|Wr]^T ----------------
__global__ void pack_wbT(const float* __restrict__ Wl, const float* __restrict__ Wr,
                         int K, int KP) {
    int kp2 = KP >> 1;
    int i = blockIdx.x * blockDim.x + threadIdx.x;
    if (i >= 512 * kp2) return;
    int n = i / kp2, k2 = (i - n * kp2) * 2;
    const float* W = (n < 256) ? Wl : Wr;
    int c = (n < 256) ? n : n - 256;
    float v0 = (k2 < K)     ? W[(size_t)k2 * 256 + c]       : 0.f;
    float v1 = (k2 + 1 < K) ? W[(size_t)(k2 + 1) * 256 + c] : 0.f;
    __nv_bfloat162 hp, lp;
    split1(v0, hp.x, lp.x);
    split1(v1, hp.y, lp.y);
    *(__nv_bfloat162*)(g_bh + (size_t)n * KP + k2) = hp;
    *(__nv_bfloat162*)(g_bl + (size_t)n * KP + k2) = lp;
}

// ---------------- pack Wa1^T (score GEMM B) ----------------
__global__ void pack_wa(const float* __restrict__ Wa1) {
    int i = blockIdx.x * blockDim.x + threadIdx.x;
    if (i >= 128 * 128) return;
    int n = i >> 7, k2 = (i & 127) * 2;
    float v0 = Wa1[(size_t)k2 * 128 + n];
    float v1 = Wa1[(size_t)(k2 + 1) * 128 + n];
    __nv_bfloat162 hp, lp;
    split1(v0, hp.x, lp.x);
    split1(v1, hp.y, lp.y);
    *(__nv_bfloat162*)(g_bh + (size_t)n * 256 + k2) = hp;
    *(__nv_bfloat162*)(g_bl + (size_t)n * 256 + k2) = lp;
}

// ---------------- split-bf16 GEMM: M128 x N128, 8 warps, k16 chunks ----------------
// 3-stage cp.async pipeline (48KB), ONE __syncthreads per chunk, prefetch distance 2.
// iter ch: wait_group 1 -> __syncthreads -> STAGE((ch+2)%3) -> ldsm(ch) -> MMA(ch).
// SCORE=1: epilogue computes g_s[row] = ba2 + sum_j tanh(acc[j]+ba1[j])*Wa2[j].
template <int SCORE>
__global__ void __launch_bounds__(256, 2) gemm_tc(int KP,
                                                  const float* __restrict__ ba1,
                                                  const float* __restrict__ Wa2,
                                                  const float* __restrict__ ba2) {
    __shared__ __align__(128) char sm_[49152];   // 3 x 16KB
    const uint32_t sb = smem_u32(sm_);
    int tid = threadIdx.x, lane = tid & 31, wid = tid >> 5;
    int wm = wid >> 2, wn = wid & 3;         // 2 x 4 warps, warp tile 64x32
    int row0 = blockIdx.y * 128;
    int col0 = blockIdx.x * 128;
    int nch = KP >> 4;

    int r = tid >> 1, s16 = (tid & 1) * 16;
    bool predA = (row0 + r) < NN;
    const char* pAh = (const char*)g_ah + ((size_t)(row0 + r) * KP) * 2 + s16;
    const char* pAl = (const char*)g_al + ((size_t)(row0 + r) * KP) * 2 + s16;
    const char* pBh = (const char*)g_bh + ((size_t)(col0 + r) * KP) * 2 + s16;
    const char* pBl = (const char*)g_bl + ((size_t)(col0 + r) * KP) * 2 + s16;
    if (!predA) { pAh = (const char*)g_ah + s16; pAl = (const char*)g_al + s16; }
    const uint32_t soff = SWZ16((uint32_t)(r * 32 + s16));

#define STAGE(BUF)                                                   \
    do {                                                             \
        uint32_t stg = sb + (uint32_t)(BUF) * 16384 + soff;          \
        cpasync16(stg,         pAh, predA);                          \
        cpasync16(stg + 4096,  pAl, predA);                          \
        cpasync16(stg + 8192,  pBh, true);                           \
        cpasync16(stg + 12288, pBl, true);                           \
        cp_commit();                                                 \
        pAh += 32; pAl += 32; pBh += 32; pBl += 32;                  \
    } while (0)

    float acc[4][4][4];
#pragma unroll
    for (int a = 0; a < 4; a++)
#pragma unroll
        for (int b = 0; b < 4; b++)
#pragma unroll
            for (int c = 0; c < 4; c++) acc[a][b][c] = 0.f;

    STAGE(0);
    STAGE(1);

    int q = lane >> 3, lr = lane & 7;
    const uint32_t aoff0 = (uint32_t)((wm * 64 + (q & 1) * 8 + lr) * 32 + (q >> 1) * 16);
    const uint32_t boff0 = (uint32_t)((wn * 32 + (q >> 1) * 8 + lr) * 32 + (q & 1) * 16);

    int bufS = 2, bufC = 0;
    for (int ch = 0; ch < nch; ch++) {
        cp_wait1();            // oldest pending (group ch) complete
        __syncthreads();       // visibility + seals iter ch-1 reads

        if (ch + 2 < nch) {
            STAGE(bufS);       // writes buf((ch-1)%3): readers sealed
        } else {
            cp_commit();
        }
        bufS = (bufS == 2) ? 0 : bufS + 1;

        uint32_t stg = sb + (uint32_t)bufC * 16384;
        bufC = (bufC == 2) ? 0 : bufC + 1;

        uint32_t Ah[4][4], Al[4][4], Bh[2][4], Bl[2][4];
#pragma unroll
        for (int mi = 0; mi < 4; mi++) {
            uint32_t a = stg + SWZ16(aoff0 + (uint32_t)(mi * 16 * 32));
            ldsm4(Ah[mi], a);
            ldsm4(Al[mi], a + 4096);
        }
#pragma unroll
        for (int p = 0; p < 2; p++) {
            uint32_t a = stg + 8192 + SWZ16(boff0 + (uint32_t)(p * 16 * 32));
            ldsm4(Bh[p], a);
            ldsm4(Bl[p], a + 4096);
        }
#pragma unroll
        for (int mi = 0; mi < 4; mi++)
#pragma unroll
            for (int ni = 0; ni < 4; ni++) {
                uint32_t bh0 = Bh[ni >> 1][(ni & 1) * 2], bh1 = Bh[ni >> 1][(ni & 1) * 2 + 1];
                uint32_t bl0 = Bl[ni >> 1][(ni & 1) * 2], bl1 = Bl[ni >> 1][(ni & 1) * 2 + 1];
                mma_bf16(acc[mi][ni], Ah[mi], bh0, bh1);
                mma_bf16(acc[mi][ni], Al[mi], bh0, bh1);
                mma_bf16(acc[mi][ni], Ah[mi], bl0, bl1);
            }
    }
#undef STAGE

    int tr = lane >> 2, tc = lane & 3;
    if (SCORE) {
        __syncthreads();
        float* red = (float*)sm_;
        if (tid < 128) red[tid] = 0.f;
        __syncthreads();
#pragma unroll
        for (int mi = 0; mi < 4; mi++)
#pragma unroll
            for (int half = 0; half < 2; half++) {
                float t = 0.f;
#pragma unroll
                for (int ni = 0; ni < 4; ni++) {
                    int col = wn * 32 + tc * 2 + ni * 8;
                    t += tanhf(acc[mi][ni][half * 2]     + ba1[col])     * Wa2[col];
                    t += tanhf(acc[mi][ni][half * 2 + 1] + ba1[col + 1]) * Wa2[col + 1];
                }
                t += __shfl_xor_sync(0xffffffffu, t, 1);
                t += __shfl_xor_sync(0xffffffffu, t, 2);
                if (tc == 0)
                    atomicAdd(&red[wm * 64 + mi * 16 + tr + half * 8], t);
            }
        __syncthreads();
        if (tid < 128) {
            int row = row0 + tid;
            if (row < NN) g_s[row] = red[tid] + ba2[0];
        }
        return;
    }

    float* dstbase = (col0 < 256) ? g_yl : g_yr;
    int cb = col0 & 255;
#pragma unroll
    for (int mi = 0; mi < 4; mi++)
#pragma unroll
        for (int half = 0; half < 2; half++) {
            int row = row0 + wm * 64 + mi * 16 + tr + half * 8;
            if (row < NN) {
                float* p = dstbase + (size_t)row * 256 + cb + wn * 32 + tc * 2;
#pragma unroll
                for (int ni = 0; ni < 4; ni++) {
                    float2 v = make_float2(acc[mi][ni][half * 2], acc[mi][ni][half * 2 + 1]);
                    *(float2*)(p + ni * 8) = v;
                }
            }
        }
}

// ---------------- CSR aggregation + combine + BN stats (8 rows/block for MLP) ----------------
__global__ __launch_bounds__(256) void agg_combine(const float* __restrict__ bl, int L) {
    int c  = threadIdx.x;
    int r0 = blockIdx.x * 8;
    if (r0 >= NN) return;
    int r1 = min(r0 + 8, NN);
    float bias = bl[c];
    float s = 0.f, s2 = 0.f;
    for (int r = r0; r < r1; r++) {
        int beg = g_off[r];
        int end = (r == NN - 1) ? NE : g_off[r + 1];
        float a0 = 0.f, a1 = 0.f, a2 = 0.f, a3 = 0.f;
        int i = beg;
        for (; i + 4 <= end; i += 4) {
            int s0 = g_csr[i], s1 = g_csr[i + 1], s2i = g_csr[i + 2], s3 = g_csr[i + 3];
            float v0 = g_yl[(size_t)s0 * 256 + c];
            float v1 = g_yl[(size_t)s1 * 256 + c];
            float v2 = g_yl[(size_t)s2i * 256 + c];
            float v3 = g_yl[(size_t)s3 * 256 + c];
            a0 += v0; a1 += v1; a2 += v2; a3 += v3;
        }
        for (; i < end; i++) a0 += g_yl[(size_t)g_csr[i] * 256 + c];
        float acc = (a0 + a1) + (a2 + a3);
        float pre = acc * g_inv[r] + bias + g_yr[(size_t)r * 256 + c];
        g_m[(size_t)r * 256 + c] = pre;
        s += pre; s2 += pre * pre;
    }
    atomicAdd(&g_sumf[L * 256 + c], s);
    atomicAdd(&g_sumsqf[L * 256 + c], s2);
}

// bnrelu: inline BN finalize (per-block smem precompute) + relu + bf16 hi/lo split.
// One block = 64 rows x 256 channels (16384 floats = 4096 float4; 256 thr x 16).
__global__ __launch_bounds__(256) void bnrelu(int L, const float* __restrict__ gm,
                                              const float* __restrict__ bt) {
    __shared__ float s_sc[256], s_sh[256];
    int t = threadIdx.x;
    {
        float mean = g_sumf[L * 256 + t] * (1.f / NN);
        float var  = g_sumsqf[L * 256 + t] * (1.f / NN) - mean * mean;
        float sc   = rsqrtf(var + 1e-5f) * gm[t];
        s_sc[t] = sc;
        s_sh[t] = bt[t] - mean * sc;
    }
    __syncthreads();
    size_t f4base = (size_t)blockIdx.x * 4096;   // float4 index base
    const size_t f4max = (size_t)NN * 64;
#pragma unroll 4
    for (int k = 0; k < 16; k++) {
        size_t fi = f4base + (size_t)k * 256 + t;
        if (fi >= f4max) break;
        size_t idx = fi * 4;
        int c = (int)(idx & 255);
        float4 v = *(const float4*)(g_m + idx);
        v.x = fmaxf(v.x * s_sc[c + 0] + s_sh[c + 0], 0.f);
        v.y = fmaxf(v.y * s_sc[c + 1] + s_sh[c + 1], 0.f);
        v.z = fmaxf(v.z * s_sc[c + 2] + s_sh[c + 2], 0.f);
        v.w = fmaxf(v.w * s_sc[c + 3] + s_sh[c + 3], 0.f);
        __nv_bfloat162 h01, l01, h23, l23;
        split1(v.x, h01.x, l01.x);
        split1(v.y, h01.y, l01.y);
        split1(v.z, h23.x, l23.x);
        split1(v.w, h23.y, l23.y);
        uint2 uh, ul;
        uh.x = *(uint32_t*)&h01; uh.y = *(uint32_t*)&h23;
        ul.x = *(uint32_t*)&l01; ul.y = *(uint32_t*)&l23;
        *(uint2*)(g_ah + idx) = uh;
        *(uint2*)(g_al + idx) = ul;
    }
}

// ---------------- fused per-graph softmax (also zeroes its pooled row) ----------------
__global__ __launch_bounds__(256) void softmax_fused() {
    int g = blockIdx.x, tid = threadIdx.x;
    for (int i = tid; i < 256; i += 256) g_pooled[g * 256 + i] = 0.f;

    int a = 0, b = NN;
    while (a < b) { int m = (a + b) >> 1; if (g_batch[m] < g) a = m + 1; else b = m; }
    int s = a;
    a = 0; b = NN;
    while (a < b) { int m = (a + b) >> 1; if (g_batch[m] < g + 1) a = m + 1; else b = m; }
    int e = a;
    if (s >= e) return;

    __shared__ float red[8];
    __shared__ float s_mx, s_sum;

    float mx = -3.4e38f;
    for (int n = s + tid; n < e; n += 256) mx = fmaxf(mx, g_s[n]);
#pragma unroll
    for (int o = 16; o; o >>= 1) mx = fmaxf(mx, __shfl_down_sync(0xffffffffu, mx, o));
    if ((tid & 31) == 0) red[tid >> 5] = mx;
    __syncthreads();
    if (tid == 0) {
        float m2 = red[0];
#pragma unroll
        for (int w = 1; w < 8; w++) m2 = fmaxf(m2, red[w]);
        s_mx = m2;
    }
    __syncthreads();
    float gmx = s_mx;

    float sum = 0.f;
    for (int n = s + tid; n < e; n += 256) {
        float ev = expf(g_s[n] - gmx);
        g_w[n] = ev;
        sum += ev;
    }
#pragma unroll
    for (int o = 16; o; o >>= 1) sum += __shfl_down_sync(0xffffffffu, sum, o);
    if ((tid & 31) == 0) red[tid >> 5] = sum;
    __syncthreads();
    if (tid == 0) {
        float t = 0.f;
#pragma unroll
        for (int w = 0; w < 8; w++) t += red[w];
        s_sum = t;
    }
    __syncthreads();

    float inv = 1.f / s_sum;
    for (int n = s + tid; n < e; n += 256) g_w[n] *= inv;
}

// ---------------- weighted pooling (128 rows/block; h from bf16 hi+lo) ----------------
__global__ void pooled_kernel() {
    int c  = threadIdx.x;
    int r0 = blockIdx.x * 128;
    if (r0 >= NN) return;
    int r1  = min(r0 + 128, NN);
    int cur = g_batch[r0];
    float acc = 0.f;
    for (int r = r0; r < r1; r++) {
        int g = g_batch[r];
        if (g != cur) { atomicAdd(&g_pooled[cur * 256 + c], acc); acc = 0.f; cur = g; }
        float h = __bfloat162float(g_ah[(size_t)r * 256 + c]) +
                  __bfloat162float(g_al[(size_t)r * 256 + c]);
        acc += h * g_w[r];
    }
    atomicAdd(&g_pooled[cur * 256 + c], acc);
}

// ---------------- classifier ----------------
__global__ void classifier_kernel(const float* __restrict__ Wc1, const float* __restrict__ bc1,
                                  const float* __restrict__ Wc2, const float* __restrict__ bc2,
                                  float* __restrict__ out) {
    int g = blockIdx.x;
    int j = threadIdx.x;
    float acc = bc1[j];
    for (int k = 0; k < 256; k++) acc += g_pooled[g * 256 + k] * Wc1[k * 128 + j];
    float t = fmaxf(acc, 0.f) * Wc2[j];
#pragma unroll
    for (int o = 16; o; o >>= 1) t += __shfl_down_sync(0xffffffffu, t, o);
    __shared__ float red[4];
    if ((j & 31) == 0) red[j >> 5] = t;
    __syncthreads();
    if (j == 0) out[g] = red[0] + red[1] + red[2] + red[3] + bc2[0];
}

// ---------------- launch ----------------
extern "C" void kernel_launch(void* const* d_in, const int* in_sizes, int n_in,
                              void* d_out, int out_size) {
    const float* x     = (const float*)d_in[0];
    const void*  ei    = d_in[1];
    const void*  batch = d_in[2];
    const float* Wl[3] = {(const float*)d_in[3], (const float*)d_in[8],  (const float*)d_in[13]};
    const float* bl[3] = {(const float*)d_in[4], (const float*)d_in[9],  (const float*)d_in[14]};
    const float* Wr[3] = {(const float*)d_in[5], (const float*)d_in[10], (const float*)d_in[15]};
    const float* gg[3] = {(const float*)d_in[6], (const float*)d_in[11], (const float*)d_in[16]};
    const float* bb[3] = {(const float*)d_in[7], (const float*)d_in[12], (const float*)d_in[17]};
    const float* Wa1 = (const float*)d_in[18];
    const float* ba1 = (const float*)d_in[19];
    const float* Wa2 = (const float*)d_in[20];
    const float* ba2 = (const float*)d_in[21];
    const float* Wc1 = (const float*)d_in[22];
    const float* bc1 = (const float*)d_in[23];
    const float* Wc2 = (const float*)d_in[24];
    const float* bc2 = (const float*)d_in[25];
    float* out = (float*)d_out;

    // launches 1-4: layer-0 GEMM path first (4th launch = gemm_tc -> ncu capture slot)
    detect_dtype<<<1, 32>>>((const unsigned long long*)ei);
    split_a<<<(NN * (KP0 / 2) + 255) / 256, 256>>>(x);
    pack_wbT<<<(512 * (KP0 / 2) + 255) / 256, 256>>>(Wl[0], Wr[0], IND, KP0);
    {
        dim3 ggrid(4, (NN + 127) / 128);
        gemm_tc<0><<<ggrid, 256>>>(KP0, nullptr, nullptr, nullptr);
    }

    // graph preprocessing (cvt_batch_zero zeroes g_cnt -> must precede cvt_edges;
    // scan3 zeroes all per-layer BN stats)
    cvt_batch_zero<<<(NN + 255) / 256, 256>>>(batch);
    cvt_edges<<<(NE + 255) / 256, 256>>>(ei);
    scan1<<<NBLK, 256>>>();
    scan2<<<1, 512>>>();
    scan3<<<(NN + 255) / 256, 256>>>();
    place_kernel<<<(NE + 255) / 256, 256>>>();

    for (int L = 0; L < 3; L++) {
        if (L > 0) {
            pack_wbT<<<(512 * (HID / 2) + 255) / 256, 256>>>(Wl[L], Wr[L], HID, HID);
            dim3 ggrid(4, (NN + 127) / 128);
            gemm_tc<0><<<ggrid, 256>>>(HID, nullptr, nullptr, nullptr);
        }
        agg_combine<<<(NN + 7) / 8, 256>>>(bl[L], L);
        bnrelu<<<(NN + 63) / 64, 256>>>(L, gg[L], bb[L]);
    }

    // attention score: fused S = h @ Wa1 -> tanh-dot epilogue writes g_s directly
    pack_wa<<<(128 * 128 + 255) / 256, 256>>>(Wa1);
    {
        dim3 sgrid(1, (NN + 127) / 128);
        gemm_tc<1><<<sgrid, 256>>>(HID, ba1, Wa2, ba2);
    }

    softmax_fused<<<NG, 256>>>();
    pooled_kernel<<<(NN + 127) / 128, 256>>>();
    classifier_kernel<<<NG, 128>>>(Wc1, bc1, Wc2, bc2, out);
}